// round 7
// baseline (speedup 1.0000x reference)
#include <cuda_runtime.h>
#include <cuda_bf16.h>
#include <math.h>
#include <stdint.h>

typedef __nv_bfloat16 BF;
#define T_ 512
#define B_ 64
#define H_ 1024
#define IN0 1536
#define OUTD 512
#define SLOT (B_*H_)
#define SLAB ((size_t)514*SLOT)
#define NBLK 64

__device__ __align__(16) BF gG0h[(size_t)NBLK*64*2560];
__device__ __align__(16) BF gG0l[(size_t)NBLK*64*2560];
__device__ __align__(16) BF gG1h[(size_t)NBLK*64*2048];
__device__ __align__(16) BF gG1l[(size_t)NBLK*64*2048];
__device__ __align__(16) BF gSkh[(size_t)2*NBLK*16*1024];
__device__ __align__(16) BF gSkl[(size_t)2*NBLK*16*1024];
__device__ __align__(16) BF gWoh[OUTD*H_];
__device__ __align__(16) BF gWol[OUTD*H_];
__device__ __align__(16) BF gXh[(size_t)T_*B_*IN0];
__device__ __align__(16) BF gXl[(size_t)T_*B_*IN0];
__device__ __align__(16) BF gHh[2*SLAB];
__device__ __align__(16) BF gHl[2*SLAB];

__device__ volatile unsigned gBarGen;
__device__ unsigned gBarCnt;

__device__ __forceinline__ float sigf(float x){ return 1.f/(1.f+expf(-x)); }
__device__ __forceinline__ void splitf(float v, BF* h, BF* l){
  BF a=__float2bfloat16(v); *h=a; *l=__float2bfloat16(v-__bfloat162float(a));
}
__device__ __forceinline__ void cp16(BF* d, const BF* s){
  unsigned u=(unsigned)__cvta_generic_to_shared(d);
  asm volatile("cp.async.cg.shared.global [%0],[%1],16;"::"r"(u),"l"(s));
}
__device__ __forceinline__ void cpc(){ asm volatile("cp.async.commit_group;"); }
template<int N> __device__ __forceinline__ void cpw(){ asm volatile("cp.async.wait_group %0;"::"n"(N)); }

__device__ __forceinline__ void gridbar(){
  __syncthreads();
  if(threadIdx.x==0){
    unsigned old = gBarGen;
    __threadfence();
    unsigned prev = atomicAdd(&gBarCnt,1u);
    if(prev==NBLK-1u){ gBarCnt=0u; __threadfence(); gBarGen=old+1u; }
    else { while(gBarGen==old){} }
    __threadfence();
  }
  __syncthreads();
}

// tiles: rows x 64 bf16, 128B rows, 8-way 16B XOR swizzle
__device__ __forceinline__ const BF* swp(const BF* t_, int r, int cseg){
  return t_ + r*64 + ((cseg ^ (r&7))<<3);
}
__device__ __forceinline__ void stT(BF* dh, BF* dl, const BF* ph, const BF* pl,
                                    int ld, int rows, int tid, int nthr){
  for(int u=tid; u<rows*8; u+=nthr){
    int r=u>>3, cs=u&7;
    int off = r*64 + ((cs ^ (r&7))<<3);
    size_t g=(size_t)r*ld + cs*8;
    cp16(dh+off, ph+g); cp16(dl+off, pl+g);
  }
}
__device__ __forceinline__ void ldsm4(unsigned a[4], const BF* p){
  unsigned u=(unsigned)__cvta_generic_to_shared(p);
  asm volatile("ldmatrix.sync.aligned.m8n8.x4.shared.b16 {%0,%1,%2,%3},[%4];"
    :"=r"(a[0]),"=r"(a[1]),"=r"(a[2]),"=r"(a[3]):"r"(u));
}
__device__ __forceinline__ void ldsm2(unsigned b[2], const BF* p){
  unsigned u=(unsigned)__cvta_generic_to_shared(p);
  asm volatile("ldmatrix.sync.aligned.m8n8.x2.shared.b16 {%0,%1},[%2];"
    :"=r"(b[0]),"=r"(b[1]):"r"(u));
}
__device__ __forceinline__ void mma(float c[4], const unsigned a[4], const unsigned b[2]){
  asm volatile("mma.sync.aligned.m16n8k16.row.col.f32.bf16.bf16.f32 "
    "{%0,%1,%2,%3},{%4,%5,%6,%7},{%8,%9},{%0,%1,%2,%3};"
    :"+f"(c[0]),"+f"(c[1]),"+f"(c[2]),"+f"(c[3])
    :"r"(a[0]),"r"(a[1]),"r"(a[2]),"r"(a[3]),"r"(b[0]),"r"(b[1]));
}
// x4 B load covering nt-pair (2 tiles of 8 rows) x 16 k
__device__ __forceinline__ void ldsm4b(unsigned b[4], const BF* t_, int np, int cs, int lane){
  int row  = np*16 + ((lane>>4)<<3) + (lane&7);
  int cseg = cs + ((lane>>3)&1);
  ldsm4(b, t_ + row*64 + ((cseg ^ (row&7))<<3));
}
// one 32-wide K slice of C(16 x NP*16); A tile 64x64, W tile rows x 64
template<int NP>
__device__ __forceinline__ void mm32p(float (*acc)[4], const BF* Ah,const BF* Al,
     const BF* Wh,const BF* Wl, int kbase, int rA,int cA,int lane){
#pragma unroll
  for(int kk=0;kk<2;kk++){
    int cs=(kbase>>3)+kk*2;
    unsigned ah[4],al[4];
    ldsm4(ah,swp(Ah,rA,cs+cA)); ldsm4(al,swp(Al,rA,cs+cA));
#pragma unroll
    for(int np=0;np<NP;np++){
      unsigned bh4[4],bl4[4];
      ldsm4b(bh4,Wh,np,cs,lane); ldsm4b(bl4,Wl,np,cs,lane);
      mma(acc[2*np],ah,bh4);   mma(acc[2*np],ah,bl4);   mma(acc[2*np],al,bh4);
      mma(acc[2*np+1],ah,bh4+2); mma(acc[2*np+1],ah,bl4+2); mma(acc[2*np+1],al,bh4+2);
    }
  }
}
// legacy NT-tile version (k_out)
template<int NT>
__device__ __forceinline__ void mm32(float (*acc)[4], const BF* Ah,const BF* Al,
     const BF* Wh,const BF* Wl, int kbase, int rA,int cA,int nB,int cB){
#pragma unroll
  for(int kk=0;kk<2;kk++){
    int cs=(kbase>>3)+kk*2;
    unsigned ah[4],al[4];
    ldsm4(ah,swp(Ah,rA,cs+cA)); ldsm4(al,swp(Al,rA,cs+cA));
#pragma unroll
    for(int nt=0;nt<NT;nt++){
      unsigned bh[2],bl[2];
      ldsm2(bh,swp(Wh,nt*8+nB,cs+cB)); ldsm2(bl,swp(Wl,nt*8+nB,cs+cB));
      mma(acc[nt],ah,bh); mma(acc[nt],ah,bl); mma(acc[nt],al,bh);
    }
  }
}

// ---------------- prep ----------------
__global__ void k_prepX(const float* __restrict__ x){
  size_t n=(size_t)T_*B_*IN0;
  for(size_t i=(size_t)blockIdx.x*blockDim.x+threadIdx.x;i<n;i+=(size_t)gridDim.x*blockDim.x)
    splitf(x[i],&gXh[i],&gXl[i]);
}
// gate weights: blk owns 16 cols; row r(0..63): gate g=r>>4, col=blk*16+(r&15)
__global__ void k_prepG(const float* __restrict__ Wih,const float* __restrict__ Whh,int layer){
  const int KA1=layer?H_:IN0, KG=KA1+H_;
  BF* dh=layer?gG1h:gG0h; BF* dl=layer?gG1l:gG0l;
  size_t n=(size_t)NBLK*64*KG;
  for(size_t i=(size_t)blockIdx.x*blockDim.x+threadIdx.x;i<n;i+=(size_t)gridDim.x*blockDim.x){
    int k=(int)(i%KG); int q=(int)(i/KG); int r=q&63, blk=q>>6;
    int row=(r>>4)*H_+blk*16+(r&15);
    float v = (k<KA1)? Wih[(size_t)row*KA1+k] : Whh[(size_t)row*H_+(k-KA1)];
    splitf(v,&dh[i],&dl[i]);
  }
}
__global__ void k_prepS2(const float* __restrict__ Wh2,int layer){
  BF* dh=gSkh+(size_t)layer*NBLK*16*1024; BF* dl=gSkl+(size_t)layer*NBLK*16*1024;
  int n=NBLK*16*1024;
  for(int i=blockIdx.x*blockDim.x+threadIdx.x;i<n;i+=gridDim.x*blockDim.x){
    int k=i&1023; int q=i>>10; int nr=q&15, blk=q>>4;
    splitf(Wh2[(size_t)k*H_+blk*16+nr],&dh[i],&dl[i]);   // transposed skip weight
  }
}
__global__ void k_prepWo(const float* __restrict__ W){
  for(int i=blockIdx.x*blockDim.x+threadIdx.x;i<OUTD*H_;i+=gridDim.x*blockDim.x)
    splitf(W[i],&gWoh[i],&gWol[i]);
}

// ---------------- persistent recurrence ----------------
// smem: sA 4 x (hi4096|lo4096) = 64KB @0 ; sW 4 x (hi4096|lo4096) = 64KB @65536 ;
// Cred 64x80 f32 @131072 -> total 151552
__global__ void __launch_bounds__(256,1) k_persist(const int* __restrict__ mask,
    const float* __restrict__ h0, const float* __restrict__ c0,
    const float* __restrict__ bih0,const float* __restrict__ bhh0,const float* __restrict__ bh20,
    const float* __restrict__ bih1,const float* __restrict__ bhh1,const float* __restrict__ bh21)
{
  extern __shared__ char smx[];
  BF* sA=(BF*)smx;
  BF* sW=(BF*)(smx+65536);
  float* Cred=(float*)(smx+131072);
  const int tid=threadIdx.x, lane=tid&31, w=tid>>5, blk=blockIdx.x;
  const int kg=w>>2, r0=(w&3)*16;
  const int rA=r0+(lane&7)+((lane>>3)&1)*8, cA=(lane>>4)&1;
  const int rr=r0+(lane>>2), cc=(lane&3)*2;
  const int kbase=kg*32;

  float creg[2][8];
  if(w<4){
#pragma unroll
    for(int q=0;q<2;q++)
#pragma unroll
      for(int hl=0;hl<2;hl++)
#pragma unroll
        for(int p=0;p<2;p++){
          int r=rr+q*8, jl=hl*8+cc+p, j=blk*16+jl, i8=q*4+hl*2+p;
          creg[0][i8]=c0[(size_t)r*H_+j];
          creg[1][i8]=c0[(size_t)(B_+r)*H_+j];
#pragma unroll
          for(int L=0;L<2;L++){
            size_t b0=(size_t)L*SLAB+(size_t)r*H_+j;
            gHh[b0]=__float2bfloat16(0.f); gHl[b0]=__float2bfloat16(0.f);
            splitf(h0[(size_t)(L*B_+r)*H_+j],&gHh[b0+SLOT],&gHl[b0+SLOT]);
          }
        }
  }
  gridbar();

  for(int t=0;t<T_;t++){
#pragma unroll 1
    for(int L=0;L<2;L++){
      const int KA1=L?H_:IN0, KG=KA1+H_;
      const int NG=KG>>6, NIT=NG+16;
      const BF* Gh=(L?gG1h:gG0h)+(size_t)blk*64*KG;
      const BF* Gl=(L?gG1l:gG0l)+(size_t)blk*64*KG;
      const BF* Sh=gSkh+(size_t)L*NBLK*16*1024+(size_t)blk*16*1024;
      const BF* Sl=gSkl+(size_t)L*NBLK*16*1024+(size_t)blk*16*1024;
      const BF* skAh=gHh+(size_t)L*SLAB+(size_t)t*SLOT;
      const BF* skAl=gHl+(size_t)L*SLAB+(size_t)t*SLOT;

      float acc[10][4];
#pragma unroll
      for(int i=0;i<10;i++){acc[i][0]=0;acc[i][1]=0;acc[i][2]=0;acc[i][3]=0;}

      auto do_stage=[&](int it){
        int st=it&3;
        BF* dA=sA+st*8192; BF* dW=sW+st*8192;
        if(it<NG){
          int k0=it*64;
          const BF *ph,*pl; int ld;
          if(L==0){
            if(k0<IN0){ph=gXh+(size_t)t*B_*IN0+k0; pl=gXl+(size_t)t*B_*IN0+k0; ld=IN0;}
            else {ph=gHh+(size_t)(t+1)*SLOT+(k0-IN0); pl=gHl+(size_t)(t+1)*SLOT+(k0-IN0); ld=H_;}
          }else{
            if(k0<H_){ph=gHh+(size_t)(t+2)*SLOT+k0; pl=gHl+(size_t)(t+2)*SLOT+k0; ld=H_;}
            else {ph=gHh+SLAB+(size_t)(t+1)*SLOT+(k0-H_); pl=gHl+SLAB+(size_t)(t+1)*SLOT+(k0-H_); ld=H_;}
          }
          stT(dA,dA+4096,ph,pl,ld,64,tid,256);
          stT(dW,dW+4096,Gh+k0,Gl+k0,KG,64,tid,256);
        }else{
          int k0=(it-NG)*64;
          stT(dA,dA+4096,skAh+k0,skAl+k0,H_,64,tid,256);
          stT(dW,dW+4096,Sh+k0,Sl+k0,1024,16,tid,256);
        }
        cpc();
      };

      do_stage(0); do_stage(1); do_stage(2);
#pragma unroll 1
      for(int it=0;it<NIT;it++){
        int rem=NIT-1-it;
        if(rem>1) cpw<2>(); else if(rem==1) cpw<1>(); else cpw<0>();
        __syncthreads();
        int st=it&3;
        BF* bA=sA+st*8192; BF* bW=sW+st*8192;
        if(it<NG) mm32p<4>(acc,bA,bA+4096,bW,bW+4096,kbase,rA,cA,lane);
        else      mm32p<1>(acc+8,bA,bA+4096,bW,bW+4096,kbase,rA,cA,lane);
        if(it+3<NIT) do_stage(it+3);
      }

      // k-split reduction: kg=1 warps dump partials
      if(w>=4){
#pragma unroll
        for(int nt=0;nt<10;nt++)
#pragma unroll
          for(int q=0;q<2;q++)
#pragma unroll
            for(int p=0;p<2;p++)
              Cred[(rr+q*8)*80+nt*8+cc+p]=acc[nt][q*2+p];
      }
      __syncthreads();
      if(w<4){
        const float* bi=L?bih1:bih0; const float* bh=L?bhh1:bhh0; const float* b2=L?bh21:bh20;
#pragma unroll
        for(int q=0;q<2;q++)
#pragma unroll
          for(int hl=0;hl<2;hl++)
#pragma unroll
            for(int p=0;p<2;p++){
              int r=rr+q*8, jl=hl*8+cc+p, j=blk*16+jl, idx=q*2+p, i8=q*4+hl*2+p;
              float ig=acc[0+hl][idx]+Cred[r*80+jl]      +bi[j]     +bh[j];
              float fg=acc[2+hl][idx]+Cred[r*80+16+jl]   +bi[H_+j]  +bh[H_+j];
              float gg=acc[4+hl][idx]+Cred[r*80+32+jl]   +bi[2*H_+j]+bh[2*H_+j];
              float og=acc[6+hl][idx]+Cred[r*80+48+jl]   +bi[3*H_+j]+bh[3*H_+j];
              float sk=acc[8+hl][idx]+Cred[r*80+64+jl]   +b2[j];
              float cv=creg[L][i8];
              float cn=sigf(fg)*cv+sigf(ig)*tanhf(gg);
              float h1=sigf(og)*tanhf(cn);
              float h2=sigf(sk);
              int code=mask[(size_t)t*2*H_+(size_t)L*H_+j];
              float hn=(code!=1?h1:0.f)+(code!=0?h2:0.f);
              creg[L][i8]=cn;
              size_t hi=(size_t)L*SLAB+(size_t)(t+2)*SLOT+(size_t)r*H_+j;
              splitf(hn,&gHh[hi],&gHl[hi]);
            }
      }
      if(L==0) gridbar();   // single barrier per step (see analysis)
      else __syncthreads(); // protect Cred reuse next step
    }
  }
}

// ---------------- output GEMM ----------------
__global__ void __launch_bounds__(256,1) k_out(const float* __restrict__ bo, float* __restrict__ out){
  extern __shared__ char smx[];
  BF* sA=(BF*)smx;
  BF* sW=(BF*)(smx+65536);
  float* Cred=(float*)(smx+131072);
  const int tid=threadIdx.x, lane=tid&31, w=tid>>5;
  const int kg=w>>2, r0=(w&3)*16;
  const int rA=r0+(lane&7)+((lane>>3)&1)*8, cA=(lane>>4)&1;
  const int nB=lane&7, cB=(lane>>3)&1;
  const int rr=r0+(lane>>2), cc=(lane&3)*2;
  const int kbase=kg*32;
  const int t=blockIdx.x, n0=blockIdx.y*64;
  const BF* Ah=gHh+SLAB+(size_t)(t+2)*SLOT;
  const BF* Al=gHl+SLAB+(size_t)(t+2)*SLOT;
  const BF* Wh=gWoh+(size_t)n0*H_;
  const BF* Wl=gWol+(size_t)n0*H_;
  float acc[8][4];
#pragma unroll
  for(int i=0;i<8;i++){acc[i][0]=0;acc[i][1]=0;acc[i][2]=0;acc[i][3]=0;}
  auto do_stage=[&](int it){
    int st=it&3, k0=it*64;
    BF* dA=sA+st*8192; BF* dW=sW+st*8192;
    stT(dA,dA+4096,Ah+k0,Al+k0,H_,64,tid,256);
    stT(dW,dW+4096,Wh+k0,Wl+k0,H_,64,tid,256);
    cpc();
  };
  do_stage(0); do_stage(1); do_stage(2);
#pragma unroll 1
  for(int it=0;it<16;it++){
    int rem=15-it;
    if(rem>1) cpw<2>(); else if(rem==1) cpw<1>(); else cpw<0>();
    __syncthreads();
    int st=it&3;
    BF* bA=sA+st*8192; BF* bW=sW+st*8192;
    mm32<8>(acc,bA,bA+4096,bW,bW+4096,kbase,rA,cA,nB,cB);
    if(it+3<16) do_stage(it+3);
  }
  if(w>=4){
#pragma unroll
    for(int nt=0;nt<8;nt++)
#pragma unroll
      for(int q=0;q<2;q++)
#pragma unroll
        for(int p=0;p<2;p++)
          Cred[(rr+q*8)*64+nt*8+cc+p]=acc[nt][q*2+p];
  }
  __syncthreads();
  if(w<4){
#pragma unroll
    for(int nt=0;nt<8;nt++)
#pragma unroll
      for(int q=0;q<2;q++)
#pragma unroll
        for(int p=0;p<2;p++){
          int r=rr+q*8, col=n0+nt*8+cc+p;
          float v=acc[nt][q*2+p]+Cred[r*64+nt*8+cc+p]+bo[col];
          out[(size_t)t*B_*OUTD+(size_t)r*OUTD+col]=v;
        }
  }
}

extern "C" void kernel_launch(void* const* d_in, const int* in_sizes, int n_in,
                              void* d_out, int out_size) {
  const float* targets=(const float*)d_in[0];
  const float* h0  =(const float*)d_in[1];
  const float* c0  =(const float*)d_in[2];
  const int*   mask=(const int*)  d_in[3];
  const float* Wih0=(const float*)d_in[4];
  const float* Whh0=(const float*)d_in[5];
  const float* bih0=(const float*)d_in[6];
  const float* bhh0=(const float*)d_in[7];
  const float* Wih1=(const float*)d_in[8];
  const float* Whh1=(const float*)d_in[9];
  const float* bih1=(const float*)d_in[10];
  const float* bhh1=(const float*)d_in[11];
  const float* Wh20=(const float*)d_in[12];
  const float* bh20=(const float*)d_in[13];
  const float* Wh21=(const float*)d_in[14];
  const float* bh21=(const float*)d_in[15];
  const float* Wout=(const float*)d_in[16];
  const float* bout=(const float*)d_in[17];

  static int inited=0;
  if(!inited){
    cudaFuncSetAttribute(k_persist, cudaFuncAttributeMaxDynamicSharedMemorySize, 151552);
    cudaFuncSetAttribute(k_out,     cudaFuncAttributeMaxDynamicSharedMemorySize, 147456);
    inited=1;
  }
  k_prepX<<<4096,256>>>(targets);
  k_prepG<<<4096,256>>>(Wih0,Whh0,0);
  k_prepG<<<4096,256>>>(Wih1,Whh1,1);
  k_prepS2<<<512,256>>>(Wh20,0);
  k_prepS2<<<512,256>>>(Wh21,1);
  k_prepWo<<<512,256>>>(Wout);
  k_persist<<<NBLK,256,151552>>>(mask,h0,c0,bih0,bhh0,bh20,bih1,bhh1,bh21);
  k_out<<<dim3(T_,8),256,147456>>>(bout,(float*)d_out);
}

// round 8
// speedup vs baseline: 1.4907x; 1.4907x over previous
#include <cuda_runtime.h>
#include <cuda_bf16.h>
#include <math.h>
#include <stdint.h>

typedef __nv_bfloat16 BF;
#define T_ 512
#define B_ 64
#define H_ 1024
#define IN0 1536
#define OUTD 512
#define SLOT (B_*H_)
#define SLAB ((size_t)514*SLOT)
#define NBLK 128

__device__ __align__(16) BF gG0h[(size_t)NBLK*32*2560];
__device__ __align__(16) BF gG0l[(size_t)NBLK*32*2560];
__device__ __align__(16) BF gG1h[(size_t)NBLK*32*2048];
__device__ __align__(16) BF gG1l[(size_t)NBLK*32*2048];
__device__ __align__(16) BF gSkh[(size_t)2*NBLK*8*1024];
__device__ __align__(16) BF gSkl[(size_t)2*NBLK*8*1024];
__device__ __align__(16) BF gWoh[OUTD*H_];
__device__ __align__(16) BF gWol[OUTD*H_];
__device__ __align__(16) BF gXh[(size_t)T_*B_*IN0];
__device__ __align__(16) BF gXl[(size_t)T_*B_*IN0];
__device__ __align__(16) BF gHh[2*SLAB];
__device__ __align__(16) BF gHl[2*SLAB];

__device__ volatile unsigned gBarGen;
__device__ unsigned gBarCnt;

__device__ __forceinline__ float sigf(float x){ return 1.f/(1.f+expf(-x)); }
__device__ __forceinline__ void splitf(float v, BF* h, BF* l){
  BF a=__float2bfloat16(v); *h=a; *l=__float2bfloat16(v-__bfloat162float(a));
}
__device__ __forceinline__ void cp16(BF* d, const BF* s){
  unsigned u=(unsigned)__cvta_generic_to_shared(d);
  asm volatile("cp.async.cg.shared.global [%0],[%1],16;"::"r"(u),"l"(s));
}
__device__ __forceinline__ void cpc(){ asm volatile("cp.async.commit_group;"); }
template<int N> __device__ __forceinline__ void cpw(){ asm volatile("cp.async.wait_group %0;"::"n"(N)); }

__device__ __forceinline__ void gridbar(){
  __syncthreads();
  if(threadIdx.x==0){
    unsigned old = gBarGen;
    __threadfence();
    unsigned prev = atomicAdd(&gBarCnt,1u);
    if(prev==NBLK-1u){ gBarCnt=0u; __threadfence(); gBarGen=old+1u; }
    else { while(gBarGen==old){} }
    __threadfence();
  }
  __syncthreads();
}

// tiles: rows x 64 bf16, 128B rows, 8-way 16B XOR swizzle
__device__ __forceinline__ const BF* swp(const BF* t_, int r, int cseg){
  return t_ + r*64 + ((cseg ^ (r&7))<<3);
}
__device__ __forceinline__ void stT(BF* dh, BF* dl, const BF* ph, const BF* pl,
                                    int ld, int rows, int tid, int nthr){
  for(int u=tid; u<rows*8; u+=nthr){
    int r=u>>3, cs=u&7;
    int off = r*64 + ((cs ^ (r&7))<<3);
    size_t g=(size_t)r*ld + cs*8;
    cp16(dh+off, ph+g); cp16(dl+off, pl+g);
  }
}
__device__ __forceinline__ void ldsm4(unsigned a[4], const BF* p){
  unsigned u=(unsigned)__cvta_generic_to_shared(p);
  asm volatile("ldmatrix.sync.aligned.m8n8.x4.shared.b16 {%0,%1,%2,%3},[%4];"
    :"=r"(a[0]),"=r"(a[1]),"=r"(a[2]),"=r"(a[3]):"r"(u));
}
__device__ __forceinline__ void ldsm2(unsigned b[2], const BF* p){
  unsigned u=(unsigned)__cvta_generic_to_shared(p);
  asm volatile("ldmatrix.sync.aligned.m8n8.x2.shared.b16 {%0,%1},[%2];"
    :"=r"(b[0]),"=r"(b[1]):"r"(u));
}
__device__ __forceinline__ void mma(float c[4], const unsigned a[4], const unsigned b[2]){
  asm volatile("mma.sync.aligned.m16n8k16.row.col.f32.bf16.bf16.f32 "
    "{%0,%1,%2,%3},{%4,%5,%6,%7},{%8,%9},{%0,%1,%2,%3};"
    :"+f"(c[0]),"+f"(c[1]),"+f"(c[2]),"+f"(c[3])
    :"r"(a[0]),"r"(a[1]),"r"(a[2]),"r"(a[3]),"r"(b[0]),"r"(b[1]));
}
// x4 B load covering an nt-pair (two 8-row tiles) x 16 k
__device__ __forceinline__ void ldsm4b(unsigned b[4], const BF* t_, int np, int cs, int lane){
  int row  = np*16 + ((lane>>4)<<3) + (lane&7);
  int cseg = cs + ((lane>>3)&1);
  ldsm4(b, t_ + row*64 + ((cseg ^ (row&7))<<3));
}
// one 32-wide K slice of C(16 x NP*16); paired-B version
template<int NP>
__device__ __forceinline__ void mm32p(float (*acc)[4], const BF* Ah,const BF* Al,
     const BF* Wh,const BF* Wl, int kbase, int rA,int cA,int lane){
#pragma unroll
  for(int kk=0;kk<2;kk++){
    int cs=(kbase>>3)+kk*2;
    unsigned ah[4],al[4];
    ldsm4(ah,swp(Ah,rA,cs+cA)); ldsm4(al,swp(Al,rA,cs+cA));
#pragma unroll
    for(int np=0;np<NP;np++){
      unsigned bh4[4],bl4[4];
      ldsm4b(bh4,Wh,np,cs,lane); ldsm4b(bl4,Wl,np,cs,lane);
      mma(acc[2*np],ah,bh4);     mma(acc[2*np],ah,bl4);     mma(acc[2*np],al,bh4);
      mma(acc[2*np+1],ah,bh4+2); mma(acc[2*np+1],ah,bl4+2); mma(acc[2*np+1],al,bh4+2);
    }
  }
}
// NT-tile version (skip + k_out)
template<int NT>
__device__ __forceinline__ void mm32(float (*acc)[4], const BF* Ah,const BF* Al,
     const BF* Wh,const BF* Wl, int kbase, int rA,int cA,int nB,int cB){
#pragma unroll
  for(int kk=0;kk<2;kk++){
    int cs=(kbase>>3)+kk*2;
    unsigned ah[4],al[4];
    ldsm4(ah,swp(Ah,rA,cs+cA)); ldsm4(al,swp(Al,rA,cs+cA));
#pragma unroll
    for(int nt=0;nt<NT;nt++){
      unsigned bh[2],bl[2];
      ldsm2(bh,swp(Wh,nt*8+nB,cs+cB)); ldsm2(bl,swp(Wl,nt*8+nB,cs+cB));
      mma(acc[nt],ah,bh); mma(acc[nt],ah,bl); mma(acc[nt],al,bh);
    }
  }
}

// ---------------- prep ----------------
__global__ void k_prepX(const float* __restrict__ x){
  size_t n=(size_t)T_*B_*IN0;
  for(size_t i=(size_t)blockIdx.x*blockDim.x+threadIdx.x;i<n;i+=(size_t)gridDim.x*blockDim.x)
    splitf(x[i],&gXh[i],&gXl[i]);
}
__global__ void k_prepG(const float* __restrict__ Wih,const float* __restrict__ Whh,int layer){
  const int KA1=layer?H_:IN0, KG=KA1+H_;
  BF* dh=layer?gG1h:gG0h; BF* dl=layer?gG1l:gG0l;
  size_t n=(size_t)NBLK*32*KG;
  for(size_t i=(size_t)blockIdx.x*blockDim.x+threadIdx.x;i<n;i+=(size_t)gridDim.x*blockDim.x){
    int k=(int)(i%KG); int q=(int)(i/KG); int nr=q&31, blk=q>>5;
    int row=(nr>>3)*H_+blk*8+(nr&7);
    float v = (k<KA1)? Wih[(size_t)row*KA1+k] : Whh[(size_t)row*H_+(k-KA1)];
    splitf(v,&dh[i],&dl[i]);
  }
}
__global__ void k_prepS2(const float* __restrict__ Wh2,int layer){
  BF* dh=gSkh+(size_t)layer*NBLK*8*1024; BF* dl=gSkl+(size_t)layer*NBLK*8*1024;
  int n=NBLK*8*1024;
  for(int i=blockIdx.x*blockDim.x+threadIdx.x;i<n;i+=gridDim.x*blockDim.x){
    int k=i&1023; int q=i>>10; int nr=q&7, blk=q>>3;
    splitf(Wh2[(size_t)k*H_+blk*8+nr],&dh[i],&dl[i]);
  }
}
__global__ void k_prepWo(const float* __restrict__ W){
  for(int i=blockIdx.x*blockDim.x+threadIdx.x;i<OUTD*H_;i+=gridDim.x*blockDim.x)
    splitf(W[i],&gWoh[i],&gWol[i]);
}

// ---------------- persistent recurrence ----------------
// smem: sA 4 x (hi4096|lo4096)=64KB @0 ; sW 4 x (hi2048|lo2048)=32KB @65536 ;
// Cred 64x40 f32 @98304 -> total 108544
__global__ void __launch_bounds__(256,1) k_persist(const int* __restrict__ mask,
    const float* __restrict__ h0, const float* __restrict__ c0,
    const float* __restrict__ bih0,const float* __restrict__ bhh0,const float* __restrict__ bh20,
    const float* __restrict__ bih1,const float* __restrict__ bhh1,const float* __restrict__ bh21)
{
  extern __shared__ char smx[];
  BF* sA=(BF*)smx;
  BF* sW=(BF*)(smx+65536);
  float* Cred=(float*)(smx+98304);
  const int tid=threadIdx.x, lane=tid&31, w=tid>>5, blk=blockIdx.x;
  const int kg=w>>2, r0=(w&3)*16;
  const int rA=r0+(lane&7)+((lane>>3)&1)*8, cA=(lane>>4)&1;
  const int nB=lane&7, cB=(lane>>3)&1;
  const int rr=r0+(lane>>2), cc=(lane&3)*2;
  const int kbase=kg*32;

  float creg[2][4];
  if(w<4){
#pragma unroll
    for(int q=0;q<2;q++)
#pragma unroll
      for(int p=0;p<2;p++){
        int r=rr+q*8, j=blk*8+cc+p, idx=q*2+p;
        creg[0][idx]=c0[(size_t)r*H_+j];
        creg[1][idx]=c0[(size_t)(B_+r)*H_+j];
#pragma unroll
        for(int L=0;L<2;L++){
          size_t b0=(size_t)L*SLAB+(size_t)r*H_+j;
          gHh[b0]=__float2bfloat16(0.f); gHl[b0]=__float2bfloat16(0.f);
          splitf(h0[(size_t)(L*B_+r)*H_+j],&gHh[b0+SLOT],&gHl[b0+SLOT]);
        }
      }
  }
  gridbar();

  for(int t=0;t<T_;t++){
#pragma unroll 1
    for(int L=0;L<2;L++){
      const int KA1=L?H_:IN0, KG=KA1+H_;
      const int NG=KG>>6, NIT=NG+16;
      const BF* Gh=(L?gG1h:gG0h)+(size_t)blk*32*KG;
      const BF* Gl=(L?gG1l:gG0l)+(size_t)blk*32*KG;
      const BF* Sh=gSkh+(size_t)L*NBLK*8*1024+(size_t)blk*8*1024;
      const BF* Sl=gSkl+(size_t)L*NBLK*8*1024+(size_t)blk*8*1024;
      const BF* skAh=gHh+(size_t)L*SLAB+(size_t)t*SLOT;
      const BF* skAl=gHl+(size_t)L*SLAB+(size_t)t*SLOT;

      float acc[5][4];
#pragma unroll
      for(int i=0;i<5;i++){acc[i][0]=0;acc[i][1]=0;acc[i][2]=0;acc[i][3]=0;}

      auto do_stage=[&](int it){
        int st=it&3;
        BF* dA=sA+st*8192; BF* dW=sW+st*4096;
        if(it<NG){
          int k0=it*64;
          const BF *ph,*pl; int ld;
          if(L==0){
            if(k0<IN0){ph=gXh+(size_t)t*B_*IN0+k0; pl=gXl+(size_t)t*B_*IN0+k0; ld=IN0;}
            else {ph=gHh+(size_t)(t+1)*SLOT+(k0-IN0); pl=gHl+(size_t)(t+1)*SLOT+(k0-IN0); ld=H_;}
          }else{
            if(k0<H_){ph=gHh+(size_t)(t+2)*SLOT+k0; pl=gHl+(size_t)(t+2)*SLOT+k0; ld=H_;}
            else {ph=gHh+SLAB+(size_t)(t+1)*SLOT+(k0-H_); pl=gHl+SLAB+(size_t)(t+1)*SLOT+(k0-H_); ld=H_;}
          }
          stT(dA,dA+4096,ph,pl,ld,64,tid,256);
          stT(dW,dW+2048,Gh+k0,Gl+k0,KG,32,tid,256);
        }else{
          int k0=(it-NG)*64;
          stT(dA,dA+4096,skAh+k0,skAl+k0,H_,64,tid,256);
          stT(dW,dW+2048,Sh+k0,Sl+k0,1024,8,tid,256);
        }
        cpc();
      };

      do_stage(0); do_stage(1); do_stage(2);
#pragma unroll 1
      for(int it=0;it<NIT;it++){
        int rem=NIT-1-it;
        if(rem>1) cpw<2>(); else if(rem==1) cpw<1>(); else cpw<0>();
        __syncthreads();
        int st=it&3;
        BF* bA=sA+st*8192; BF* bW=sW+st*4096;
        if(it<NG) mm32p<2>(acc,bA,bA+4096,bW,bW+2048,kbase,rA,cA,lane);
        else      mm32<1>(acc+4,bA,bA+4096,bW,bW+2048,kbase,rA,cA,nB,cB);
        if(it+3<NIT) do_stage(it+3);
      }

      // k-split reduction: kg=1 warps dump partials
      if(w>=4){
#pragma unroll
        for(int nt=0;nt<5;nt++)
#pragma unroll
          for(int q=0;q<2;q++)
#pragma unroll
            for(int p=0;p<2;p++)
              Cred[(rr+q*8)*40+nt*8+cc+p]=acc[nt][q*2+p];
      }
      __syncthreads();
      if(w<4){
        const float* bi=L?bih1:bih0; const float* bh=L?bhh1:bhh0; const float* b2=L?bh21:bh20;
#pragma unroll
        for(int q=0;q<2;q++)
#pragma unroll
          for(int p=0;p<2;p++){
            int r=rr+q*8, jl=cc+p, j=blk*8+jl, idx=q*2+p;
            float ig=acc[0][idx]+Cred[r*40+jl]      +bi[j]     +bh[j];
            float fg=acc[1][idx]+Cred[r*40+8+jl]    +bi[H_+j]  +bh[H_+j];
            float gg=acc[2][idx]+Cred[r*40+16+jl]   +bi[2*H_+j]+bh[2*H_+j];
            float og=acc[3][idx]+Cred[r*40+24+jl]   +bi[3*H_+j]+bh[3*H_+j];
            float sk=acc[4][idx]+Cred[r*40+32+jl]   +b2[j];
            float cv=creg[L][idx];
            float cn=sigf(fg)*cv+sigf(ig)*tanhf(gg);
            float h1=sigf(og)*tanhf(cn);
            float h2=sigf(sk);
            int code=mask[(size_t)t*2*H_+(size_t)L*H_+j];
            float hn=(code!=1?h1:0.f)+(code!=0?h2:0.f);
            creg[L][idx]=cn;
            size_t hi=(size_t)L*SLAB+(size_t)(t+2)*SLOT+(size_t)r*H_+j;
            splitf(hn,&gHh[hi],&gHl[hi]);
          }
      }
      if(L==0) gridbar();   // single grid barrier per step; L1->L0(t+1) needs none
    }
  }
}

// ---------------- output GEMM ----------------
__global__ void __launch_bounds__(256,1) k_out(const float* __restrict__ bo, float* __restrict__ out){
  extern __shared__ char smx[];
  BF* sA=(BF*)smx;
  BF* sW=(BF*)(smx+65536);
  float* Cred=(float*)(smx+131072);
  const int tid=threadIdx.x, lane=tid&31, w=tid>>5;
  const int kg=w>>2, r0=(w&3)*16;
  const int rA=r0+(lane&7)+((lane>>3)&1)*8, cA=(lane>>4)&1;
  const int rr=r0+(lane>>2), cc=(lane&3)*2;
  const int kbase=kg*32;
  const int t=blockIdx.x, n0=blockIdx.y*64;
  const BF* Ah=gHh+SLAB+(size_t)(t+2)*SLOT;
  const BF* Al=gHl+SLAB+(size_t)(t+2)*SLOT;
  const BF* Wh=gWoh+(size_t)n0*H_;
  const BF* Wl=gWol+(size_t)n0*H_;
  float acc[8][4];
#pragma unroll
  for(int i=0;i<8;i++){acc[i][0]=0;acc[i][1]=0;acc[i][2]=0;acc[i][3]=0;}
  auto do_stage=[&](int it){
    int st=it&3, k0=it*64;
    BF* dA=sA+st*8192; BF* dW=sW+st*8192;
    stT(dA,dA+4096,Ah+k0,Al+k0,H_,64,tid,256);
    stT(dW,dW+4096,Wh+k0,Wl+k0,H_,64,tid,256);
    cpc();
  };
  do_stage(0); do_stage(1); do_stage(2);
#pragma unroll 1
  for(int it=0;it<16;it++){
    int rem=15-it;
    if(rem>1) cpw<2>(); else if(rem==1) cpw<1>(); else cpw<0>();
    __syncthreads();
    int st=it&3;
    BF* bA=sA+st*8192; BF* bW=sW+st*8192;
    mm32p<4>(acc,bA,bA+4096,bW,bW+4096,kbase,rA,cA,lane);
    if(it+3<16) do_stage(it+3);
  }
  if(w>=4){
#pragma unroll
    for(int nt=0;nt<8;nt++)
#pragma unroll
      for(int q=0;q<2;q++)
#pragma unroll
        for(int p=0;p<2;p++)
          Cred[(rr+q*8)*64+nt*8+cc+p]=acc[nt][q*2+p];
  }
  __syncthreads();
  if(w<4){
#pragma unroll
    for(int nt=0;nt<8;nt++)
#pragma unroll
      for(int q=0;q<2;q++)
#pragma unroll
        for(int p=0;p<2;p++){
          int r=rr+q*8, col=n0+nt*8+cc+p;
          float v=acc[nt][q*2+p]+Cred[r*64+nt*8+cc+p]+bo[col];
          out[(size_t)t*B_*OUTD+(size_t)r*OUTD+col]=v;
        }
  }
}

extern "C" void kernel_launch(void* const* d_in, const int* in_sizes, int n_in,
                              void* d_out, int out_size) {
  const float* targets=(const float*)d_in[0];
  const float* h0  =(const float*)d_in[1];
  const float* c0  =(const float*)d_in[2];
  const int*   mask=(const int*)  d_in[3];
  const float* Wih0=(const float*)d_in[4];
  const float* Whh0=(const float*)d_in[5];
  const float* bih0=(const float*)d_in[6];
  const float* bhh0=(const float*)d_in[7];
  const float* Wih1=(const float*)d_in[8];
  const float* Whh1=(const float*)d_in[9];
  const float* bih1=(const float*)d_in[10];
  const float* bhh1=(const float*)d_in[11];
  const float* Wh20=(const float*)d_in[12];
  const float* bh20=(const float*)d_in[13];
  const float* Wh21=(const float*)d_in[14];
  const float* bh21=(const float*)d_in[15];
  const float* Wout=(const float*)d_in[16];
  const float* bout=(const float*)d_in[17];

  static int inited=0;
  if(!inited){
    cudaFuncSetAttribute(k_persist, cudaFuncAttributeMaxDynamicSharedMemorySize, 108544);
    cudaFuncSetAttribute(k_out,     cudaFuncAttributeMaxDynamicSharedMemorySize, 147456);
    inited=1;
  }
  // launch order chosen so k_persist is launch index 5 (ncu -s 5 -c 1 profiles it)
  k_prepX<<<4096,256>>>(targets);
  k_prepG<<<4096,256>>>(Wih0,Whh0,0);
  k_prepG<<<4096,256>>>(Wih1,Whh1,1);
  k_prepS2<<<512,256>>>(Wh20,0);
  k_prepS2<<<512,256>>>(Wh21,1);
  k_persist<<<NBLK,256,108544>>>(mask,h0,c0,bih0,bhh0,bh20,bih1,bhh1,bh21);
  k_prepWo<<<512,256>>>(Wout);
  k_out<<<dim3(T_,8),256,147456>>>(bout,(float*)d_out);
}

// round 9
// speedup vs baseline: 1.7174x; 1.1521x over previous
#include <cuda_runtime.h>
#include <cuda_bf16.h>
#include <math.h>
#include <stdint.h>

typedef __nv_bfloat16 BF;
#define T_ 512
#define B_ 64
#define H_ 1024
#define IN0 1536
#define OUTD 512
#define SLOT (B_*H_)
#define SLAB ((size_t)514*SLOT)
#define NBLK 128

__device__ __align__(16) BF gG0h[(size_t)NBLK*32*2560];
__device__ __align__(16) BF gG0l[(size_t)NBLK*32*2560];
__device__ __align__(16) BF gG1h[(size_t)NBLK*32*2048];
__device__ __align__(16) BF gG1l[(size_t)NBLK*32*2048];
__device__ __align__(16) BF gSkh[(size_t)2*NBLK*8*1024];
__device__ __align__(16) BF gSkl[(size_t)2*NBLK*8*1024];
__device__ __align__(16) BF gWoh[OUTD*H_];
__device__ __align__(16) BF gWol[OUTD*H_];
__device__ __align__(16) BF gXh[(size_t)T_*B_*IN0];
__device__ __align__(16) BF gXl[(size_t)T_*B_*IN0];
__device__ __align__(16) BF gHh[2*SLAB];
__device__ __align__(16) BF gHl[2*SLAB];

__device__ volatile unsigned gBarGen;
__device__ unsigned gBarCnt;

__device__ __forceinline__ float sigf(float x){ return 1.f/(1.f+expf(-x)); }
__device__ __forceinline__ void splitf(float v, BF* h, BF* l){
  BF a=__float2bfloat16(v); *h=a; *l=__float2bfloat16(v-__bfloat162float(a));
}
__device__ __forceinline__ void cp16(BF* d, const BF* s){
  unsigned u=(unsigned)__cvta_generic_to_shared(d);
  asm volatile("cp.async.cg.shared.global [%0],[%1],16;"::"r"(u),"l"(s));
}
__device__ __forceinline__ void cpc(){ asm volatile("cp.async.commit_group;"); }
template<int N> __device__ __forceinline__ void cpw(){ asm volatile("cp.async.wait_group %0;"::"n"(N)); }

__device__ __forceinline__ void gridbar(){
  __syncthreads();
  if(threadIdx.x==0){
    unsigned old = gBarGen;
    __threadfence();
    unsigned prev = atomicAdd(&gBarCnt,1u);
    if(prev==NBLK-1u){ gBarCnt=0u; __threadfence(); gBarGen=old+1u; }
    else { while(gBarGen==old){} }
    __threadfence();
  }
  __syncthreads();
}

// tiles: rows x 64 bf16, 128B rows, 8-way 16B XOR swizzle
__device__ __forceinline__ const BF* swp(const BF* t_, int r, int cseg){
  return t_ + r*64 + ((cseg ^ (r&7))<<3);
}
__device__ __forceinline__ void stT(BF* dh, BF* dl, const BF* ph, const BF* pl,
                                    int ld, int rows, int tid, int nthr){
  for(int u=tid; u<rows*8; u+=nthr){
    int r=u>>3, cs=u&7;
    int off = r*64 + ((cs ^ (r&7))<<3);
    size_t g=(size_t)r*ld + cs*8;
    cp16(dh+off, ph+g); cp16(dl+off, pl+g);
  }
}
__device__ __forceinline__ void ldsm4(unsigned a[4], const BF* p){
  unsigned u=(unsigned)__cvta_generic_to_shared(p);
  asm volatile("ldmatrix.sync.aligned.m8n8.x4.shared.b16 {%0,%1,%2,%3},[%4];"
    :"=r"(a[0]),"=r"(a[1]),"=r"(a[2]),"=r"(a[3]):"r"(u));
}
__device__ __forceinline__ void ldsm2(unsigned b[2], const BF* p){
  unsigned u=(unsigned)__cvta_generic_to_shared(p);
  asm volatile("ldmatrix.sync.aligned.m8n8.x2.shared.b16 {%0,%1},[%2];"
    :"=r"(b[0]),"=r"(b[1]):"r"(u));
}
__device__ __forceinline__ void mma(float c[4], const unsigned a[4], const unsigned b[2]){
  asm volatile("mma.sync.aligned.m16n8k16.row.col.f32.bf16.bf16.f32 "
    "{%0,%1,%2,%3},{%4,%5,%6,%7},{%8,%9},{%0,%1,%2,%3};"
    :"+f"(c[0]),"+f"(c[1]),"+f"(c[2]),"+f"(c[3])
    :"r"(a[0]),"r"(a[1]),"r"(a[2]),"r"(a[3]),"r"(b[0]),"r"(b[1]));
}
// x4 B load covering an nt-pair (two 8-row tiles) x 16 k
__device__ __forceinline__ void ldsm4b(unsigned b[4], const BF* t_, int np, int cs, int lane){
  int row  = np*16 + ((lane>>4)<<3) + (lane&7);
  int cseg = cs + ((lane>>3)&1);
  ldsm4(b, t_ + row*64 + ((cseg ^ (row&7))<<3));
}
// one 32-wide K slice of C(16 x NP*16); paired-B version
template<int NP>
__device__ __forceinline__ void mm32p(float (*acc)[4], const BF* Ah,const BF* Al,
     const BF* Wh,const BF* Wl, int kbase, int rA,int cA,int lane){
#pragma unroll
  for(int kk=0;kk<2;kk++){
    int cs=(kbase>>3)+kk*2;
    unsigned ah[4],al[4];
    ldsm4(ah,swp(Ah,rA,cs+cA)); ldsm4(al,swp(Al,rA,cs+cA));
#pragma unroll
    for(int np=0;np<NP;np++){
      unsigned bh4[4],bl4[4];
      ldsm4b(bh4,Wh,np,cs,lane); ldsm4b(bl4,Wl,np,cs,lane);
      mma(acc[2*np],ah,bh4);     mma(acc[2*np],ah,bl4);     mma(acc[2*np],al,bh4);
      mma(acc[2*np+1],ah,bh4+2); mma(acc[2*np+1],ah,bl4+2); mma(acc[2*np+1],al,bh4+2);
    }
  }
}
// NT-tile version (skip phase)
template<int NT>
__device__ __forceinline__ void mm32(float (*acc)[4], const BF* Ah,const BF* Al,
     const BF* Wh,const BF* Wl, int kbase, int rA,int cA,int nB,int cB){
#pragma unroll
  for(int kk=0;kk<2;kk++){
    int cs=(kbase>>3)+kk*2;
    unsigned ah[4],al[4];
    ldsm4(ah,swp(Ah,rA,cs+cA)); ldsm4(al,swp(Al,rA,cs+cA));
#pragma unroll
    for(int nt=0;nt<NT;nt++){
      unsigned bh[2],bl[2];
      ldsm2(bh,swp(Wh,nt*8+nB,cs+cB)); ldsm2(bl,swp(Wl,nt*8+nB,cs+cB));
      mma(acc[nt],ah,bh); mma(acc[nt],ah,bl); mma(acc[nt],al,bh);
    }
  }
}

// ---------------- prep (4 launches so k_persist is launch #5) ----------------
__global__ void k_prepX(const float* __restrict__ x){
  size_t n=(size_t)T_*B_*IN0;
  for(size_t i=(size_t)blockIdx.x*blockDim.x+threadIdx.x;i<n;i+=(size_t)gridDim.x*blockDim.x)
    splitf(x[i],&gXh[i],&gXl[i]);
}
__global__ void k_prepG(const float* __restrict__ Wih0,const float* __restrict__ Whh0,
                        const float* __restrict__ Wih1,const float* __restrict__ Whh1){
  const size_t n0=(size_t)NBLK*32*2560, n1=(size_t)NBLK*32*2048;
  for(size_t i=(size_t)blockIdx.x*blockDim.x+threadIdx.x;i<n0+n1;i+=(size_t)gridDim.x*blockDim.x){
    int layer = i>=n0;
    size_t ii = layer? i-n0 : i;
    const int KA1=layer?H_:IN0, KG=KA1+H_;
    const float* Wih=layer?Wih1:Wih0; const float* Whh=layer?Whh1:Whh0;
    BF* dh=layer?gG1h:gG0h; BF* dl=layer?gG1l:gG0l;
    int k=(int)(ii%KG); int q=(int)(ii/KG); int nr=q&31, blk=q>>5;
    int row=(nr>>3)*H_+blk*8+(nr&7);
    float v = (k<KA1)? Wih[(size_t)row*KA1+k] : Whh[(size_t)row*H_+(k-KA1)];
    splitf(v,&dh[ii],&dl[ii]);
  }
}
__global__ void k_prepS2(const float* __restrict__ W0,const float* __restrict__ W1){
  const int n=NBLK*8*1024;
  for(int i=blockIdx.x*blockDim.x+threadIdx.x;i<2*n;i+=gridDim.x*blockDim.x){
    int layer=i>=n, ii=layer?i-n:i;
    const float* W=layer?W1:W0;
    BF* dh=gSkh+(size_t)layer*n; BF* dl=gSkl+(size_t)layer*n;
    int k=ii&1023; int q=ii>>10; int nr=q&7, blk=q>>3;
    splitf(W[(size_t)k*H_+blk*8+nr],&dh[ii],&dl[ii]);
  }
}
__global__ void k_prepWo(const float* __restrict__ W){
  for(int i=blockIdx.x*blockDim.x+threadIdx.x;i<OUTD*H_;i+=gridDim.x*blockDim.x)
    splitf(W[i],&gWoh[i],&gWol[i]);
}

// ---------------- persistent recurrence ----------------
// smem: sA 3 stages x 16384 elems (sub0 hi|lo, sub1 hi|lo) = 96KB @0
//       sW 3 stages x 8192 elems = 48KB @98304 ; Cred 64x40 f32 @147456 -> 157696
__global__ void __launch_bounds__(256,1) k_persist(const int* __restrict__ mask,
    const float* __restrict__ h0, const float* __restrict__ c0,
    const float* __restrict__ bih0,const float* __restrict__ bhh0,const float* __restrict__ bh20,
    const float* __restrict__ bih1,const float* __restrict__ bhh1,const float* __restrict__ bh21)
{
  extern __shared__ char smx[];
  BF* sA=(BF*)smx;
  BF* sW=(BF*)(smx+98304);
  float* Cred=(float*)(smx+147456);
  const int tid=threadIdx.x, lane=tid&31, w=tid>>5, blk=blockIdx.x;
  const int kg=w>>2, r0=(w&3)*16;
  const int rA=r0+(lane&7)+((lane>>3)&1)*8, cA=(lane>>4)&1;
  const int nB=lane&7, cB=(lane>>3)&1;
  const int rr=r0+(lane>>2), cc=(lane&3)*2;
  const int kbase=kg*32;

  float creg[2][4];
  if(w<4){
#pragma unroll
    for(int q=0;q<2;q++)
#pragma unroll
      for(int p=0;p<2;p++){
        int r=rr+q*8, j=blk*8+cc+p, idx=q*2+p;
        creg[0][idx]=c0[(size_t)r*H_+j];
        creg[1][idx]=c0[(size_t)(B_+r)*H_+j];
#pragma unroll
        for(int L=0;L<2;L++){
          size_t b0=(size_t)L*SLAB+(size_t)r*H_+j;
          gHh[b0]=__float2bfloat16(0.f); gHl[b0]=__float2bfloat16(0.f);
          splitf(h0[(size_t)(L*B_+r)*H_+j],&gHh[b0+SLOT],&gHl[b0+SLOT]);
        }
      }
  }
  gridbar();

  for(int t=0;t<T_;t++){
#pragma unroll 1
    for(int L=0;L<2;L++){
      const int KA1=L?H_:IN0, KG=KA1+H_;
      const int NG2=KG>>7, NIT=NG2+8;         // 128-wide chunks: gates + skip(1024)
      const BF* Gh=(L?gG1h:gG0h)+(size_t)blk*32*KG;
      const BF* Gl=(L?gG1l:gG0l)+(size_t)blk*32*KG;
      const BF* Sh=gSkh+(size_t)L*NBLK*8*1024+(size_t)blk*8*1024;
      const BF* Sl=gSkl+(size_t)L*NBLK*8*1024+(size_t)blk*8*1024;
      const BF* skAh=gHh+(size_t)L*SLAB+(size_t)t*SLOT;
      const BF* skAl=gHl+(size_t)L*SLAB+(size_t)t*SLOT;

      float acc[5][4];
#pragma unroll
      for(int i=0;i<5;i++){acc[i][0]=0;acc[i][1]=0;acc[i][2]=0;acc[i][3]=0;}

      auto do_stage=[&](int it){
        int st=it%3;
        BF* dA=sA+st*16384; BF* dW=sW+st*8192;
#pragma unroll
        for(int half=0;half<2;half++){
          BF* dAh=dA+half*8192; BF* dWh=dW+half*4096;
          if(it<NG2){
            int k0=it*128+half*64;
            const BF *ph,*pl; int ld;
            if(L==0){
              if(k0<IN0){ph=gXh+(size_t)t*B_*IN0+k0; pl=gXl+(size_t)t*B_*IN0+k0; ld=IN0;}
              else {ph=gHh+(size_t)(t+1)*SLOT+(k0-IN0); pl=gHl+(size_t)(t+1)*SLOT+(k0-IN0); ld=H_;}
            }else{
              if(k0<H_){ph=gHh+(size_t)(t+2)*SLOT+k0; pl=gHl+(size_t)(t+2)*SLOT+k0; ld=H_;}
              else {ph=gHh+SLAB+(size_t)(t+1)*SLOT+(k0-H_); pl=gHl+SLAB+(size_t)(t+1)*SLOT+(k0-H_); ld=H_;}
            }
            stT(dAh,dAh+4096,ph,pl,ld,64,tid,256);
            stT(dWh,dWh+2048,Gh+k0,Gl+k0,KG,32,tid,256);
          }else{
            int k0=(it-NG2)*128+half*64;
            stT(dAh,dAh+4096,skAh+k0,skAl+k0,H_,64,tid,256);
            stT(dWh,dWh+2048,Sh+k0,Sl+k0,1024,8,tid,256);
          }
        }
        cpc();
      };

      do_stage(0); do_stage(1);
#pragma unroll 1
      for(int it=0;it<NIT;it++){
        if(it+1<NIT) cpw<1>(); else cpw<0>();
        __syncthreads();
        if(it+2<NIT) do_stage(it+2);
        int st=it%3;
        BF* bA=sA+st*16384; BF* bW=sW+st*8192;
        if(it<NG2){
          mm32p<2>(acc,bA,bA+4096,bW,bW+2048,kbase,rA,cA,lane);
          mm32p<2>(acc,bA+8192,bA+12288,bW+4096,bW+6144,kbase,rA,cA,lane);
        }else{
          mm32<1>(acc+4,bA,bA+4096,bW,bW+2048,kbase,rA,cA,nB,cB);
          mm32<1>(acc+4,bA+8192,bA+12288,bW+4096,bW+6144,kbase,rA,cA,nB,cB);
        }
      }
      __syncthreads();

      // k-split reduction: kg=1 warps dump partials
      if(w>=4){
#pragma unroll
        for(int nt=0;nt<5;nt++)
#pragma unroll
          for(int q=0;q<2;q++)
#pragma unroll
            for(int p=0;p<2;p++)
              Cred[(rr+q*8)*40+nt*8+cc+p]=acc[nt][q*2+p];
      }
      __syncthreads();
      if(w<4){
        const float* bi=L?bih1:bih0; const float* bh=L?bhh1:bhh0; const float* b2=L?bh21:bh20;
#pragma unroll
        for(int q=0;q<2;q++)
#pragma unroll
          for(int p=0;p<2;p++){
            int r=rr+q*8, jl=cc+p, j=blk*8+jl, idx=q*2+p;
            float ig=acc[0][idx]+Cred[r*40+jl]      +bi[j]     +bh[j];
            float fg=acc[1][idx]+Cred[r*40+8+jl]    +bi[H_+j]  +bh[H_+j];
            float gg=acc[2][idx]+Cred[r*40+16+jl]   +bi[2*H_+j]+bh[2*H_+j];
            float og=acc[3][idx]+Cred[r*40+24+jl]   +bi[3*H_+j]+bh[3*H_+j];
            float sk=acc[4][idx]+Cred[r*40+32+jl]   +b2[j];
            float cv=creg[L][idx];
            float cn=sigf(fg)*cv+sigf(ig)*tanhf(gg);
            float h1=sigf(og)*tanhf(cn);
            float h2=sigf(sk);
            int code=mask[(size_t)t*2*H_+(size_t)L*H_+j];
            float hn=(code!=1?h1:0.f)+(code!=0?h2:0.f);
            creg[L][idx]=cn;
            size_t hi=(size_t)L*SLAB+(size_t)(t+2)*SLOT+(size_t)r*H_+j;
            splitf(hn,&gHh[hi],&gHl[hi]);
          }
      }
      if(L==0) gridbar();   // single grid barrier per step
    }
  }
}

// ---------------- output GEMM ----------------
__global__ void __launch_bounds__(256,1) k_out(const float* __restrict__ bo, float* __restrict__ out){
  extern __shared__ char smx[];
  BF* sA=(BF*)smx;
  BF* sW=(BF*)(smx+65536);
  float* Cred=(float*)(smx+131072);
  const int tid=threadIdx.x, lane=tid&31, w=tid>>5;
  const int kg=w>>2, r0=(w&3)*16;
  const int rA=r0+(lane&7)+((lane>>3)&1)*8, cA=(lane>>4)&1;
  const int rr=r0+(lane>>2), cc=(lane&3)*2;
  const int kbase=kg*32;
  const int t=blockIdx.x, n0=blockIdx.y*64;
  const BF* Ah=gHh+SLAB+(size_t)(t+2)*SLOT;
  const BF* Al=gHl+SLAB+(size_t)(t+2)*SLOT;
  const BF* Wh=gWoh+(size_t)n0*H_;
  const BF* Wl=gWol+(size_t)n0*H_;
  float acc[8][4];
#pragma unroll
  for(int i=0;i<8;i++){acc[i][0]=0;acc[i][1]=0;acc[i][2]=0;acc[i][3]=0;}
  auto do_stage=[&](int it){
    int st=it&3, k0=it*64;
    BF* dA=sA+st*8192; BF* dW=sW+st*8192;
    stT(dA,dA+4096,Ah+k0,Al+k0,H_,64,tid,256);
    stT(dW,dW+4096,Wh+k0,Wl+k0,H_,64,tid,256);
    cpc();
  };
  do_stage(0); do_stage(1); do_stage(2);
#pragma unroll 1
  for(int it=0;it<16;it++){
    int rem=15-it;
    if(rem>1) cpw<2>(); else if(rem==1) cpw<1>(); else cpw<0>();
    __syncthreads();
    int st=it&3;
    BF* bA=sA+st*8192; BF* bW=sW+st*8192;
    mm32p<4>(acc,bA,bA+4096,bW,bW+4096,kbase,rA,cA,lane);
    if(it+3<16) do_stage(it+3);
  }
  if(w>=4){
#pragma unroll
    for(int nt=0;nt<8;nt++)
#pragma unroll
      for(int q=0;q<2;q++)
#pragma unroll
        for(int p=0;p<2;p++)
          Cred[(rr+q*8)*64+nt*8+cc+p]=acc[nt][q*2+p];
  }
  __syncthreads();
  if(w<4){
#pragma unroll
    for(int nt=0;nt<8;nt++)
#pragma unroll
      for(int q=0;q<2;q++)
#pragma unroll
        for(int p=0;p<2;p++){
          int r=rr+q*8, col=n0+nt*8+cc+p;
          float v=acc[nt][q*2+p]+Cred[r*64+nt*8+cc+p]+bo[col];
          out[(size_t)t*B_*OUTD+(size_t)r*OUTD+col]=v;
        }
  }
}

extern "C" void kernel_launch(void* const* d_in, const int* in_sizes, int n_in,
                              void* d_out, int out_size) {
  const float* targets=(const float*)d_in[0];
  const float* h0  =(const float*)d_in[1];
  const float* c0  =(const float*)d_in[2];
  const int*   mask=(const int*)  d_in[3];
  const float* Wih0=(const float*)d_in[4];
  const float* Whh0=(const float*)d_in[5];
  const float* bih0=(const float*)d_in[6];
  const float* bhh0=(const float*)d_in[7];
  const float* Wih1=(const float*)d_in[8];
  const float* Whh1=(const float*)d_in[9];
  const float* bih1=(const float*)d_in[10];
  const float* bhh1=(const float*)d_in[11];
  const float* Wh20=(const float*)d_in[12];
  const float* bh20=(const float*)d_in[13];
  const float* Wh21=(const float*)d_in[14];
  const float* bh21=(const float*)d_in[15];
  const float* Wout=(const float*)d_in[16];
  const float* bout=(const float*)d_in[17];

  static int inited=0;
  if(!inited){
    cudaFuncSetAttribute(k_persist, cudaFuncAttributeMaxDynamicSharedMemorySize, 157696);
    cudaFuncSetAttribute(k_out,     cudaFuncAttributeMaxDynamicSharedMemorySize, 147456);
    inited=1;
  }
  // exactly 4 launches before k_persist -> k_persist is launch #5 (ncu slot)
  k_prepX<<<4096,256>>>(targets);
  k_prepG<<<4096,256>>>(Wih0,Whh0,Wih1,Whh1);
  k_prepS2<<<1024,256>>>(Wh20,Wh21);
  k_prepWo<<<512,256>>>(Wout);
  k_persist<<<NBLK,256,157696>>>(mask,h0,c0,bih0,bhh0,bh20,bih1,bhh1,bh21);
  k_out<<<dim3(T_,8),256,147456>>>(bout,(float*)d_out);
}

// round 10
// speedup vs baseline: 1.7381x; 1.0120x over previous
#include <cuda_runtime.h>
#include <cuda_bf16.h>
#include <math.h>
#include <stdint.h>

typedef __nv_bfloat16 BF;
#define T_ 512
#define B_ 64
#define H_ 1024
#define IN0 1536
#define OUTD 512
#define SLOT (B_*H_)
#define SLAB ((size_t)514*SLOT)
#define NBLK 128

__device__ __align__(16) BF gG0h[(size_t)NBLK*32*2560];
__device__ __align__(16) BF gG0l[(size_t)NBLK*32*2560];
__device__ __align__(16) BF gG1h[(size_t)NBLK*32*2048];
__device__ __align__(16) BF gG1l[(size_t)NBLK*32*2048];
__device__ __align__(16) BF gSkh[(size_t)2*NBLK*8*1024];
__device__ __align__(16) BF gSkl[(size_t)2*NBLK*8*1024];
__device__ __align__(16) BF gWoh[OUTD*H_];
__device__ __align__(16) BF gWol[OUTD*H_];
__device__ __align__(16) BF gXh[(size_t)T_*B_*IN0];
__device__ __align__(16) BF gXl[(size_t)T_*B_*IN0];
__device__ __align__(16) BF gHh[2*SLAB];
__device__ __align__(16) BF gHl[2*SLAB];

__device__ volatile unsigned gBarGen;
__device__ unsigned gBarCnt;

__device__ __forceinline__ float sigf(float x){ return 1.f/(1.f+expf(-x)); }
__device__ __forceinline__ void splitf(float v, BF* h, BF* l){
  BF a=__float2bfloat16(v); *h=a; *l=__float2bfloat16(v-__bfloat162float(a));
}
__device__ __forceinline__ void cp16(BF* d, const BF* s){
  unsigned u=(unsigned)__cvta_generic_to_shared(d);
  asm volatile("cp.async.cg.shared.global [%0],[%1],16;"::"r"(u),"l"(s));
}
__device__ __forceinline__ void cpc(){ asm volatile("cp.async.commit_group;"); }
template<int N> __device__ __forceinline__ void cpw(){ asm volatile("cp.async.wait_group %0;"::"n"(N)); }

__device__ __forceinline__ void gridbar(){
  __syncthreads();
  if(threadIdx.x==0){
    unsigned old = gBarGen;
    __threadfence();
    unsigned prev = atomicAdd(&gBarCnt,1u);
    if(prev==NBLK-1u){ gBarCnt=0u; __threadfence(); gBarGen=old+1u; }
    else { while(gBarGen==old){} }
    __threadfence();
  }
  __syncthreads();
}

// tiles: rows x 64 bf16, 128B rows, 8-way 16B XOR swizzle
__device__ __forceinline__ const BF* swp(const BF* t_, int r, int cseg){
  return t_ + r*64 + ((cseg ^ (r&7))<<3);
}
__device__ __forceinline__ void stT(BF* dh, BF* dl, const BF* ph, const BF* pl,
                                    int ld, int rows, int tid, int nthr){
  for(int u=tid; u<rows*8; u+=nthr){
    int r=u>>3, cs=u&7;
    int off = r*64 + ((cs ^ (r&7))<<3);
    size_t g=(size_t)r*ld + cs*8;
    cp16(dh+off, ph+g); cp16(dl+off, pl+g);
  }
}
__device__ __forceinline__ void ldsm4(unsigned a[4], const BF* p){
  unsigned u=(unsigned)__cvta_generic_to_shared(p);
  asm volatile("ldmatrix.sync.aligned.m8n8.x4.shared.b16 {%0,%1,%2,%3},[%4];"
    :"=r"(a[0]),"=r"(a[1]),"=r"(a[2]),"=r"(a[3]):"r"(u));
}
__device__ __forceinline__ void ldsm2(unsigned b[2], const BF* p){
  unsigned u=(unsigned)__cvta_generic_to_shared(p);
  asm volatile("ldmatrix.sync.aligned.m8n8.x2.shared.b16 {%0,%1},[%2];"
    :"=r"(b[0]),"=r"(b[1]):"r"(u));
}
__device__ __forceinline__ void mma(float c[4], const unsigned a[4], const unsigned b[2]){
  asm volatile("mma.sync.aligned.m16n8k16.row.col.f32.bf16.bf16.f32 "
    "{%0,%1,%2,%3},{%4,%5,%6,%7},{%8,%9},{%0,%1,%2,%3};"
    :"+f"(c[0]),"+f"(c[1]),"+f"(c[2]),"+f"(c[3])
    :"r"(a[0]),"r"(a[1]),"r"(a[2]),"r"(a[3]),"r"(b[0]),"r"(b[1]));
}
// x4 B load covering an nt-pair (two 8-row tiles) x 16 k
__device__ __forceinline__ void ldsm4b(unsigned b[4], const BF* t_, int np, int cs, int lane){
  int row  = np*16 + ((lane>>4)<<3) + (lane&7);
  int cseg = cs + ((lane>>3)&1);
  ldsm4(b, t_ + row*64 + ((cseg ^ (row&7))<<3));
}
// one 32-wide K slice of C(16 x NP*16); paired-B version
template<int NP>
__device__ __forceinline__ void mm32p(float (*acc)[4], const BF* Ah,const BF* Al,
     const BF* Wh,const BF* Wl, int kbase, int rA,int cA,int lane){
#pragma unroll
  for(int kk=0;kk<2;kk++){
    int cs=(kbase>>3)+kk*2;
    unsigned ah[4],al[4];
    ldsm4(ah,swp(Ah,rA,cs+cA)); ldsm4(al,swp(Al,rA,cs+cA));
#pragma unroll
    for(int np=0;np<NP;np++){
      unsigned bh4[4],bl4[4];
      ldsm4b(bh4,Wh,np,cs,lane); ldsm4b(bl4,Wl,np,cs,lane);
      mma(acc[2*np],ah,bh4);     mma(acc[2*np],ah,bl4);     mma(acc[2*np],al,bh4);
      mma(acc[2*np+1],ah,bh4+2); mma(acc[2*np+1],ah,bl4+2); mma(acc[2*np+1],al,bh4+2);
    }
  }
}
// NT-tile version (skip phase)
template<int NT>
__device__ __forceinline__ void mm32(float (*acc)[4], const BF* Ah,const BF* Al,
     const BF* Wh,const BF* Wl, int kbase, int rA,int cA,int nB,int cB){
#pragma unroll
  for(int kk=0;kk<2;kk++){
    int cs=(kbase>>3)+kk*2;
    unsigned ah[4],al[4];
    ldsm4(ah,swp(Ah,rA,cs+cA)); ldsm4(al,swp(Al,rA,cs+cA));
#pragma unroll
    for(int nt=0;nt<NT;nt++){
      unsigned bh[2],bl[2];
      ldsm2(bh,swp(Wh,nt*8+nB,cs+cB)); ldsm2(bl,swp(Wl,nt*8+nB,cs+cB));
      mma(acc[nt],ah,bh); mma(acc[nt],ah,bl); mma(acc[nt],al,bh);
    }
  }
}

// ---------------- prep (3 launches so k_persist is launch #4 = ncu slot) ----------------
__global__ void k_prepX(const float* __restrict__ x){
  size_t n=(size_t)T_*B_*IN0;
  for(size_t i=(size_t)blockIdx.x*blockDim.x+threadIdx.x;i<n;i+=(size_t)gridDim.x*blockDim.x)
    splitf(x[i],&gXh[i],&gXl[i]);
}
__global__ void k_prepG(const float* __restrict__ Wih0,const float* __restrict__ Whh0,
                        const float* __restrict__ Wih1,const float* __restrict__ Whh1){
  const size_t n0=(size_t)NBLK*32*2560, n1=(size_t)NBLK*32*2048;
  for(size_t i=(size_t)blockIdx.x*blockDim.x+threadIdx.x;i<n0+n1;i+=(size_t)gridDim.x*blockDim.x){
    int layer = i>=n0;
    size_t ii = layer? i-n0 : i;
    const int KA1=layer?H_:IN0, KG=KA1+H_;
    const float* Wih=layer?Wih1:Wih0; const float* Whh=layer?Whh1:Whh0;
    BF* dh=layer?gG1h:gG0h; BF* dl=layer?gG1l:gG0l;
    int k=(int)(ii%KG); int q=(int)(ii/KG); int nr=q&31, blk=q>>5;
    int row=(nr>>3)*H_+blk*8+(nr&7);
    float v = (k<KA1)? Wih[(size_t)row*KA1+k] : Whh[(size_t)row*H_+(k-KA1)];
    splitf(v,&dh[ii],&dl[ii]);
  }
}
__global__ void k_prepS2(const float* __restrict__ W0,const float* __restrict__ W1){
  const int n=NBLK*8*1024;
  for(int i=blockIdx.x*blockDim.x+threadIdx.x;i<2*n;i+=gridDim.x*blockDim.x){
    int layer=i>=n, ii=layer?i-n:i;
    const float* W=layer?W1:W0;
    BF* dh=gSkh+(size_t)layer*n; BF* dl=gSkl+(size_t)layer*n;
    int k=ii&1023; int q=ii>>10; int nr=q&7, blk=q>>3;
    splitf(W[(size_t)k*H_+blk*8+nr],&dh[ii],&dl[ii]);
  }
}
__global__ void k_prepWo(const float* __restrict__ W){
  for(int i=blockIdx.x*blockDim.x+threadIdx.x;i<OUTD*H_;i+=gridDim.x*blockDim.x)
    splitf(W[i],&gWoh[i],&gWol[i]);
}

// ---------------- persistent recurrence ----------------
// smem: sA 4 stages x 16384 elems (two 64-col halves, hi|lo) = 128KB @0
//       sW 4 stages x 8192 elems = 64KB @131072 ; Cred 64x40 f32 @196608 -> 206848
__global__ void __launch_bounds__(256,1) k_persist(const int* __restrict__ mask,
    const float* __restrict__ h0, const float* __restrict__ c0,
    const float* __restrict__ bih0,const float* __restrict__ bhh0,const float* __restrict__ bh20,
    const float* __restrict__ bih1,const float* __restrict__ bhh1,const float* __restrict__ bh21)
{
  extern __shared__ char smx[];
  BF* sA=(BF*)smx;
  BF* sW=(BF*)(smx+131072);
  float* Cred=(float*)(smx+196608);
  const int tid=threadIdx.x, lane=tid&31, w=tid>>5, blk=blockIdx.x;
  const int kg=w>>2, r0=(w&3)*16;
  const int rA=r0+(lane&7)+((lane>>3)&1)*8, cA=(lane>>4)&1;
  const int nB=lane&7, cB=(lane>>3)&1;
  const int rr=r0+(lane>>2), cc=(lane&3)*2;
  const int kbase=kg*32;

  float creg[2][4];
  if(w<4){
#pragma unroll
    for(int q=0;q<2;q++)
#pragma unroll
      for(int p=0;p<2;p++){
        int r=rr+q*8, j=blk*8+cc+p, idx=q*2+p;
        creg[0][idx]=c0[(size_t)r*H_+j];
        creg[1][idx]=c0[(size_t)(B_+r)*H_+j];
#pragma unroll
        for(int L=0;L<2;L++){
          size_t b0=(size_t)L*SLAB+(size_t)r*H_+j;
          gHh[b0]=__float2bfloat16(0.f); gHl[b0]=__float2bfloat16(0.f);
          splitf(h0[(size_t)(L*B_+r)*H_+j],&gHh[b0+SLOT],&gHl[b0+SLOT]);
        }
      }
  }
  gridbar();

  for(int t=0;t<T_;t++){
#pragma unroll 1
    for(int L=0;L<2;L++){
      const int KA1=L?H_:IN0, KG=KA1+H_;
      const int NG2=KG>>7, NIT=NG2+8;         // 128-wide chunks: gates + skip(1024)
      const BF* Gh=(L?gG1h:gG0h)+(size_t)blk*32*KG;
      const BF* Gl=(L?gG1l:gG0l)+(size_t)blk*32*KG;
      const BF* Sh=gSkh+(size_t)L*NBLK*8*1024+(size_t)blk*8*1024;
      const BF* Sl=gSkl+(size_t)L*NBLK*8*1024+(size_t)blk*8*1024;
      const BF* skAh=gHh+(size_t)L*SLAB+(size_t)t*SLOT;
      const BF* skAl=gHl+(size_t)L*SLAB+(size_t)t*SLOT;

      float acc[5][4];
#pragma unroll
      for(int i=0;i<5;i++){acc[i][0]=0;acc[i][1]=0;acc[i][2]=0;acc[i][3]=0;}

      auto do_stage=[&](int it){
        int st=it&3;
        BF* dA=sA+st*16384; BF* dW=sW+st*8192;
#pragma unroll
        for(int half=0;half<2;half++){
          BF* dAh=dA+half*8192; BF* dWh=dW+half*4096;
          if(it<NG2){
            int k0=it*128+half*64;
            const BF *ph,*pl; int ld;
            if(L==0){
              if(k0<IN0){ph=gXh+(size_t)t*B_*IN0+k0; pl=gXl+(size_t)t*B_*IN0+k0; ld=IN0;}
              else {ph=gHh+(size_t)(t+1)*SLOT+(k0-IN0); pl=gHl+(size_t)(t+1)*SLOT+(k0-IN0); ld=H_;}
            }else{
              if(k0<H_){ph=gHh+(size_t)(t+2)*SLOT+k0; pl=gHl+(size_t)(t+2)*SLOT+k0; ld=H_;}
              else {ph=gHh+SLAB+(size_t)(t+1)*SLOT+(k0-H_); pl=gHl+SLAB+(size_t)(t+1)*SLOT+(k0-H_); ld=H_;}
            }
            stT(dAh,dAh+4096,ph,pl,ld,64,tid,256);
            stT(dWh,dWh+2048,Gh+k0,Gl+k0,KG,32,tid,256);
          }else{
            int k0=(it-NG2)*128+half*64;
            stT(dAh,dAh+4096,skAh+k0,skAl+k0,H_,64,tid,256);
            stT(dWh,dWh+2048,Sh+k0,Sl+k0,1024,8,tid,256);
          }
        }
        cpc();
      };

      do_stage(0); do_stage(1); do_stage(2);
#pragma unroll 1
      for(int it=0;it<NIT;it++){
        if(it+2<NIT) cpw<2>(); else if(it+1<NIT) cpw<1>(); else cpw<0>();
        __syncthreads();
        if(it+3<NIT) do_stage(it+3);
        int st=it&3;
        BF* bA=sA+st*16384; BF* bW=sW+st*8192;
        if(it<NG2){
          mm32p<2>(acc,bA,bA+4096,bW,bW+2048,kbase,rA,cA,lane);
          mm32p<2>(acc,bA+8192,bA+12288,bW+4096,bW+6144,kbase,rA,cA,lane);
        }else{
          mm32<1>(acc+4,bA,bA+4096,bW,bW+2048,kbase,rA,cA,nB,cB);
          mm32<1>(acc+4,bA+8192,bA+12288,bW+4096,bW+6144,kbase,rA,cA,nB,cB);
        }
      }
      __syncthreads();

      // k-split reduction: kg=1 warps dump partials
      if(w>=4){
#pragma unroll
        for(int nt=0;nt<5;nt++)
#pragma unroll
          for(int q=0;q<2;q++)
#pragma unroll
            for(int p=0;p<2;p++)
              Cred[(rr+q*8)*40+nt*8+cc+p]=acc[nt][q*2+p];
      }
      __syncthreads();
      if(w<4){
        const float* bi=L?bih1:bih0; const float* bh=L?bhh1:bhh0; const float* b2=L?bh21:bh20;
#pragma unroll
        for(int q=0;q<2;q++)
#pragma unroll
          for(int p=0;p<2;p++){
            int r=rr+q*8, jl=cc+p, j=blk*8+jl, idx=q*2+p;
            float ig=acc[0][idx]+Cred[r*40+jl]      +bi[j]     +bh[j];
            float fg=acc[1][idx]+Cred[r*40+8+jl]    +bi[H_+j]  +bh[H_+j];
            float gg=acc[2][idx]+Cred[r*40+16+jl]   +bi[2*H_+j]+bh[2*H_+j];
            float og=acc[3][idx]+Cred[r*40+24+jl]   +bi[3*H_+j]+bh[3*H_+j];
            float sk=acc[4][idx]+Cred[r*40+32+jl]   +b2[j];
            float cv=creg[L][idx];
            float cn=sigf(fg)*cv+sigf(ig)*tanhf(gg);
            float h1=sigf(og)*tanhf(cn);
            float h2=sigf(sk);
            int code=mask[(size_t)t*2*H_+(size_t)L*H_+j];
            float hn=(code!=1?h1:0.f)+(code!=0?h2:0.f);
            creg[L][idx]=cn;
            size_t hi=(size_t)L*SLAB+(size_t)(t+2)*SLOT+(size_t)r*H_+j;
            splitf(hn,&gHh[hi],&gHl[hi]);
          }
      }
      if(L==0) gridbar();   // single grid barrier per step
    }
  }
}

// ---------------- output GEMM ----------------
__global__ void __launch_bounds__(256,1) k_out(const float* __restrict__ bo, float* __restrict__ out){
  extern __shared__ char smx[];
  BF* sA=(BF*)smx;
  BF* sW=(BF*)(smx+65536);
  float* Cred=(float*)(smx+131072);
  const int tid=threadIdx.x, lane=tid&31, w=tid>>5;
  const int kg=w>>2, r0=(w&3)*16;
  const int rA=r0+(lane&7)+((lane>>3)&1)*8, cA=(lane>>4)&1;
  const int rr=r0+(lane>>2), cc=(lane&3)*2;
  const int kbase=kg*32;
  const int t=blockIdx.x, n0=blockIdx.y*64;
  const BF* Ah=gHh+SLAB+(size_t)(t+2)*SLOT;
  const BF* Al=gHl+SLAB+(size_t)(t+2)*SLOT;
  const BF* Wh=gWoh+(size_t)n0*H_;
  const BF* Wl=gWol+(size_t)n0*H_;
  float acc[8][4];
#pragma unroll
  for(int i=0;i<8;i++){acc[i][0]=0;acc[i][1]=0;acc[i][2]=0;acc[i][3]=0;}
  auto do_stage=[&](int it){
    int st=it&3, k0=it*64;
    BF* dA=sA+st*8192; BF* dW=sW+st*8192;
    stT(dA,dA+4096,Ah+k0,Al+k0,H_,64,tid,256);
    stT(dW,dW+4096,Wh+k0,Wl+k0,H_,64,tid,256);
    cpc();
  };
  do_stage(0); do_stage(1); do_stage(2);
#pragma unroll 1
  for(int it=0;it<16;it++){
    int rem=15-it;
    if(rem>1) cpw<2>(); else if(rem==1) cpw<1>(); else cpw<0>();
    __syncthreads();
    int st=it&3;
    BF* bA=sA+st*8192; BF* bW=sW+st*8192;
    mm32p<4>(acc,bA,bA+4096,bW,bW+4096,kbase,rA,cA,lane);
    if(it+3<16) do_stage(it+3);
  }
  if(w>=4){
#pragma unroll
    for(int nt=0;nt<8;nt++)
#pragma unroll
      for(int q=0;q<2;q++)
#pragma unroll
        for(int p=0;p<2;p++)
          Cred[(rr+q*8)*64+nt*8+cc+p]=acc[nt][q*2+p];
  }
  __syncthreads();
  if(w<4){
#pragma unroll
    for(int nt=0;nt<8;nt++)
#pragma unroll
      for(int q=0;q<2;q++)
#pragma unroll
        for(int p=0;p<2;p++){
          int r=rr+q*8, col=n0+nt*8+cc+p;
          float v=acc[nt][q*2+p]+Cred[r*64+nt*8+cc+p]+bo[col];
          out[(size_t)t*B_*OUTD+(size_t)r*OUTD+col]=v;
        }
  }
}

extern "C" void kernel_launch(void* const* d_in, const int* in_sizes, int n_in,
                              void* d_out, int out_size) {
  const float* targets=(const float*)d_in[0];
  const float* h0  =(const float*)d_in[1];
  const float* c0  =(const float*)d_in[2];
  const int*   mask=(const int*)  d_in[3];
  const float* Wih0=(const float*)d_in[4];
  const float* Whh0=(const float*)d_in[5];
  const float* bih0=(const float*)d_in[6];
  const float* bhh0=(const float*)d_in[7];
  const float* Wih1=(const float*)d_in[8];
  const float* Whh1=(const float*)d_in[9];
  const float* bih1=(const float*)d_in[10];
  const float* bhh1=(const float*)d_in[11];
  const float* Wh20=(const float*)d_in[12];
  const float* bh20=(const float*)d_in[13];
  const float* Wh21=(const float*)d_in[14];
  const float* bh21=(const float*)d_in[15];
  const float* Wout=(const float*)d_in[16];
  const float* bout=(const float*)d_in[17];

  static int inited=0;
  if(!inited){
    cudaFuncSetAttribute(k_persist, cudaFuncAttributeMaxDynamicSharedMemorySize, 206848);
    cudaFuncSetAttribute(k_out,     cudaFuncAttributeMaxDynamicSharedMemorySize, 147456);
    inited=1;
  }
  // exactly 3 launches before k_persist -> k_persist occupies the ncu capture slot
  k_prepX<<<4096,256>>>(targets);
  k_prepG<<<4096,256>>>(Wih0,Whh0,Wih1,Whh1);
  k_prepS2<<<1024,256>>>(Wh20,Wh21);
  k_persist<<<NBLK,256,206848>>>(mask,h0,c0,bih0,bhh0,bh20,bih1,bhh1,bh21);
  k_prepWo<<<512,256>>>(Wout);
  k_out<<<dim3(T_,8),256,147456>>>(bout,(float*)d_out);
}

// round 11
// speedup vs baseline: 1.7506x; 1.0072x over previous
#include <cuda_runtime.h>
#include <cuda_bf16.h>
#include <math.h>
#include <stdint.h>

typedef __nv_bfloat16 BF;
#define T_ 512
#define B_ 64
#define H_ 1024
#define IN0 1536
#define OUTD 512
#define SLOT (B_*H_)
#define SLAB ((size_t)514*SLOT)
#define NBLK 128

__device__ __align__(16) BF gG0h[(size_t)NBLK*32*2560];
__device__ __align__(16) BF gG0l[(size_t)NBLK*32*2560];
__device__ __align__(16) BF gG1h[(size_t)NBLK*32*2048];
__device__ __align__(16) BF gG1l[(size_t)NBLK*32*2048];
__device__ __align__(16) BF gSkh[(size_t)2*NBLK*8*1024];
__device__ __align__(16) BF gSkl[(size_t)2*NBLK*8*1024];
__device__ __align__(16) BF gWoh[OUTD*H_];
__device__ __align__(16) BF gWol[OUTD*H_];
__device__ __align__(16) BF gXh[(size_t)T_*B_*IN0];
__device__ __align__(16) BF gXl[(size_t)T_*B_*IN0];
__device__ __align__(16) BF gHh[2*SLAB];
__device__ __align__(16) BF gHl[2*SLAB];

__device__ volatile unsigned gBarGen;
__device__ unsigned gBarCnt;

__device__ __forceinline__ float sigf(float x){ return 1.f/(1.f+expf(-x)); }
__device__ __forceinline__ void splitf(float v, BF* h, BF* l){
  BF a=__float2bfloat16(v); *h=a; *l=__float2bfloat16(v-__bfloat162float(a));
}
__device__ __forceinline__ void cp16(BF* d, const BF* s){
  unsigned u=(unsigned)__cvta_generic_to_shared(d);
  asm volatile("cp.async.cg.shared.global [%0],[%1],16;"::"r"(u),"l"(s));
}
__device__ __forceinline__ void cpc(){ asm volatile("cp.async.commit_group;"); }
template<int N> __device__ __forceinline__ void cpw(){ asm volatile("cp.async.wait_group %0;"::"n"(N)); }

__device__ __forceinline__ void gridbar(){
  __syncthreads();
  if(threadIdx.x==0){
    unsigned old = gBarGen;
    __threadfence();
    unsigned prev = atomicAdd(&gBarCnt,1u);
    if(prev==NBLK-1u){ gBarCnt=0u; __threadfence(); gBarGen=old+1u; }
    else { while(gBarGen==old){} }
    __threadfence();
  }
  __syncthreads();
}

// tiles: rows x 64 bf16, 128B rows, 8-way 16B XOR swizzle
__device__ __forceinline__ const BF* swp(const BF* t_, int r, int cseg){
  return t_ + r*64 + ((cseg ^ (r&7))<<3);
}
__device__ __forceinline__ void stT(BF* dh, BF* dl, const BF* ph, const BF* pl,
                                    int ld, int rows, int tid, int nthr){
  for(int u=tid; u<rows*8; u+=nthr){
    int r=u>>3, cs=u&7;
    int off = r*64 + ((cs ^ (r&7))<<3);
    size_t g=(size_t)r*ld + cs*8;
    cp16(dh+off, ph+g); cp16(dl+off, pl+g);
  }
}
__device__ __forceinline__ void ldsm4(unsigned a[4], const BF* p){
  unsigned u=(unsigned)__cvta_generic_to_shared(p);
  asm volatile("ldmatrix.sync.aligned.m8n8.x4.shared.b16 {%0,%1,%2,%3},[%4];"
    :"=r"(a[0]),"=r"(a[1]),"=r"(a[2]),"=r"(a[3]):"r"(u));
}
__device__ __forceinline__ void ldsm2(unsigned b[2], const BF* p){
  unsigned u=(unsigned)__cvta_generic_to_shared(p);
  asm volatile("ldmatrix.sync.aligned.m8n8.x2.shared.b16 {%0,%1},[%2];"
    :"=r"(b[0]),"=r"(b[1]):"r"(u));
}
__device__ __forceinline__ void mma(float c[4], const unsigned a[4], const unsigned b[2]){
  asm volatile("mma.sync.aligned.m16n8k16.row.col.f32.bf16.bf16.f32 "
    "{%0,%1,%2,%3},{%4,%5,%6,%7},{%8,%9},{%0,%1,%2,%3};"
    :"+f"(c[0]),"+f"(c[1]),"+f"(c[2]),"+f"(c[3])
    :"r"(a[0]),"r"(a[1]),"r"(a[2]),"r"(a[3]),"r"(b[0]),"r"(b[1]));
}
// x4 B load covering an nt-pair (two 8-row tiles) x 16 k
__device__ __forceinline__ void ldsm4b(unsigned b[4], const BF* t_, int np, int cs, int lane){
  int row  = np*16 + ((lane>>4)<<3) + (lane&7);
  int cseg = cs + ((lane>>3)&1);
  ldsm4(b, t_ + row*64 + ((cseg ^ (row&7))<<3));
}
// one 32-wide K slice of C(16 x NP*16); term-major interleaved issue:
// same-accumulator reuse distance = 2*NP mma slots (breaks in-order stalls)
template<int NP>
__device__ __forceinline__ void mm32i(float (*acc)[4], const BF* Ah,const BF* Al,
     const BF* Wh,const BF* Wl, int kbase, int rA,int cA,int lane){
#pragma unroll
  for(int kk=0;kk<2;kk++){
    int cs=(kbase>>3)+kk*2;
    unsigned ah[4],al[4];
    ldsm4(ah,swp(Ah,rA,cs+cA)); ldsm4(al,swp(Al,rA,cs+cA));
    unsigned bh[NP][4], bl[NP][4];
#pragma unroll
    for(int np=0;np<NP;np++){ ldsm4b(bh[np],Wh,np,cs,lane); ldsm4b(bl[np],Wl,np,cs,lane); }
    // term 1: Ah*Bh across all accumulators
#pragma unroll
    for(int np=0;np<NP;np++){ mma(acc[2*np],ah,bh[np]); mma(acc[2*np+1],ah,bh[np]+2); }
    // term 2: Ah*Bl
#pragma unroll
    for(int np=0;np<NP;np++){ mma(acc[2*np],ah,bl[np]); mma(acc[2*np+1],ah,bl[np]+2); }
    // term 3: Al*Bh
#pragma unroll
    for(int np=0;np<NP;np++){ mma(acc[2*np],al,bh[np]); mma(acc[2*np+1],al,bh[np]+2); }
  }
}
// skip-phase 32-wide K slice, single 8-col tile: dual accumulator chains (per kk)
__device__ __forceinline__ void mm32s(float accA[4], float accB[4],
     const BF* Ah,const BF* Al,const BF* Wh,const BF* Wl,
     int kbase, int rA,int cA,int nB,int cB){
  int cs0=(kbase>>3), cs1=cs0+2;
  unsigned ah0[4],al0[4],ah1[4],al1[4];
  ldsm4(ah0,swp(Ah,rA,cs0+cA)); ldsm4(al0,swp(Al,rA,cs0+cA));
  ldsm4(ah1,swp(Ah,rA,cs1+cA)); ldsm4(al1,swp(Al,rA,cs1+cA));
  unsigned bh0[2],bl0[2],bh1[2],bl1[2];
  ldsm2(bh0,swp(Wh,nB,cs0+cB)); ldsm2(bl0,swp(Wl,nB,cs0+cB));
  ldsm2(bh1,swp(Wh,nB,cs1+cB)); ldsm2(bl1,swp(Wl,nB,cs1+cB));
  mma(accA,ah0,bh0); mma(accB,ah1,bh1);
  mma(accA,ah0,bl0); mma(accB,ah1,bl1);
  mma(accA,al0,bh0); mma(accB,al1,bh1);
}

// ---------------- prep (3 launches so k_persist is launch #4 = ncu slot) ----------------
__global__ void k_prepX(const float* __restrict__ x){
  size_t n=(size_t)T_*B_*IN0;
  for(size_t i=(size_t)blockIdx.x*blockDim.x+threadIdx.x;i<n;i+=(size_t)gridDim.x*blockDim.x)
    splitf(x[i],&gXh[i],&gXl[i]);
}
__global__ void k_prepG(const float* __restrict__ Wih0,const float* __restrict__ Whh0,
                        const float* __restrict__ Wih1,const float* __restrict__ Whh1){
  const size_t n0=(size_t)NBLK*32*2560, n1=(size_t)NBLK*32*2048;
  for(size_t i=(size_t)blockIdx.x*blockDim.x+threadIdx.x;i<n0+n1;i+=(size_t)gridDim.x*blockDim.x){
    int layer = i>=n0;
    size_t ii = layer? i-n0 : i;
    const int KA1=layer?H_:IN0, KG=KA1+H_;
    const float* Wih=layer?Wih1:Wih0; const float* Whh=layer?Whh1:Whh0;
    BF* dh=layer?gG1h:gG0h; BF* dl=layer?gG1l:gG0l;
    int k=(int)(ii%KG); int q=(int)(ii/KG); int nr=q&31, blk=q>>5;
    int row=(nr>>3)*H_+blk*8+(nr&7);
    float v = (k<KA1)? Wih[(size_t)row*KA1+k] : Whh[(size_t)row*H_+(k-KA1)];
    splitf(v,&dh[ii],&dl[ii]);
  }
}
__global__ void k_prepS2(const float* __restrict__ W0,const float* __restrict__ W1){
  const int n=NBLK*8*1024;
  for(int i=blockIdx.x*blockDim.x+threadIdx.x;i<2*n;i+=gridDim.x*blockDim.x){
    int layer=i>=n, ii=layer?i-n:i;
    const float* W=layer?W1:W0;
    BF* dh=gSkh+(size_t)layer*n; BF* dl=gSkl+(size_t)layer*n;
    int k=ii&1023; int q=ii>>10; int nr=q&7, blk=q>>3;
    splitf(W[(size_t)k*H_+blk*8+nr],&dh[ii],&dl[ii]);
  }
}
__global__ void k_prepWo(const float* __restrict__ W){
  for(int i=blockIdx.x*blockDim.x+threadIdx.x;i<OUTD*H_;i+=gridDim.x*blockDim.x)
    splitf(W[i],&gWoh[i],&gWol[i]);
}

// ---------------- persistent recurrence ----------------
// smem: sA 4 stages x 16384 elems (two 64-col halves, hi|lo) = 128KB @0
//       sW 4 stages x 8192 elems = 64KB @131072 ; Cred 64x40 f32 @196608 -> 206848
__global__ void __launch_bounds__(256,1) k_persist(const int* __restrict__ mask,
    const float* __restrict__ h0, const float* __restrict__ c0,
    const float* __restrict__ bih0,const float* __restrict__ bhh0,const float* __restrict__ bh20,
    const float* __restrict__ bih1,const float* __restrict__ bhh1,const float* __restrict__ bh21)
{
  extern __shared__ char smx[];
  BF* sA=(BF*)smx;
  BF* sW=(BF*)(smx+131072);
  float* Cred=(float*)(smx+196608);
  const int tid=threadIdx.x, lane=tid&31, w=tid>>5, blk=blockIdx.x;
  const int kg=w>>2, r0=(w&3)*16;
  const int rA=r0+(lane&7)+((lane>>3)&1)*8, cA=(lane>>4)&1;
  const int nB=lane&7, cB=(lane>>3)&1;
  const int rr=r0+(lane>>2), cc=(lane&3)*2;
  const int kbase=kg*32;

  float creg[2][4];
  if(w<4){
#pragma unroll
    for(int q=0;q<2;q++)
#pragma unroll
      for(int p=0;p<2;p++){
        int r=rr+q*8, j=blk*8+cc+p, idx=q*2+p;
        creg[0][idx]=c0[(size_t)r*H_+j];
        creg[1][idx]=c0[(size_t)(B_+r)*H_+j];
#pragma unroll
        for(int L=0;L<2;L++){
          size_t b0=(size_t)L*SLAB+(size_t)r*H_+j;
          gHh[b0]=__float2bfloat16(0.f); gHl[b0]=__float2bfloat16(0.f);
          splitf(h0[(size_t)(L*B_+r)*H_+j],&gHh[b0+SLOT],&gHl[b0+SLOT]);
        }
      }
  }
  gridbar();

  for(int t=0;t<T_;t++){
#pragma unroll 1
    for(int L=0;L<2;L++){
      const int KA1=L?H_:IN0, KG=KA1+H_;
      const int NG2=KG>>7, NIT=NG2+8;         // 128-wide chunks: gates + skip(1024)
      const BF* Gh=(L?gG1h:gG0h)+(size_t)blk*32*KG;
      const BF* Gl=(L?gG1l:gG0l)+(size_t)blk*32*KG;
      const BF* Sh=gSkh+(size_t)L*NBLK*8*1024+(size_t)blk*8*1024;
      const BF* Sl=gSkl+(size_t)L*NBLK*8*1024+(size_t)blk*8*1024;
      const BF* skAh=gHh+(size_t)L*SLAB+(size_t)t*SLOT;
      const BF* skAl=gHl+(size_t)L*SLAB+(size_t)t*SLOT;

      float acc[5][4];
      float accX[4]={0,0,0,0};
#pragma unroll
      for(int i=0;i<5;i++){acc[i][0]=0;acc[i][1]=0;acc[i][2]=0;acc[i][3]=0;}

      auto do_stage=[&](int it){
        int st=it&3;
        BF* dA=sA+st*16384; BF* dW=sW+st*8192;
#pragma unroll
        for(int half=0;half<2;half++){
          BF* dAh=dA+half*8192; BF* dWh=dW+half*4096;
          if(it<NG2){
            int k0=it*128+half*64;
            const BF *ph,*pl; int ld;
            if(L==0){
              if(k0<IN0){ph=gXh+(size_t)t*B_*IN0+k0; pl=gXl+(size_t)t*B_*IN0+k0; ld=IN0;}
              else {ph=gHh+(size_t)(t+1)*SLOT+(k0-IN0); pl=gHl+(size_t)(t+1)*SLOT+(k0-IN0); ld=H_;}
            }else{
              if(k0<H_){ph=gHh+(size_t)(t+2)*SLOT+k0; pl=gHl+(size_t)(t+2)*SLOT+k0; ld=H_;}
              else {ph=gHh+SLAB+(size_t)(t+1)*SLOT+(k0-H_); pl=gHl+SLAB+(size_t)(t+1)*SLOT+(k0-H_); ld=H_;}
            }
            stT(dAh,dAh+4096,ph,pl,ld,64,tid,256);
            stT(dWh,dWh+2048,Gh+k0,Gl+k0,KG,32,tid,256);
          }else{
            int k0=(it-NG2)*128+half*64;
            stT(dAh,dAh+4096,skAh+k0,skAl+k0,H_,64,tid,256);
            stT(dWh,dWh+2048,Sh+k0,Sl+k0,1024,8,tid,256);
          }
        }
        cpc();
      };

      do_stage(0); do_stage(1); do_stage(2);
#pragma unroll 1
      for(int it=0;it<NIT;it++){
        if(it+2<NIT) cpw<2>(); else if(it+1<NIT) cpw<1>(); else cpw<0>();
        __syncthreads();
        if(it+3<NIT) do_stage(it+3);
        int st=it&3;
        BF* bA=sA+st*16384; BF* bW=sW+st*8192;
        if(it<NG2){
          mm32i<2>(acc,bA,bA+4096,bW,bW+2048,kbase,rA,cA,lane);
          mm32i<2>(acc,bA+8192,bA+12288,bW+4096,bW+6144,kbase,rA,cA,lane);
        }else{
          mm32s(acc[4],accX,bA,bA+4096,bW,bW+2048,kbase,rA,cA,nB,cB);
          mm32s(acc[4],accX,bA+8192,bA+12288,bW+4096,bW+6144,kbase,rA,cA,nB,cB);
        }
      }
      __syncthreads();
#pragma unroll
      for(int i=0;i<4;i++) acc[4][i]+=accX[i];

      // k-split reduction: kg=1 warps dump partials
      if(w>=4){
#pragma unroll
        for(int nt=0;nt<5;nt++)
#pragma unroll
          for(int q=0;q<2;q++)
#pragma unroll
            for(int p=0;p<2;p++)
              Cred[(rr+q*8)*40+nt*8+cc+p]=acc[nt][q*2+p];
      }
      __syncthreads();
      if(w<4){
        const float* bi=L?bih1:bih0; const float* bh=L?bhh1:bhh0; const float* b2=L?bh21:bh20;
#pragma unroll
        for(int q=0;q<2;q++)
#pragma unroll
          for(int p=0;p<2;p++){
            int r=rr+q*8, jl=cc+p, j=blk*8+jl, idx=q*2+p;
            float ig=acc[0][idx]+Cred[r*40+jl]      +bi[j]     +bh[j];
            float fg=acc[1][idx]+Cred[r*40+8+jl]    +bi[H_+j]  +bh[H_+j];
            float gg=acc[2][idx]+Cred[r*40+16+jl]   +bi[2*H_+j]+bh[2*H_+j];
            float og=acc[3][idx]+Cred[r*40+24+jl]   +bi[3*H_+j]+bh[3*H_+j];
            float sk=acc[4][idx]+Cred[r*40+32+jl]   +b2[j];
            float cv=creg[L][idx];
            float cn=sigf(fg)*cv+sigf(ig)*tanhf(gg);
            float h1=sigf(og)*tanhf(cn);
            float h2=sigf(sk);
            int code=mask[(size_t)t*2*H_+(size_t)L*H_+j];
            float hn=(code!=1?h1:0.f)+(code!=0?h2:0.f);
            creg[L][idx]=cn;
            size_t hi=(size_t)L*SLAB+(size_t)(t+2)*SLOT+(size_t)r*H_+j;
            splitf(hn,&gHh[hi],&gHl[hi]);
          }
      }
      if(L==0) gridbar();   // single grid barrier per step
    }
  }
}

// ---------------- output GEMM ----------------
__global__ void __launch_bounds__(256,1) k_out(const float* __restrict__ bo, float* __restrict__ out){
  extern __shared__ char smx[];
  BF* sA=(BF*)smx;
  BF* sW=(BF*)(smx+65536);
  float* Cred=(float*)(smx+131072);
  const int tid=threadIdx.x, lane=tid&31, w=tid>>5;
  const int kg=w>>2, r0=(w&3)*16;
  const int rA=r0+(lane&7)+((lane>>3)&1)*8, cA=(lane>>4)&1;
  const int rr=r0+(lane>>2), cc=(lane&3)*2;
  const int kbase=kg*32;
  const int t=blockIdx.x, n0=blockIdx.y*64;
  const BF* Ah=gHh+SLAB+(size_t)(t+2)*SLOT;
  const BF* Al=gHl+SLAB+(size_t)(t+2)*SLOT;
  const BF* Wh=gWoh+(size_t)n0*H_;
  const BF* Wl=gWol+(size_t)n0*H_;
  float acc[8][4];
#pragma unroll
  for(int i=0;i<8;i++){acc[i][0]=0;acc[i][1]=0;acc[i][2]=0;acc[i][3]=0;}
  auto do_stage=[&](int it){
    int st=it&3, k0=it*64;
    BF* dA=sA+st*8192; BF* dW=sW+st*8192;
    stT(dA,dA+4096,Ah+k0,Al+k0,H_,64,tid,256);
    stT(dW,dW+4096,Wh+k0,Wl+k0,H_,64,tid,256);
    cpc();
  };
  do_stage(0); do_stage(1); do_stage(2);
#pragma unroll 1
  for(int it=0;it<16;it++){
    int rem=15-it;
    if(rem>1) cpw<2>(); else if(rem==1) cpw<1>(); else cpw<0>();
    __syncthreads();
    int st=it&3;
    BF* bA=sA+st*8192; BF* bW=sW+st*8192;
    mm32i<4>(acc,bA,bA+4096,bW,bW+4096,kbase,rA,cA,lane);
    if(it+3<16) do_stage(it+3);
  }
  if(w>=4){
#pragma unroll
    for(int nt=0;nt<8;nt++)
#pragma unroll
      for(int q=0;q<2;q++)
#pragma unroll
        for(int p=0;p<2;p++)
          Cred[(rr+q*8)*64+nt*8+cc+p]=acc[nt][q*2+p];
  }
  __syncthreads();
  if(w<4){
#pragma unroll
    for(int nt=0;nt<8;nt++)
#pragma unroll
      for(int q=0;q<2;q++)
#pragma unroll
        for(int p=0;p<2;p++){
          int r=rr+q*8, col=n0+nt*8+cc+p;
          float v=acc[nt][q*2+p]+Cred[r*64+nt*8+cc+p]+bo[col];
          out[(size_t)t*B_*OUTD+(size_t)r*OUTD+col]=v;
        }
  }
}

extern "C" void kernel_launch(void* const* d_in, const int* in_sizes, int n_in,
                              void* d_out, int out_size) {
  const float* targets=(const float*)d_in[0];
  const float* h0  =(const float*)d_in[1];
  const float* c0  =(const float*)d_in[2];
  const int*   mask=(const int*)  d_in[3];
  const float* Wih0=(const float*)d_in[4];
  const float* Whh0=(const float*)d_in[5];
  const float* bih0=(const float*)d_in[6];
  const float* bhh0=(const float*)d_in[7];
  const float* Wih1=(const float*)d_in[8];
  const float* Whh1=(const float*)d_in[9];
  const float* bih1=(const float*)d_in[10];
  const float* bhh1=(const float*)d_in[11];
  const float* Wh20=(const float*)d_in[12];
  const float* bh20=(const float*)d_in[13];
  const float* Wh21=(const float*)d_in[14];
  const float* bh21=(const float*)d_in[15];
  const float* Wout=(const float*)d_in[16];
  const float* bout=(const float*)d_in[17];

  static int inited=0;
  if(!inited){
    cudaFuncSetAttribute(k_persist, cudaFuncAttributeMaxDynamicSharedMemorySize, 206848);
    cudaFuncSetAttribute(k_out,     cudaFuncAttributeMaxDynamicSharedMemorySize, 147456);
    inited=1;
  }
  // exactly 3 launches before k_persist -> k_persist occupies the ncu capture slot
  k_prepX<<<4096,256>>>(targets);
  k_prepG<<<4096,256>>>(Wih0,Whh0,Wih1,Whh1);
  k_prepS2<<<1024,256>>>(Wh20,Wh21);
  k_persist<<<NBLK,256,206848>>>(mask,h0,c0,bih0,bhh0,bh20,bih1,bhh1,bh21);
  k_prepWo<<<512,256>>>(Wout);
  k_out<<<dim3(T_,8),256,147456>>>(bout,(float*)d_out);
}

// round 12
// speedup vs baseline: 1.8120x; 1.0351x over previous
#include <cuda_runtime.h>
#include <cuda_bf16.h>
#include <math.h>
#include <stdint.h>

typedef __nv_bfloat16 BF;
#define T_ 512
#define B_ 64
#define H_ 1024
#define IN0 1536
#define OUTD 512
#define SLOT (B_*H_)
#define SLAB ((size_t)514*SLOT)
#define NBLK 128
#define NTHR 512

__device__ __align__(16) BF gG0h[(size_t)NBLK*32*2560];
__device__ __align__(16) BF gG0l[(size_t)NBLK*32*2560];
__device__ __align__(16) BF gG1h[(size_t)NBLK*32*2048];
__device__ __align__(16) BF gG1l[(size_t)NBLK*32*2048];
__device__ __align__(16) BF gSkh[(size_t)2*NBLK*8*1024];
__device__ __align__(16) BF gSkl[(size_t)2*NBLK*8*1024];
__device__ __align__(16) BF gWoh[OUTD*H_];
__device__ __align__(16) BF gWol[OUTD*H_];
__device__ __align__(16) BF gXh[(size_t)T_*B_*IN0];
__device__ __align__(16) BF gXl[(size_t)T_*B_*IN0];
__device__ __align__(16) BF gHh[2*SLAB];
__device__ __align__(16) BF gHl[2*SLAB];

__device__ volatile unsigned gBarGen;
__device__ unsigned gBarCnt;

__device__ __forceinline__ float sigf(float x){ return 1.f/(1.f+expf(-x)); }
__device__ __forceinline__ void splitf(float v, BF* h, BF* l){
  BF a=__float2bfloat16(v); *h=a; *l=__float2bfloat16(v-__bfloat162float(a));
}
__device__ __forceinline__ void cp16(BF* d, const BF* s){
  unsigned u=(unsigned)__cvta_generic_to_shared(d);
  asm volatile("cp.async.cg.shared.global [%0],[%1],16;"::"r"(u),"l"(s));
}
__device__ __forceinline__ void cpc(){ asm volatile("cp.async.commit_group;"); }
template<int N> __device__ __forceinline__ void cpw(){ asm volatile("cp.async.wait_group %0;"::"n"(N)); }

__device__ __forceinline__ void gridbar(){
  __syncthreads();
  if(threadIdx.x==0){
    unsigned old = gBarGen;
    __threadfence();
    unsigned prev = atomicAdd(&gBarCnt,1u);
    if(prev==NBLK-1u){ gBarCnt=0u; __threadfence(); gBarGen=old+1u; }
    else { while(gBarGen==old){} }
    __threadfence();
  }
  __syncthreads();
}

// tiles: rows x 64 bf16, 128B rows, 8-way 16B XOR swizzle
__device__ __forceinline__ const BF* swp(const BF* t_, int r, int cseg){
  return t_ + r*64 + ((cseg ^ (r&7))<<3);
}
__device__ __forceinline__ void stT(BF* dh, BF* dl, const BF* ph, const BF* pl,
                                    int ld, int rows, int tid, int nthr){
  for(int u=tid; u<rows*8; u+=nthr){
    int r=u>>3, cs=u&7;
    int off = r*64 + ((cs ^ (r&7))<<3);
    size_t g=(size_t)r*ld + cs*8;
    cp16(dh+off, ph+g); cp16(dl+off, pl+g);
  }
}
__device__ __forceinline__ void ldsm4(unsigned a[4], const BF* p){
  unsigned u=(unsigned)__cvta_generic_to_shared(p);
  asm volatile("ldmatrix.sync.aligned.m8n8.x4.shared.b16 {%0,%1,%2,%3},[%4];"
    :"=r"(a[0]),"=r"(a[1]),"=r"(a[2]),"=r"(a[3]):"r"(u));
}
__device__ __forceinline__ void ldsm2(unsigned b[2], const BF* p){
  unsigned u=(unsigned)__cvta_generic_to_shared(p);
  asm volatile("ldmatrix.sync.aligned.m8n8.x2.shared.b16 {%0,%1},[%2];"
    :"=r"(b[0]),"=r"(b[1]):"r"(u));
}
__device__ __forceinline__ void mma(float c[4], const unsigned a[4], const unsigned b[2]){
  asm volatile("mma.sync.aligned.m16n8k16.row.col.f32.bf16.bf16.f32 "
    "{%0,%1,%2,%3},{%4,%5,%6,%7},{%8,%9},{%0,%1,%2,%3};"
    :"+f"(c[0]),"+f"(c[1]),"+f"(c[2]),"+f"(c[3])
    :"r"(a[0]),"r"(a[1]),"r"(a[2]),"r"(a[3]),"r"(b[0]),"r"(b[1]));
}
// x4 B load covering an nt-pair (two 8-row tiles) x 16 k
__device__ __forceinline__ void ldsm4b(unsigned b[4], const BF* t_, int np, int cs, int lane){
  int row  = np*16 + ((lane>>4)<<3) + (lane&7);
  int cseg = cs + ((lane>>3)&1);
  ldsm4(b, t_ + row*64 + ((cseg ^ (row&7))<<3));
}
// one 32-wide K slice of C(16 x NP*16); term-major interleaved issue
template<int NP>
__device__ __forceinline__ void mm32i(float (*acc)[4], const BF* Ah,const BF* Al,
     const BF* Wh,const BF* Wl, int kbase, int rA,int cA,int lane){
#pragma unroll
  for(int kk=0;kk<2;kk++){
    int cs=(kbase>>3)+kk*2;
    unsigned ah[4],al[4];
    ldsm4(ah,swp(Ah,rA,cs+cA)); ldsm4(al,swp(Al,rA,cs+cA));
    unsigned bh[NP][4], bl[NP][4];
#pragma unroll
    for(int np=0;np<NP;np++){ ldsm4b(bh[np],Wh,np,cs,lane); ldsm4b(bl[np],Wl,np,cs,lane); }
#pragma unroll
    for(int np=0;np<NP;np++){ mma(acc[2*np],ah,bh[np]); mma(acc[2*np+1],ah,bh[np]+2); }
#pragma unroll
    for(int np=0;np<NP;np++){ mma(acc[2*np],ah,bl[np]); mma(acc[2*np+1],ah,bl[np]+2); }
#pragma unroll
    for(int np=0;np<NP;np++){ mma(acc[2*np],al,bh[np]); mma(acc[2*np+1],al,bh[np]+2); }
  }
}
// skip-phase 32-wide K slice, single 8-col tile: dual accumulator chains
__device__ __forceinline__ void mm32s(float accA[4], float accB[4],
     const BF* Ah,const BF* Al,const BF* Wh,const BF* Wl,
     int kbase, int rA,int cA,int nB,int cB){
  int cs0=(kbase>>3), cs1=cs0+2;
  unsigned ah0[4],al0[4],ah1[4],al1[4];
  ldsm4(ah0,swp(Ah,rA,cs0+cA)); ldsm4(al0,swp(Al,rA,cs0+cA));
  ldsm4(ah1,swp(Ah,rA,cs1+cA)); ldsm4(al1,swp(Al,rA,cs1+cA));
  unsigned bh0[2],bl0[2],bh1[2],bl1[2];
  ldsm2(bh0,swp(Wh,nB,cs0+cB)); ldsm2(bl0,swp(Wl,nB,cs0+cB));
  ldsm2(bh1,swp(Wh,nB,cs1+cB)); ldsm2(bl1,swp(Wl,nB,cs1+cB));
  mma(accA,ah0,bh0); mma(accB,ah1,bh1);
  mma(accA,ah0,bl0); mma(accB,ah1,bl1);
  mma(accA,al0,bh0); mma(accB,al1,bh1);
}

// ---------------- prep (3 launches so k_persist is launch #4 = ncu slot) ----------------
__global__ void k_prepX(const float* __restrict__ x){
  size_t n=(size_t)T_*B_*IN0;
  for(size_t i=(size_t)blockIdx.x*blockDim.x+threadIdx.x;i<n;i+=(size_t)gridDim.x*blockDim.x)
    splitf(x[i],&gXh[i],&gXl[i]);
}
__global__ void k_prepG(const float* __restrict__ Wih0,const float* __restrict__ Whh0,
                        const float* __restrict__ Wih1,const float* __restrict__ Whh1){
  const size_t n0=(size_t)NBLK*32*2560, n1=(size_t)NBLK*32*2048;
  for(size_t i=(size_t)blockIdx.x*blockDim.x+threadIdx.x;i<n0+n1;i+=(size_t)gridDim.x*blockDim.x){
    int layer = i>=n0;
    size_t ii = layer? i-n0 : i;
    const int KA1=layer?H_:IN0, KG=KA1+H_;
    const float* Wih=layer?Wih1:Wih0; const float* Whh=layer?Whh1:Whh0;
    BF* dh=layer?gG1h:gG0h; BF* dl=layer?gG1l:gG0l;
    int k=(int)(ii%KG); int q=(int)(ii/KG); int nr=q&31, blk=q>>5;
    int row=(nr>>3)*H_+blk*8+(nr&7);
    float v = (k<KA1)? Wih[(size_t)row*KA1+k] : Whh[(size_t)row*H_+(k-KA1)];
    splitf(v,&dh[ii],&dl[ii]);
  }
}
__global__ void k_prepS2(const float* __restrict__ W0,const float* __restrict__ W1){
  const int n=NBLK*8*1024;
  for(int i=blockIdx.x*blockDim.x+threadIdx.x;i<2*n;i+=gridDim.x*blockDim.x){
    int layer=i>=n, ii=layer?i-n:i;
    const float* W=layer?W1:W0;
    BF* dh=gSkh+(size_t)layer*n; BF* dl=gSkl+(size_t)layer*n;
    int k=ii&1023; int q=ii>>10; int nr=q&7, blk=q>>3;
    splitf(W[(size_t)k*H_+blk*8+nr],&dh[ii],&dl[ii]);
  }
}
__global__ void k_prepWo(const float* __restrict__ W){
  for(int i=blockIdx.x*blockDim.x+threadIdx.x;i<OUTD*H_;i+=gridDim.x*blockDim.x)
    splitf(W[i],&gWoh[i],&gWol[i]);
}

// ---------------- persistent recurrence (512 threads, k-split x4) ----------------
// smem: sA 4 stages x 16384 elems = 128KB @0 ; sW 4 stages x 8192 = 64KB @131072
//       Cred 3 slabs x 64x40 f32 @196608 -> total 227328
__global__ void __launch_bounds__(NTHR,1) k_persist(const int* __restrict__ mask,
    const float* __restrict__ h0, const float* __restrict__ c0,
    const float* __restrict__ bih0,const float* __restrict__ bhh0,const float* __restrict__ bh20,
    const float* __restrict__ bih1,const float* __restrict__ bhh1,const float* __restrict__ bh21)
{
  extern __shared__ char smx[];
  BF* sA=(BF*)smx;
  BF* sW=(BF*)(smx+131072);
  float* Cred=(float*)(smx+196608);     // 3 slabs of 2560 floats
  const int tid=threadIdx.x, lane=tid&31, w=tid>>5, blk=blockIdx.x;
  const int kg=w>>2, r0=(w&3)*16;
  const int rA=r0+(lane&7)+((lane>>3)&1)*8, cA=(lane>>4)&1;
  const int nB=lane&7, cB=(lane>>3)&1;
  const int rr=r0+(lane>>2), cc=(lane&3)*2;
  const int kbase=(kg&1)*32, hsel=kg>>1;   // which 64-col half + 32-col slice

  float creg[2][4];
  if(w<4){
#pragma unroll
    for(int q=0;q<2;q++)
#pragma unroll
      for(int p=0;p<2;p++){
        int r=rr+q*8, j=blk*8+cc+p, idx=q*2+p;
        creg[0][idx]=c0[(size_t)r*H_+j];
        creg[1][idx]=c0[(size_t)(B_+r)*H_+j];
#pragma unroll
        for(int L=0;L<2;L++){
          size_t b0=(size_t)L*SLAB+(size_t)r*H_+j;
          gHh[b0]=__float2bfloat16(0.f); gHl[b0]=__float2bfloat16(0.f);
          splitf(h0[(size_t)(L*B_+r)*H_+j],&gHh[b0+SLOT],&gHl[b0+SLOT]);
        }
      }
  }
  gridbar();

  for(int t=0;t<T_;t++){
#pragma unroll 1
    for(int L=0;L<2;L++){
      const int KA1=L?H_:IN0, KG=KA1+H_;
      const int NG2=KG>>7, NIT=NG2+8;         // 128-wide chunks: gates + skip(1024)
      const BF* Gh=(L?gG1h:gG0h)+(size_t)blk*32*KG;
      const BF* Gl=(L?gG1l:gG0l)+(size_t)blk*32*KG;
      const BF* Sh=gSkh+(size_t)L*NBLK*8*1024+(size_t)blk*8*1024;
      const BF* Sl=gSkl+(size_t)L*NBLK*8*1024+(size_t)blk*8*1024;
      const BF* skAh=gHh+(size_t)L*SLAB+(size_t)t*SLOT;
      const BF* skAl=gHl+(size_t)L*SLAB+(size_t)t*SLOT;

      float acc[5][4];
      float accX[4]={0,0,0,0};
#pragma unroll
      for(int i=0;i<5;i++){acc[i][0]=0;acc[i][1]=0;acc[i][2]=0;acc[i][3]=0;}

      auto do_stage=[&](int it){
        int st=it&3;
        BF* dA=sA+st*16384; BF* dW=sW+st*8192;
#pragma unroll
        for(int half=0;half<2;half++){
          BF* dAh=dA+half*8192; BF* dWh=dW+half*4096;
          if(it<NG2){
            int k0=it*128+half*64;
            const BF *ph,*pl; int ld;
            if(L==0){
              if(k0<IN0){ph=gXh+(size_t)t*B_*IN0+k0; pl=gXl+(size_t)t*B_*IN0+k0; ld=IN0;}
              else {ph=gHh+(size_t)(t+1)*SLOT+(k0-IN0); pl=gHl+(size_t)(t+1)*SLOT+(k0-IN0); ld=H_;}
            }else{
              if(k0<H_){ph=gHh+(size_t)(t+2)*SLOT+k0; pl=gHl+(size_t)(t+2)*SLOT+k0; ld=H_;}
              else {ph=gHh+SLAB+(size_t)(t+1)*SLOT+(k0-H_); pl=gHl+SLAB+(size_t)(t+1)*SLOT+(k0-H_); ld=H_;}
            }
            stT(dAh,dAh+4096,ph,pl,ld,64,tid,NTHR);
            stT(dWh,dWh+2048,Gh+k0,Gl+k0,KG,32,tid,NTHR);
          }else{
            int k0=(it-NG2)*128+half*64;
            stT(dAh,dAh+4096,skAh+k0,skAl+k0,H_,64,tid,NTHR);
            stT(dWh,dWh+2048,Sh+k0,Sl+k0,1024,8,tid,NTHR);
          }
        }
        cpc();
      };

      do_stage(0); do_stage(1); do_stage(2);
#pragma unroll 1
      for(int it=0;it<NIT;it++){
        if(it+2<NIT) cpw<2>(); else if(it+1<NIT) cpw<1>(); else cpw<0>();
        __syncthreads();
        if(it+3<NIT) do_stage(it+3);
        int st=it&3;
        BF* bA=sA+st*16384+hsel*8192;
        BF* bW=sW+st*8192 +hsel*4096;
        if(it<NG2) mm32i<2>(acc,bA,bA+4096,bW,bW+2048,kbase,rA,cA,lane);
        else       mm32s(acc[4],accX,bA,bA+4096,bW,bW+2048,kbase,rA,cA,nB,cB);
      }
      __syncthreads();
#pragma unroll
      for(int i=0;i<4;i++) acc[4][i]+=accX[i];

      // 4-way k-split reduction: kg>0 warps dump partials into slab kg-1
      if(kg>0){
        float* Cs=Cred+(kg-1)*2560;
#pragma unroll
        for(int nt=0;nt<5;nt++)
#pragma unroll
          for(int q=0;q<2;q++)
#pragma unroll
            for(int p=0;p<2;p++)
              Cs[(rr+q*8)*40+nt*8+cc+p]=acc[nt][q*2+p];
      }
      __syncthreads();
      if(kg==0){
        const float* bi=L?bih1:bih0; const float* bh=L?bhh1:bhh0; const float* b2=L?bh21:bh20;
#pragma unroll
        for(int q=0;q<2;q++)
#pragma unroll
          for(int p=0;p<2;p++){
            int r=rr+q*8, jl=cc+p, j=blk*8+jl, idx=q*2+p;
            float g0=acc[0][idx], g1=acc[1][idx], g2=acc[2][idx], g3=acc[3][idx], g4=acc[4][idx];
#pragma unroll
            for(int s=0;s<3;s++){
              const float* Cs=Cred+s*2560;
              g0+=Cs[r*40+jl]; g1+=Cs[r*40+8+jl]; g2+=Cs[r*40+16+jl];
              g3+=Cs[r*40+24+jl]; g4+=Cs[r*40+32+jl];
            }
            float ig=g0+bi[j]     +bh[j];
            float fg=g1+bi[H_+j]  +bh[H_+j];
            float gg=g2+bi[2*H_+j]+bh[2*H_+j];
            float og=g3+bi[3*H_+j]+bh[3*H_+j];
            float sk=g4+b2[j];
            float cv=creg[L][idx];
            float cn=sigf(fg)*cv+sigf(ig)*tanhf(gg);
            float h1=sigf(og)*tanhf(cn);
            float h2=sigf(sk);
            int code=mask[(size_t)t*2*H_+(size_t)L*H_+j];
            float hn=(code!=1?h1:0.f)+(code!=0?h2:0.f);
            creg[L][idx]=cn;
            size_t hi=(size_t)L*SLAB+(size_t)(t+2)*SLOT+(size_t)r*H_+j;
            splitf(hn,&gHh[hi],&gHl[hi]);
          }
      }
      if(L==0) gridbar();   // single grid barrier per step
    }
  }
}

// ---------------- output GEMM ----------------
__global__ void __launch_bounds__(256,1) k_out(const float* __restrict__ bo, float* __restrict__ out){
  extern __shared__ char smx[];
  BF* sA=(BF*)smx;
  BF* sW=(BF*)(smx+65536);
  float* Cred=(float*)(smx+131072);
  const int tid=threadIdx.x, lane=tid&31, w=tid>>5;
  const int kg=w>>2, r0=(w&3)*16;
  const int rA=r0+(lane&7)+((lane>>3)&1)*8, cA=(lane>>4)&1;
  const int rr=r0+(lane>>2), cc=(lane&3)*2;
  const int kbase=kg*32;
  const int t=blockIdx.x, n0=blockIdx.y*64;
  const BF* Ah=gHh+SLAB+(size_t)(t+2)*SLOT;
  const BF* Al=gHl+SLAB+(size_t)(t+2)*SLOT;
  const BF* Wh=gWoh+(size_t)n0*H_;
  const BF* Wl=gWol+(size_t)n0*H_;
  float acc[8][4];
#pragma unroll
  for(int i=0;i<8;i++){acc[i][0]=0;acc[i][1]=0;acc[i][2]=0;acc[i][3]=0;}
  auto do_stage=[&](int it){
    int st=it&3, k0=it*64;
    BF* dA=sA+st*8192; BF* dW=sW+st*8192;
    stT(dA,dA+4096,Ah+k0,Al+k0,H_,64,tid,256);
    stT(dW,dW+4096,Wh+k0,Wl+k0,H_,64,tid,256);
    cpc();
  };
  do_stage(0); do_stage(1); do_stage(2);
#pragma unroll 1
  for(int it=0;it<16;it++){
    int rem=15-it;
    if(rem>1) cpw<2>(); else if(rem==1) cpw<1>(); else cpw<0>();
    __syncthreads();
    int st=it&3;
    BF* bA=sA+st*8192; BF* bW=sW+st*8192;
    mm32i<4>(acc,bA,bA+4096,bW,bW+4096,kbase,rA,cA,lane);
    if(it+3<16) do_stage(it+3);
  }
  if(w>=4){
#pragma unroll
    for(int nt=0;nt<8;nt++)
#pragma unroll
      for(int q=0;q<2;q++)
#pragma unroll
        for(int p=0;p<2;p++)
          Cred[(rr+q*8)*64+nt*8+cc+p]=acc[nt][q*2+p];
  }
  __syncthreads();
  if(w<4){
#pragma unroll
    for(int nt=0;nt<8;nt++)
#pragma unroll
      for(int q=0;q<2;q++)
#pragma unroll
        for(int p=0;p<2;p++){
          int r=rr+q*8, col=n0+nt*8+cc+p;
          float v=acc[nt][q*2+p]+Cred[r*64+nt*8+cc+p]+bo[col];
          out[(size_t)t*B_*OUTD+(size_t)r*OUTD+col]=v;
        }
  }
}

extern "C" void kernel_launch(void* const* d_in, const int* in_sizes, int n_in,
                              void* d_out, int out_size) {
  const float* targets=(const float*)d_in[0];
  const float* h0  =(const float*)d_in[1];
  const float* c0  =(const float*)d_in[2];
  const int*   mask=(const int*)  d_in[3];
  const float* Wih0=(const float*)d_in[4];
  const float* Whh0=(const float*)d_in[5];
  const float* bih0=(const float*)d_in[6];
  const float* bhh0=(const float*)d_in[7];
  const float* Wih1=(const float*)d_in[8];
  const float* Whh1=(const float*)d_in[9];
  const float* bih1=(const float*)d_in[10];
  const float* bhh1=(const float*)d_in[11];
  const float* Wh20=(const float*)d_in[12];
  const float* bh20=(const float*)d_in[13];
  const float* Wh21=(const float*)d_in[14];
  const float* bh21=(const float*)d_in[15];
  const float* Wout=(const float*)d_in[16];
  const float* bout=(const float*)d_in[17];

  static int inited=0;
  if(!inited){
    cudaFuncSetAttribute(k_persist, cudaFuncAttributeMaxDynamicSharedMemorySize, 227328);
    cudaFuncSetAttribute(k_out,     cudaFuncAttributeMaxDynamicSharedMemorySize, 147456);
    inited=1;
  }
  // exactly 3 launches before k_persist -> k_persist occupies the ncu capture slot
  k_prepX<<<4096,256>>>(targets);
  k_prepG<<<4096,256>>>(Wih0,Whh0,Wih1,Whh1);
  k_prepS2<<<1024,256>>>(Wh20,Wh21);
  k_persist<<<NBLK,NTHR,227328>>>(mask,h0,c0,bih0,bhh0,bh20,bih1,bhh1,bh21);
  k_prepWo<<<512,256>>>(Wout);
  k_out<<<dim3(T_,8),256,147456>>>(bout,(float*)d_out);
}

// round 13
// speedup vs baseline: 2.1370x; 1.1794x over previous
#include <cuda_runtime.h>
#include <cuda_fp16.h>
#include <math.h>
#include <stdint.h>

typedef __half HF;
#define T_ 512
#define B_ 64
#define H_ 1024
#define IN0 1536
#define OUTD 512
#define SLOT (B_*H_)
#define SLAB ((size_t)514*SLOT)
#define NBLK 128
#define NTHR 512

__device__ __align__(16) HF gG0h[(size_t)NBLK*32*2560];
__device__ __align__(16) HF gG0l[(size_t)NBLK*32*2560];
__device__ __align__(16) HF gG1h[(size_t)NBLK*32*2048];
__device__ __align__(16) HF gG1l[(size_t)NBLK*32*2048];
__device__ __align__(16) HF gSkh[(size_t)2*NBLK*8*1024];
__device__ __align__(16) HF gSkl[(size_t)2*NBLK*8*1024];
__device__ __align__(16) HF gWoh[OUTD*H_];
__device__ __align__(16) HF gWol[OUTD*H_];
__device__ __align__(16) HF gX[(size_t)T_*B_*IN0];
__device__ __align__(16) HF gH[2*SLAB];

__device__ volatile unsigned gBarGen;
__device__ unsigned gBarCnt;

__device__ __forceinline__ float sigf(float x){ return 1.f/(1.f+expf(-x)); }
__device__ __forceinline__ void splitw(float v, HF* h, HF* l){
  HF a=__float2half(v); *h=a; *l=__float2half(v-__half2float(a));
}
__device__ __forceinline__ void cp16(HF* d, const HF* s){
  unsigned u=(unsigned)__cvta_generic_to_shared(d);
  asm volatile("cp.async.cg.shared.global [%0],[%1],16;"::"r"(u),"l"(s));
}
__device__ __forceinline__ void cpc(){ asm volatile("cp.async.commit_group;"); }
template<int N> __device__ __forceinline__ void cpw(){ asm volatile("cp.async.wait_group %0;"::"n"(N)); }

__device__ __forceinline__ void gridbar(){
  __syncthreads();
  if(threadIdx.x==0){
    unsigned old = gBarGen;
    __threadfence();
    unsigned prev = atomicAdd(&gBarCnt,1u);
    if(prev==NBLK-1u){ gBarCnt=0u; __threadfence(); gBarGen=old+1u; }
    else { while(gBarGen==old){} }
    __threadfence();
  }
  __syncthreads();
}

// tiles: rows x 64 fp16, 128B rows, 8-way 16B XOR swizzle
__device__ __forceinline__ const HF* swp(const HF* t_, int r, int cseg){
  return t_ + r*64 + ((cseg ^ (r&7))<<3);
}
// single-array stage (A panels)
__device__ __forceinline__ void stA(HF* d, const HF* p, int ld, int rows, int tid, int nthr){
  for(int u=tid; u<rows*8; u+=nthr){
    int r=u>>3, cs=u&7;
    cp16(d + r*64 + ((cs ^ (r&7))<<3), p + (size_t)r*ld + cs*8);
  }
}
// hi/lo pair stage (weights)
__device__ __forceinline__ void stW(HF* dh, HF* dl, const HF* ph, const HF* pl,
                                    int ld, int rows, int tid, int nthr){
  for(int u=tid; u<rows*8; u+=nthr){
    int r=u>>3, cs=u&7;
    int off = r*64 + ((cs ^ (r&7))<<3);
    size_t g=(size_t)r*ld + cs*8;
    cp16(dh+off, ph+g); cp16(dl+off, pl+g);
  }
}
__device__ __forceinline__ void ldsm4(unsigned a[4], const HF* p){
  unsigned u=(unsigned)__cvta_generic_to_shared(p);
  asm volatile("ldmatrix.sync.aligned.m8n8.x4.shared.b16 {%0,%1,%2,%3},[%4];"
    :"=r"(a[0]),"=r"(a[1]),"=r"(a[2]),"=r"(a[3]):"r"(u));
}
__device__ __forceinline__ void ldsm2(unsigned b[2], const HF* p){
  unsigned u=(unsigned)__cvta_generic_to_shared(p);
  asm volatile("ldmatrix.sync.aligned.m8n8.x2.shared.b16 {%0,%1},[%2];"
    :"=r"(b[0]),"=r"(b[1]):"r"(u));
}
__device__ __forceinline__ void mma(float c[4], const unsigned a[4], const unsigned b[2]){
  asm volatile("mma.sync.aligned.m16n8k16.row.col.f32.f16.f16.f32 "
    "{%0,%1,%2,%3},{%4,%5,%6,%7},{%8,%9},{%0,%1,%2,%3};"
    :"+f"(c[0]),"+f"(c[1]),"+f"(c[2]),"+f"(c[3])
    :"r"(a[0]),"r"(a[1]),"r"(a[2]),"r"(a[3]),"r"(b[0]),"r"(b[1]));
}
// x4 B load covering an nt-pair (two 8-row tiles) x 16 k
__device__ __forceinline__ void ldsm4b(unsigned b[4], const HF* t_, int np, int cs, int lane){
  int row  = np*16 + ((lane>>4)<<3) + (lane&7);
  int cseg = cs + ((lane>>3)&1);
  ldsm4(b, t_ + row*64 + ((cseg ^ (row&7))<<3));
}
// one 32-wide K slice of C(16 x NP*16); fp16 2-term: Ah*Wh + Ah*Wl
template<int NP>
__device__ __forceinline__ void mm32i(float (*acc)[4], const HF* A,
     const HF* Wh,const HF* Wl, int kbase, int rA,int cA,int lane){
#pragma unroll
  for(int kk=0;kk<2;kk++){
    int cs=(kbase>>3)+kk*2;
    unsigned ah[4];
    ldsm4(ah,swp(A,rA,cs+cA));
    unsigned bh[NP][4], bl[NP][4];
#pragma unroll
    for(int np=0;np<NP;np++){ ldsm4b(bh[np],Wh,np,cs,lane); ldsm4b(bl[np],Wl,np,cs,lane); }
#pragma unroll
    for(int np=0;np<NP;np++){ mma(acc[2*np],ah,bh[np]); mma(acc[2*np+1],ah,bh[np]+2); }
#pragma unroll
    for(int np=0;np<NP;np++){ mma(acc[2*np],ah,bl[np]); mma(acc[2*np+1],ah,bl[np]+2); }
  }
}
// skip-phase 32-wide K slice, single 8-col tile: dual accumulator chains
__device__ __forceinline__ void mm32s(float accA[4], float accB[4],
     const HF* A,const HF* Wh,const HF* Wl,
     int kbase, int rA,int cA,int nB,int cB){
  int cs0=(kbase>>3), cs1=cs0+2;
  unsigned ah0[4],ah1[4];
  ldsm4(ah0,swp(A,rA,cs0+cA));
  ldsm4(ah1,swp(A,rA,cs1+cA));
  unsigned bh0[2],bl0[2],bh1[2],bl1[2];
  ldsm2(bh0,swp(Wh,nB,cs0+cB)); ldsm2(bl0,swp(Wl,nB,cs0+cB));
  ldsm2(bh1,swp(Wh,nB,cs1+cB)); ldsm2(bl1,swp(Wl,nB,cs1+cB));
  mma(accA,ah0,bh0); mma(accB,ah1,bh1);
  mma(accA,ah0,bl0); mma(accB,ah1,bl1);
}

// ---------------- prep (3 launches so k_persist is launch #4 = ncu slot) ----------------
__global__ void k_prepX(const float* __restrict__ x){
  size_t n=(size_t)T_*B_*IN0;
  for(size_t i=(size_t)blockIdx.x*blockDim.x+threadIdx.x;i<n;i+=(size_t)gridDim.x*blockDim.x)
    gX[i]=__float2half(x[i]);
}
__global__ void k_prepG(const float* __restrict__ Wih0,const float* __restrict__ Whh0,
                        const float* __restrict__ Wih1,const float* __restrict__ Whh1){
  const size_t n0=(size_t)NBLK*32*2560, n1=(size_t)NBLK*32*2048;
  for(size_t i=(size_t)blockIdx.x*blockDim.x+threadIdx.x;i<n0+n1;i+=(size_t)gridDim.x*blockDim.x){
    int layer = i>=n0;
    size_t ii = layer? i-n0 : i;
    const int KA1=layer?H_:IN0, KG=KA1+H_;
    const float* Wih=layer?Wih1:Wih0; const float* Whh=layer?Whh1:Whh0;
    HF* dh=layer?gG1h:gG0h; HF* dl=layer?gG1l:gG0l;
    int k=(int)(ii%KG); int q=(int)(ii/KG); int nr=q&31, blk=q>>5;
    int row=(nr>>3)*H_+blk*8+(nr&7);
    float v = (k<KA1)? Wih[(size_t)row*KA1+k] : Whh[(size_t)row*H_+(k-KA1)];
    splitw(v,&dh[ii],&dl[ii]);
  }
}
__global__ void k_prepS2(const float* __restrict__ W0,const float* __restrict__ W1){
  const int n=NBLK*8*1024;
  for(int i=blockIdx.x*blockDim.x+threadIdx.x;i<2*n;i+=gridDim.x*blockDim.x){
    int layer=i>=n, ii=layer?i-n:i;
    const float* W=layer?W1:W0;
    HF* dh=gSkh+(size_t)layer*n; HF* dl=gSkl+(size_t)layer*n;
    int k=ii&1023; int q=ii>>10; int nr=q&7, blk=q>>3;
    splitw(W[(size_t)k*H_+blk*8+nr],&dh[ii],&dl[ii]);
  }
}
__global__ void k_prepWo(const float* __restrict__ W){
  for(int i=blockIdx.x*blockDim.x+threadIdx.x;i<OUTD*H_;i+=gridDim.x*blockDim.x)
    splitw(W[i],&gWoh[i],&gWol[i]);
}

// ---------------- persistent recurrence (512 threads, k-split x4, fp16 2-term) ----------------
// smem: sA 4 stages x 8192 elems (two 64-col halves) = 64KB @0
//       sW 4 stages x 8192 (two halves x (hi2048|lo2048)) = 64KB @65536
//       Cred 3 slabs x 64x40 f32 @131072 -> total 161792
__global__ void __launch_bounds__(NTHR,1) k_persist(const int* __restrict__ mask,
    const float* __restrict__ h0, const float* __restrict__ c0,
    const float* __restrict__ bih0,const float* __restrict__ bhh0,const float* __restrict__ bh20,
    const float* __restrict__ bih1,const float* __restrict__ bhh1,const float* __restrict__ bh21)
{
  extern __shared__ char smx[];
  HF* sA=(HF*)smx;
  HF* sW=(HF*)(smx+65536);
  float* Cred=(float*)(smx+131072);     // 3 slabs of 2560 floats
  const int tid=threadIdx.x, lane=tid&31, w=tid>>5, blk=blockIdx.x;
  const int kg=w>>2, r0=(w&3)*16;
  const int rA=r0+(lane&7)+((lane>>3)&1)*8, cA=(lane>>4)&1;
  const int nB=lane&7, cB=(lane>>3)&1;
  const int rr=r0+(lane>>2), cc=(lane&3)*2;
  const int kbase=(kg&1)*32, hsel=kg>>1;   // which 64-col half + 32-col slice

  float creg[2][4];
  if(w<4){
#pragma unroll
    for(int q=0;q<2;q++)
#pragma unroll
      for(int p=0;p<2;p++){
        int r=rr+q*8, j=blk*8+cc+p, idx=q*2+p;
        creg[0][idx]=c0[(size_t)r*H_+j];
        creg[1][idx]=c0[(size_t)(B_+r)*H_+j];
#pragma unroll
        for(int L=0;L<2;L++){
          size_t b0=(size_t)L*SLAB+(size_t)r*H_+j;
          gH[b0]=__float2half(0.f);                          // slot 0 zeros
          gH[b0+SLOT]=__float2half(h0[(size_t)(L*B_+r)*H_+j]); // slot 1 = h0
        }
      }
  }
  gridbar();

  for(int t=0;t<T_;t++){
#pragma unroll 1
    for(int L=0;L<2;L++){
      const int KA1=L?H_:IN0, KG=KA1+H_;
      const int NG2=KG>>7, NIT=NG2+8;         // 128-wide chunks: gates + skip(1024)
      const HF* Gh=(L?gG1h:gG0h)+(size_t)blk*32*KG;
      const HF* Gl=(L?gG1l:gG0l)+(size_t)blk*32*KG;
      const HF* Sh=gSkh+(size_t)L*NBLK*8*1024+(size_t)blk*8*1024;
      const HF* Sl=gSkl+(size_t)L*NBLK*8*1024+(size_t)blk*8*1024;
      const HF* skA=gH+(size_t)L*SLAB+(size_t)t*SLOT;

      float acc[5][4];
      float accX[4]={0,0,0,0};
#pragma unroll
      for(int i=0;i<5;i++){acc[i][0]=0;acc[i][1]=0;acc[i][2]=0;acc[i][3]=0;}

      auto do_stage=[&](int it){
        int st=it&3;
        HF* dA=sA+st*8192; HF* dW=sW+st*8192;
#pragma unroll
        for(int half=0;half<2;half++){
          HF* dAh=dA+half*4096; HF* dWh=dW+half*4096;
          if(it<NG2){
            int k0=it*128+half*64;
            const HF *pa; int ld;
            if(L==0){
              if(k0<IN0){pa=gX+(size_t)t*B_*IN0+k0; ld=IN0;}
              else {pa=gH+(size_t)(t+1)*SLOT+(k0-IN0); ld=H_;}
            }else{
              if(k0<H_){pa=gH+(size_t)(t+2)*SLOT+k0; ld=H_;}
              else {pa=gH+SLAB+(size_t)(t+1)*SLOT+(k0-H_); ld=H_;}
            }
            stA(dAh,pa,ld,64,tid,NTHR);
            stW(dWh,dWh+2048,Gh+k0,Gl+k0,KG,32,tid,NTHR);
          }else{
            int k0=(it-NG2)*128+half*64;
            stA(dAh,skA+k0,H_,64,tid,NTHR);
            stW(dWh,dWh+2048,Sh+k0,Sl+k0,1024,8,tid,NTHR);
          }
        }
        cpc();
      };

      do_stage(0); do_stage(1); do_stage(2);
#pragma unroll 1
      for(int it=0;it<NIT;it++){
        if(it+2<NIT) cpw<2>(); else if(it+1<NIT) cpw<1>(); else cpw<0>();
        __syncthreads();
        if(it+3<NIT) do_stage(it+3);
        int st=it&3;
        HF* bA=sA+st*8192+hsel*4096;
        HF* bW=sW+st*8192+hsel*4096;
        if(it<NG2) mm32i<2>(acc,bA,bW,bW+2048,kbase,rA,cA,lane);
        else       mm32s(acc[4],accX,bA,bW,bW+2048,kbase,rA,cA,nB,cB);
      }
      __syncthreads();
#pragma unroll
      for(int i=0;i<4;i++) acc[4][i]+=accX[i];

      // 4-way k-split reduction: kg>0 warps dump partials into slab kg-1
      if(kg>0){
        float* Cs=Cred+(kg-1)*2560;
#pragma unroll
        for(int nt=0;nt<5;nt++)
#pragma unroll
          for(int q=0;q<2;q++)
#pragma unroll
            for(int p=0;p<2;p++)
              Cs[(rr+q*8)*40+nt*8+cc+p]=acc[nt][q*2+p];
      }
      __syncthreads();
      if(kg==0){
        const float* bi=L?bih1:bih0; const float* bh=L?bhh1:bhh0; const float* b2=L?bh21:bh20;
#pragma unroll
        for(int q=0;q<2;q++)
#pragma unroll
          for(int p=0;p<2;p++){
            int r=rr+q*8, jl=cc+p, j=blk*8+jl, idx=q*2+p;
            float g0=acc[0][idx], g1=acc[1][idx], g2=acc[2][idx], g3=acc[3][idx], g4=acc[4][idx];
#pragma unroll
            for(int s=0;s<3;s++){
              const float* Cs=Cred+s*2560;
              g0+=Cs[r*40+jl]; g1+=Cs[r*40+8+jl]; g2+=Cs[r*40+16+jl];
              g3+=Cs[r*40+24+jl]; g4+=Cs[r*40+32+jl];
            }
            float ig=g0+bi[j]     +bh[j];
            float fg=g1+bi[H_+j]  +bh[H_+j];
            float gg=g2+bi[2*H_+j]+bh[2*H_+j];
            float og=g3+bi[3*H_+j]+bh[3*H_+j];
            float sk=g4+b2[j];
            float cv=creg[L][idx];
            float cn=sigf(fg)*cv+sigf(ig)*tanhf(gg);
            float h1=sigf(og)*tanhf(cn);
            float h2=sigf(sk);
            int code=mask[(size_t)t*2*H_+(size_t)L*H_+j];
            float hn=(code!=1?h1:0.f)+(code!=0?h2:0.f);
            creg[L][idx]=cn;
            gH[(size_t)L*SLAB+(size_t)(t+2)*SLOT+(size_t)r*H_+j]=__float2half(hn);
          }
      }
      if(L==0) gridbar();   // single grid barrier per step
    }
  }
}

// ---------------- output GEMM (fp16 2-term) ----------------
// smem: sA 4 x 4096 = 32KB @0 ; sW 4 x 8192 (hi|lo) = 64KB @32768 ; Cred 16KB @98304
__global__ void __launch_bounds__(256,1) k_out(const float* __restrict__ bo, float* __restrict__ out){
  extern __shared__ char smx[];
  HF* sA=(HF*)smx;
  HF* sW=(HF*)(smx+32768);
  float* Cred=(float*)(smx+98304);
  const int tid=threadIdx.x, lane=tid&31, w=tid>>5;
  const int kg=w>>2, r0=(w&3)*16;
  const int rA=r0+(lane&7)+((lane>>3)&1)*8, cA=(lane>>4)&1;
  const int rr=r0+(lane>>2), cc=(lane&3)*2;
  const int kbase=kg*32;
  const int t=blockIdx.x, n0=blockIdx.y*64;
  const HF* Ah=gH+SLAB+(size_t)(t+2)*SLOT;
  const HF* Wh=gWoh+(size_t)n0*H_;
  const HF* Wl=gWol+(size_t)n0*H_;
  float acc[8][4];
#pragma unroll
  for(int i=0;i<8;i++){acc[i][0]=0;acc[i][1]=0;acc[i][2]=0;acc[i][3]=0;}
  auto do_stage=[&](int it){
    int st=it&3, k0=it*64;
    HF* dA=sA+st*4096; HF* dW=sW+st*8192;
    stA(dA,Ah+k0,H_,64,tid,256);
    stW(dW,dW+4096,Wh+k0,Wl+k0,H_,64,tid,256);
    cpc();
  };
  do_stage(0); do_stage(1); do_stage(2);
#pragma unroll 1
  for(int it=0;it<16;it++){
    int rem=15-it;
    if(rem>1) cpw<2>(); else if(rem==1) cpw<1>(); else cpw<0>();
    __syncthreads();
    int st=it&3;
    HF* bA=sA+st*4096; HF* bW=sW+st*8192;
    mm32i<4>(acc,bA,bW,bW+4096,kbase,rA,cA,lane);
    if(it+3<16) do_stage(it+3);
  }
  if(w>=4){
#pragma unroll
    for(int nt=0;nt<8;nt++)
#pragma unroll
      for(int q=0;q<2;q++)
#pragma unroll
        for(int p=0;p<2;p++)
          Cred[(rr+q*8)*64+nt*8+cc+p]=acc[nt][q*2+p];
  }
  __syncthreads();
  if(w<4){
#pragma unroll
    for(int nt=0;nt<8;nt++)
#pragma unroll
      for(int q=0;q<2;q++)
#pragma unroll
        for(int p=0;p<2;p++){
          int r=rr+q*8, col=n0+nt*8+cc+p;
          float v=acc[nt][q*2+p]+Cred[r*64+nt*8+cc+p]+bo[col];
          out[(size_t)t*B_*OUTD+(size_t)r*OUTD+col]=v;
        }
  }
}

extern "C" void kernel_launch(void* const* d_in, const int* in_sizes, int n_in,
                              void* d_out, int out_size) {
  const float* targets=(const float*)d_in[0];
  const float* h0  =(const float*)d_in[1];
  const float* c0  =(const float*)d_in[2];
  const int*   mask=(const int*)  d_in[3];
  const float* Wih0=(const float*)d_in[4];
  const float* Whh0=(const float*)d_in[5];
  const float* bih0=(const float*)d_in[6];
  const float* bhh0=(const float*)d_in[7];
  const float* Wih1=(const float*)d_in[8];
  const float* Whh1=(const float*)d_in[9];
  const float* bih1=(const float*)d_in[10];
  const float* bhh1=(const float*)d_in[11];
  const float* Wh20=(const float*)d_in[12];
  const float* bh20=(const float*)d_in[13];
  const float* Wh21=(const float*)d_in[14];
  const float* bh21=(const float*)d_in[15];
  const float* Wout=(const float*)d_in[16];
  const float* bout=(const float*)d_in[17];

  static int inited=0;
  if(!inited){
    cudaFuncSetAttribute(k_persist, cudaFuncAttributeMaxDynamicSharedMemorySize, 161792);
    cudaFuncSetAttribute(k_out,     cudaFuncAttributeMaxDynamicSharedMemorySize, 114688);
    inited=1;
  }
  // exactly 3 launches before k_persist -> k_persist occupies the ncu capture slot
  k_prepX<<<4096,256>>>(targets);
  k_prepG<<<4096,256>>>(Wih0,Whh0,Wih1,Whh1);
  k_prepS2<<<1024,256>>>(Wh20,Wh21);
  k_persist<<<NBLK,NTHR,161792>>>(mask,h0,c0,bih0,bhh0,bh20,bih1,bhh1,bh21);
  k_prepWo<<<512,256>>>(Wout);
  k_out<<<dim3(T_,8),256,114688>>>(bout,(float*)d_out);
}

// round 15
// speedup vs baseline: 2.2423x; 1.0493x over previous
#include <cuda_runtime.h>
#include <cuda_fp16.h>
#include <math.h>
#include <stdint.h>

typedef __half HF;
#define T_ 512
#define B_ 64
#define H_ 1024
#define IN0 1536
#define OUTD 512
#define SLOT (B_*H_)
#define SLAB ((size_t)514*SLOT)
#define NBLK 128
#define NTHR 512

__device__ __align__(16) HF gG0h[(size_t)NBLK*32*2560];
__device__ __align__(16) HF gG0l[(size_t)NBLK*32*2560];
__device__ __align__(16) HF gG1h[(size_t)NBLK*32*2048];
__device__ __align__(16) HF gG1l[(size_t)NBLK*32*2048];
__device__ __align__(16) HF gSkh[(size_t)2*NBLK*8*1024];
__device__ __align__(16) HF gSkl[(size_t)2*NBLK*8*1024];
__device__ __align__(16) HF gWoh[OUTD*H_];
__device__ __align__(16) HF gWol[OUTD*H_];
__device__ __align__(16) HF gX[(size_t)T_*B_*IN0];
__device__ __align__(16) HF gH[2*SLAB];

__device__ volatile unsigned gBarGen;
__device__ unsigned gBarCnt;

__device__ __forceinline__ float sigf(float x){ return 1.f/(1.f+expf(-x)); }
__device__ __forceinline__ void splitw(float v, HF* h, HF* l){
  HF a=__float2half(v); *h=a; *l=__float2half(v-__half2float(a));
}
__device__ __forceinline__ unsigned su32(const void* p){ return (unsigned)__cvta_generic_to_shared(p); }
__device__ __forceinline__ void cp16(HF* d, const HF* s){
  asm volatile("cp.async.cg.shared.global [%0],[%1],16;"::"r"(su32(d)),"l"(s));
}
__device__ __forceinline__ void cpc(){ asm volatile("cp.async.commit_group;"); }
template<int N> __device__ __forceinline__ void cpw(){ asm volatile("cp.async.wait_group %0;"::"n"(N)); }

__device__ __forceinline__ void gridbar(){
  __syncthreads();
  if(threadIdx.x==0){
    unsigned old = gBarGen;
    __threadfence();
    unsigned prev = atomicAdd(&gBarCnt,1u);
    if(prev==NBLK-1u){ gBarCnt=0u; __threadfence(); gBarGen=old+1u; }
    else { while(gBarGen==old){} }
    __threadfence();
  }
  __syncthreads();
}

// tiles: rows x 64 fp16, 128B rows, 8-way 16B XOR swizzle
__device__ __forceinline__ const HF* swp(const HF* t_, int r, int cseg){
  return t_ + r*64 + ((cseg ^ (r&7))<<3);
}
__device__ __forceinline__ void stA(HF* d, const HF* p, int ld, int rows, int tid, int nthr){
  for(int u=tid; u<rows*8; u+=nthr){
    int r=u>>3, cs=u&7;
    cp16(d + r*64 + ((cs ^ (r&7))<<3), p + (size_t)r*ld + cs*8);
  }
}
__device__ __forceinline__ void stW(HF* dh, HF* dl, const HF* ph, const HF* pl,
                                    int ld, int rows, int tid, int nthr){
  for(int u=tid; u<rows*8; u+=nthr){
    int r=u>>3, cs=u&7;
    int off = r*64 + ((cs ^ (r&7))<<3);
    size_t g=(size_t)r*ld + cs*8;
    cp16(dh+off, ph+g); cp16(dl+off, pl+g);
  }
}
__device__ __forceinline__ void ldsm4(unsigned a[4], const HF* p){
  asm volatile("ldmatrix.sync.aligned.m8n8.x4.shared.b16 {%0,%1,%2,%3},[%4];"
    :"=r"(a[0]),"=r"(a[1]),"=r"(a[2]),"=r"(a[3]):"r"(su32(p)));
}
__device__ __forceinline__ void ldsm2(unsigned b[2], const HF* p){
  asm volatile("ldmatrix.sync.aligned.m8n8.x2.shared.b16 {%0,%1},[%2];"
    :"=r"(b[0]),"=r"(b[1]):"r"(su32(p)));
}
__device__ __forceinline__ void mma(float c[4], const unsigned a[4], const unsigned b[2]){
  asm volatile("mma.sync.aligned.m16n8k16.row.col.f32.f16.f16.f32 "
    "{%0,%1,%2,%3},{%4,%5,%6,%7},{%8,%9},{%0,%1,%2,%3};"
    :"+f"(c[0]),"+f"(c[1]),"+f"(c[2]),"+f"(c[3])
    :"r"(a[0]),"r"(a[1]),"r"(a[2]),"r"(a[3]),"r"(b[0]),"r"(b[1]));
}
// x4 B load covering an nt-pair (two 8-row tiles) x 16 k
__device__ __forceinline__ void ldsm4b(unsigned b[4], const HF* t_, int np, int cs, int lane){
  int row  = np*16 + ((lane>>4)<<3) + (lane&7);
  int cseg = cs + ((lane>>3)&1);
  ldsm4(b, t_ + row*64 + ((cseg ^ (row&7))<<3));
}
// k_out helper (unchanged from R12)
template<int NP>
__device__ __forceinline__ void mm32i(float (*acc)[4], const HF* A,
     const HF* Wh,const HF* Wl, int kbase, int rA,int cA,int lane){
#pragma unroll
  for(int kk=0;kk<2;kk++){
    int cs=(kbase>>3)+kk*2;
    unsigned ah[4];
    ldsm4(ah,swp(A,rA,cs+cA));
    unsigned bh[NP][4], bl[NP][4];
#pragma unroll
    for(int np=0;np<NP;np++){ ldsm4b(bh[np],Wh,np,cs,lane); ldsm4b(bl[np],Wl,np,cs,lane); }
#pragma unroll
    for(int np=0;np<NP;np++){ mma(acc[2*np],ah,bh[np]); mma(acc[2*np+1],ah,bh[np]+2); }
#pragma unroll
    for(int np=0;np<NP;np++){ mma(acc[2*np],ah,bl[np]); mma(acc[2*np+1],ah,bl[np]+2); }
  }
}

// ---------------- prep (3 launches so k_persist is launch #4 = ncu slot) ----------------
__global__ void k_prepX(const float* __restrict__ x){
  size_t n=(size_t)T_*B_*IN0;
  for(size_t i=(size_t)blockIdx.x*blockDim.x+threadIdx.x;i<n;i+=(size_t)gridDim.x*blockDim.x)
    gX[i]=__float2half(x[i]);
}
__global__ void k_prepG(const float* __restrict__ Wih0,const float* __restrict__ Whh0,
                        const float* __restrict__ Wih1,const float* __restrict__ Whh1){
  const size_t n0=(size_t)NBLK*32*2560, n1=(size_t)NBLK*32*2048;
  for(size_t i=(size_t)blockIdx.x*blockDim.x+threadIdx.x;i<n0+n1;i+=(size_t)gridDim.x*blockDim.x){
    int layer = i>=n0;
    size_t ii = layer? i-n0 : i;
    const int KA1=layer?H_:IN0, KG=KA1+H_;
    const float* Wih=layer?Wih1:Wih0; const float* Whh=layer?Whh1:Whh0;
    HF* dh=layer?gG1h:gG0h; HF* dl=layer?gG1l:gG0l;
    int k=(int)(ii%KG); int q=(int)(ii/KG); int nr=q&31, blk=q>>5;
    int row=(nr>>3)*H_+blk*8+(nr&7);
    float v = (k<KA1)? Wih[(size_t)row*KA1+k] : Whh[(size_t)row*H_+(k-KA1)];
    splitw(v,&dh[ii],&dl[ii]);
  }
}
__global__ void k_prepS2(const float* __restrict__ W0,const float* __restrict__ W1){
  const int n=NBLK*8*1024;
  for(int i=blockIdx.x*blockDim.x+threadIdx.x;i<2*n;i+=gridDim.x*blockDim.x){
    int layer=i>=n, ii=layer?i-n:i;
    const float* W=layer?W1:W0;
    HF* dh=gSkh+(size_t)layer*n; HF* dl=gSkl+(size_t)layer*n;
    int k=ii&1023; int q=ii>>10; int nr=q&7, blk=q>>3;
    splitw(W[(size_t)k*H_+blk*8+nr],&dh[ii],&dl[ii]);
  }
}
__global__ void k_prepWo(const float* __restrict__ W){
  for(int i=blockIdx.x*blockDim.x+threadIdx.x;i<OUTD*H_;i+=gridDim.x*blockDim.x)
    splitw(W[i],&gWoh[i],&gWol[i]);
}

// ---------------- persistent recurrence (512 thr, 2m x 8kg, fp16 2-term) ----------------
// smem: sA 4 x 8192 HF (two 64-col halves) = 64KB @0
//       sW 4 x 8192 HF (two halves x (hi|lo)) = 64KB @65536
//       Cred 8 slabs x 2560 f32 = 80KB @131072 ; sC 2x512 f32 @212992 -> 217088
__global__ void __launch_bounds__(NTHR,1) k_persist(const int* __restrict__ mask,
    const float* __restrict__ h0, const float* __restrict__ c0,
    const float* __restrict__ bih0,const float* __restrict__ bhh0,const float* __restrict__ bh20,
    const float* __restrict__ bih1,const float* __restrict__ bhh1,const float* __restrict__ bh21)
{
  extern __shared__ __align__(1024) char smx[];
  HF* sA=(HF*)smx;
  HF* sW=(HF*)(smx+65536);
  float* Cred=(float*)(smx+131072);
  float* sC=(float*)(smx+212992);
  const int tid=threadIdx.x, lane=tid&31, w=tid>>5, blk=blockIdx.x;
  const int m=w&1, kg=w>>1;
  const int hsel=kg>>2, csl=(kg&3)*2;
  const int rA0=m*32+(lane&7)+((lane>>3)&1)*8, cA=(lane>>4)&1;
  const int nB=lane&7, cB=(lane>>3)&1;
  const int rr=lane>>2, cc=(lane&3)*2;

  // init c-state (smem) and h history slots 0/1
  {
    int e=tid, r=e>>3, jl=e&7, j=blk*8+jl;
    sC[e]     =c0[(size_t)r*H_+j];
    sC[512+e] =c0[(size_t)(B_+r)*H_+j];
#pragma unroll
    for(int L=0;L<2;L++){
      size_t b0=(size_t)L*SLAB+(size_t)r*H_+j;
      gH[b0]=__float2half(0.f);                            // slot 0 zeros
      gH[b0+SLOT]=__float2half(h0[(size_t)(L*B_+r)*H_+j]); // slot 1 = h0
    }
  }
  gridbar();

  for(int t=0;t<T_;t++){
#pragma unroll 1
    for(int L=0;L<2;L++){
      const int KA1=L?H_:IN0, KG=KA1+H_;
      const int NG2=KG>>7, NIT=NG2+8;
      const HF* Gh=(L?gG1h:gG0h)+(size_t)blk*32*KG;
      const HF* Gl=(L?gG1l:gG0l)+(size_t)blk*32*KG;
      const HF* Sh=gSkh+(size_t)L*NBLK*8*1024+(size_t)blk*8*1024;
      const HF* Sl=gSkl+(size_t)L*NBLK*8*1024+(size_t)blk*8*1024;
      const HF* skA=gH+(size_t)L*SLAB+(size_t)t*SLOT;

      float accG[2][4][4], accS[2][4];
#pragma unroll
      for(int a=0;a<2;a++){
#pragma unroll
        for(int b=0;b<4;b++){accG[a][b][0]=0;accG[a][b][1]=0;accG[a][b][2]=0;accG[a][b][3]=0;}
        accS[a][0]=0;accS[a][1]=0;accS[a][2]=0;accS[a][3]=0;
      }

      auto do_stage=[&](int it){
        int st=it&3;
        HF* dA=sA+st*8192; HF* dW=sW+st*8192;
#pragma unroll
        for(int half=0;half<2;half++){
          HF* dAh=dA+half*4096; HF* dWh=dW+half*4096;
          if(it<NG2){
            int k0=it*128+half*64;
            const HF *pa; int ld;
            if(L==0){
              if(k0<IN0){pa=gX+(size_t)t*B_*IN0+k0; ld=IN0;}
              else {pa=gH+(size_t)(t+1)*SLOT+(k0-IN0); ld=H_;}
            }else{
              if(k0<H_){pa=gH+(size_t)(t+2)*SLOT+k0; ld=H_;}
              else {pa=gH+SLAB+(size_t)(t+1)*SLOT+(k0-H_); ld=H_;}
            }
            stA(dAh,pa,ld,64,tid,NTHR);
            stW(dWh,dWh+2048,Gh+k0,Gl+k0,KG,32,tid,NTHR);
          }else{
            int k0=(it-NG2)*128+half*64;
            stA(dAh,skA+k0,H_,64,tid,NTHR);
            stW(dWh,dWh+2048,Sh+k0,Sl+k0,1024,8,tid,NTHR);
          }
        }
        cpc();
      };

      do_stage(0); do_stage(1); do_stage(2);
#pragma unroll 1
      for(int it=0;it<NIT;it++){
        if(it+2<NIT) cpw<2>(); else if(it+1<NIT) cpw<1>(); else cpw<0>();
        __syncthreads();
        if(it+3<NIT) do_stage(it+3);
        int st=it&3;
        const HF* bA=sA+st*8192+hsel*4096;
        const HF* bW=sW+st*8192+hsel*4096;
        unsigned a0[4],a1[4];
        ldsm4(a0,swp(bA,rA0,csl+cA));
        ldsm4(a1,swp(bA,rA0+16,csl+cA));
        if(it<NG2){
#pragma unroll
          for(int np=0;np<2;np++){
            unsigned bh[4],bl[4];
            ldsm4b(bh,bW,np,csl,lane);
            ldsm4b(bl,bW+2048,np,csl,lane);
            mma(accG[0][2*np],a0,bh);   mma(accG[0][2*np+1],a0,bh+2);
            mma(accG[1][2*np],a1,bh);   mma(accG[1][2*np+1],a1,bh+2);
            mma(accG[0][2*np],a0,bl);   mma(accG[0][2*np+1],a0,bl+2);
            mma(accG[1][2*np],a1,bl);   mma(accG[1][2*np+1],a1,bl+2);
          }
        }else{
          unsigned bh[2],bl[2];
          ldsm2(bh,swp(bW,nB,csl+cB));
          ldsm2(bl,swp(bW+2048,nB,csl+cB));
          mma(accS[0],a0,bh); mma(accS[1],a1,bh);
          mma(accS[0],a0,bl); mma(accS[1],a1,bl);
        }
      }
      __syncthreads();

      // every warp dumps its partials into its kg slab
      {
        float* Cs=Cred+kg*2560;
#pragma unroll
        for(int mi=0;mi<2;mi++){
          int rb=m*32+mi*16+rr;
#pragma unroll
          for(int nt=0;nt<4;nt++){
#pragma unroll
            for(int q=0;q<2;q++){
              Cs[(rb+q*8)*40+nt*8+cc]   =accG[mi][nt][q*2];
              Cs[(rb+q*8)*40+nt*8+cc+1] =accG[mi][nt][q*2+1];
            }
          }
#pragma unroll
          for(int q=0;q<2;q++){
            Cs[(rb+q*8)*40+32+cc]   =accS[mi][q*2];
            Cs[(rb+q*8)*40+32+cc+1] =accS[mi][q*2+1];
          }
        }
      }
      __syncthreads();

      // cooperative reduce + LSTM elementwise: 512 threads, 1 h-element each
      {
        const float* bi=L?bih1:bih0; const float* bh=L?bhh1:bhh0; const float* b2=L?bh21:bh20;
        int e=tid, r=e>>3, jl=e&7, j=blk*8+jl;
        float g0=0,g1=0,g2=0,g3=0,g4=0;
#pragma unroll
        for(int s=0;s<8;s++){
          const float* Cs=Cred+s*2560+r*40;
          g0+=Cs[jl]; g1+=Cs[8+jl]; g2+=Cs[16+jl]; g3+=Cs[24+jl]; g4+=Cs[32+jl];
        }
        float ig=g0+bi[j]     +bh[j];
        float fg=g1+bi[H_+j]  +bh[H_+j];
        float gg=g2+bi[2*H_+j]+bh[2*H_+j];
        float og=g3+bi[3*H_+j]+bh[3*H_+j];
        float sk=g4+b2[j];
        float cv=sC[L*512+e];
        float cn=sigf(fg)*cv+sigf(ig)*tanhf(gg);
        float h1=sigf(og)*tanhf(cn);
        float h2=sigf(sk);
        int code=mask[(size_t)t*2*H_+(size_t)L*H_+j];
        float hn=(code!=1?h1:0.f)+(code!=0?h2:0.f);
        sC[L*512+e]=cn;
        gH[(size_t)L*SLAB+(size_t)(t+2)*SLOT+(size_t)r*H_+j]=__float2half(hn);
      }
      if(L==0) gridbar();   // single grid barrier per step
      else __syncthreads(); // protect Cred/sC reuse into next step
    }
  }
}

// ---------------- output GEMM (fp16 2-term, unchanged from R12) ----------------
__global__ void __launch_bounds__(256,1) k_out(const float* __restrict__ bo, float* __restrict__ out){
  extern __shared__ __align__(1024) char smx[];
  HF* sA=(HF*)smx;
  HF* sW=(HF*)(smx+32768);
  float* Cred=(float*)(smx+98304);
  const int tid=threadIdx.x, lane=tid&31, w=tid>>5;
  const int kg=w>>2, r0=(w&3)*16;
  const int rA=r0+(lane&7)+((lane>>3)&1)*8, cA=(lane>>4)&1;
  const int rr=r0+(lane>>2), cc=(lane&3)*2;
  const int kbase=kg*32;
  const int t=blockIdx.x, n0=blockIdx.y*64;
  const HF* Ah=gH+SLAB+(size_t)(t+2)*SLOT;
  const HF* Wh=gWoh+(size_t)n0*H_;
  const HF* Wl=gWol+(size_t)n0*H_;
  float acc[8][4];
#pragma unroll
  for(int i=0;i<8;i++){acc[i][0]=0;acc[i][1]=0;acc[i][2]=0;acc[i][3]=0;}
  auto do_stage=[&](int it){
    int st=it&3, k0=it*64;
    HF* dA=sA+st*4096; HF* dW=sW+st*8192;
    stA(dA,Ah+k0,H_,64,tid,256);
    stW(dW,dW+4096,Wh+k0,Wl+k0,H_,64,tid,256);
    cpc();
  };
  do_stage(0); do_stage(1); do_stage(2);
#pragma unroll 1
  for(int it=0;it<16;it++){
    int rem=15-it;
    if(rem>1) cpw<2>(); else if(rem==1) cpw<1>(); else cpw<0>();
    __syncthreads();
    int st=it&3;
    HF* bA=sA+st*4096; HF* bW=sW+st*8192;
    mm32i<4>(acc,bA,bW,bW+4096,kbase,rA,cA,lane);
    if(it+3<16) do_stage(it+3);
  }
  if(w>=4){
#pragma unroll
    for(int nt=0;nt<8;nt++)
#pragma unroll
      for(int q=0;q<2;q++)
#pragma unroll
        for(int p=0;p<2;p++)
          Cred[(rr+q*8)*64+nt*8+cc+p]=acc[nt][q*2+p];
  }
  __syncthreads();
  if(w<4){
#pragma unroll
    for(int nt=0;nt<8;nt++)
#pragma unroll
      for(int q=0;q<2;q++)
#pragma unroll
        for(int p=0;p<2;p++){
          int r=rr+q*8, col=n0+nt*8+cc+p;
          float v=acc[nt][q*2+p]+Cred[r*64+nt*8+cc+p]+bo[col];
          out[(size_t)t*B_*OUTD+(size_t)r*OUTD+col]=v;
        }
  }
}

extern "C" void kernel_launch(void* const* d_in, const int* in_sizes, int n_in,
                              void* d_out, int out_size) {
  const float* targets=(const float*)d_in[0];
  const float* h0  =(const float*)d_in[1];
  const float* c0  =(const float*)d_in[2];
  const int*   mask=(const int*)  d_in[3];
  const float* Wih0=(const float*)d_in[4];
  const float* Whh0=(const float*)d_in[5];
  const float* bih0=(const float*)d_in[6];
  const float* bhh0=(const float*)d_in[7];
  const float* Wih1=(const float*)d_in[8];
  const float* Whh1=(const float*)d_in[9];
  const float* bih1=(const float*)d_in[10];
  const float* bhh1=(const float*)d_in[11];
  const float* Wh20=(const float*)d_in[12];
  const float* bh20=(const float*)d_in[13];
  const float* Wh21=(const float*)d_in[14];
  const float* bh21=(const float*)d_in[15];
  const float* Wout=(const float*)d_in[16];
  const float* bout=(const float*)d_in[17];

  static int inited=0;
  if(!inited){
    cudaFuncSetAttribute(k_persist, cudaFuncAttributeMaxDynamicSharedMemorySize, 217088);
    cudaFuncSetAttribute(k_out,     cudaFuncAttributeMaxDynamicSharedMemorySize, 114688);
    inited=1;
  }
  // exactly 3 launches before k_persist -> k_persist occupies the ncu capture slot
  k_prepX<<<4096,256>>>(targets);
  k_prepG<<<4096,256>>>(Wih0,Whh0,Wih1,Whh1);
  k_prepS2<<<1024,256>>>(Wh20,Wh21);
  k_persist<<<NBLK,NTHR,217088>>>(mask,h0,c0,bih0,bhh0,bh20,bih1,bhh1,bh21);
  k_prepWo<<<512,256>>>(Wout);
  k_out<<<dim3(T_,8),256,114688>>>(bout,(float*)d_out);
}

// round 16
// speedup vs baseline: 2.5895x; 1.1548x over previous
#include <cuda_runtime.h>
#include <cuda_fp16.h>
#include <math.h>
#include <stdint.h>

typedef __half HF;
#define T_ 512
#define B_ 64
#define H_ 1024
#define IN0 1536
#define OUTD 512
#define SLOT (B_*H_)
#define SLAB ((size_t)514*SLOT)
#define NBLK 128
#define NTHR 512

__device__ __align__(16) HF gG0h[(size_t)NBLK*32*2560];
__device__ __align__(16) HF gG0l[(size_t)NBLK*32*2560];
__device__ __align__(16) HF gG1h[(size_t)NBLK*32*2048];
__device__ __align__(16) HF gG1l[(size_t)NBLK*32*2048];
__device__ __align__(16) HF gSkh[(size_t)2*NBLK*8*1024];
__device__ __align__(16) HF gSkl[(size_t)2*NBLK*8*1024];
__device__ __align__(16) HF gWoh[OUTD*H_];
__device__ __align__(16) HF gWol[OUTD*H_];
__device__ __align__(16) HF gX[(size_t)T_*B_*IN0];
__device__ __align__(16) HF gH[2*SLAB];

__device__ volatile unsigned gBarGen;
__device__ unsigned gBarCnt;

__device__ __forceinline__ float sigf(float x){ return 1.f/(1.f+expf(-x)); }
__device__ __forceinline__ void splitw(float v, HF* h, HF* l){
  HF a=__float2half(v); *h=a; *l=__float2half(v-__half2float(a));
}
__device__ __forceinline__ unsigned su32(const void* p){ return (unsigned)__cvta_generic_to_shared(p); }
__device__ __forceinline__ void cp16(HF* d, const HF* s){
  asm volatile("cp.async.cg.shared.global [%0],[%1],16;"::"r"(su32(d)),"l"(s));
}
__device__ __forceinline__ void cp16u(unsigned d, const HF* s){
  asm volatile("cp.async.cg.shared.global [%0],[%1],16;"::"r"(d),"l"(s));
}
__device__ __forceinline__ void cpc(){ asm volatile("cp.async.commit_group;"); }
template<int N> __device__ __forceinline__ void cpw(){ asm volatile("cp.async.wait_group %0;"::"n"(N)); }

__device__ __forceinline__ void gridbar(){
  __syncthreads();
  if(threadIdx.x==0){
    unsigned old = gBarGen;
    __threadfence();
    unsigned prev = atomicAdd(&gBarCnt,1u);
    if(prev==NBLK-1u){ gBarCnt=0u; __threadfence(); gBarGen=old+1u; }
    else { while(gBarGen==old){} }
    __threadfence();
  }
  __syncthreads();
}

// tiles: rows x 64 fp16, 128B rows, 8-way 16B XOR swizzle
__device__ __forceinline__ const HF* swp(const HF* t_, int r, int cseg){
  return t_ + r*64 + ((cseg ^ (r&7))<<3);
}
__device__ __forceinline__ void stA(HF* d, const HF* p, int ld, int rows, int tid, int nthr){
  for(int u=tid; u<rows*8; u+=nthr){
    int r=u>>3, cs=u&7;
    cp16(d + r*64 + ((cs ^ (r&7))<<3), p + (size_t)r*ld + cs*8);
  }
}
__device__ __forceinline__ void stW(HF* dh, HF* dl, const HF* ph, const HF* pl,
                                    int ld, int rows, int tid, int nthr){
  for(int u=tid; u<rows*8; u+=nthr){
    int r=u>>3, cs=u&7;
    int off = r*64 + ((cs ^ (r&7))<<3);
    size_t g=(size_t)r*ld + cs*8;
    cp16(dh+off, ph+g); cp16(dl+off, pl+g);
  }
}
__device__ __forceinline__ void ldsm4(unsigned a[4], const HF* p){
  asm volatile("ldmatrix.sync.aligned.m8n8.x4.shared.b16 {%0,%1,%2,%3},[%4];"
    :"=r"(a[0]),"=r"(a[1]),"=r"(a[2]),"=r"(a[3]):"r"(su32(p)));
}
__device__ __forceinline__ void ldsm4u(unsigned a[4], unsigned p){
  asm volatile("ldmatrix.sync.aligned.m8n8.x4.shared.b16 {%0,%1,%2,%3},[%4];"
    :"=r"(a[0]),"=r"(a[1]),"=r"(a[2]),"=r"(a[3]):"r"(p));
}
__device__ __forceinline__ void ldsm2u(unsigned b[2], unsigned p){
  asm volatile("ldmatrix.sync.aligned.m8n8.x2.shared.b16 {%0,%1},[%2];"
    :"=r"(b[0]),"=r"(b[1]):"r"(p));
}
__device__ __forceinline__ void mma(float c[4], const unsigned a[4], const unsigned b[2]){
  asm volatile("mma.sync.aligned.m16n8k16.row.col.f32.f16.f16.f32 "
    "{%0,%1,%2,%3},{%4,%5,%6,%7},{%8,%9},{%0,%1,%2,%3};"
    :"+f"(c[0]),"+f"(c[1]),"+f"(c[2]),"+f"(c[3])
    :"r"(a[0]),"r"(a[1]),"r"(a[2]),"r"(a[3]),"r"(b[0]),"r"(b[1]));
}
__device__ __forceinline__ void ldsm4b(unsigned b[4], const HF* t_, int np, int cs, int lane){
  int row  = np*16 + ((lane>>4)<<3) + (lane&7);
  int cseg = cs + ((lane>>3)&1);
  ldsm4(b, t_ + row*64 + ((cseg ^ (row&7))<<3));
}
// k_out helper
template<int NP>
__device__ __forceinline__ void mm32i(float (*acc)[4], const HF* A,
     const HF* Wh,const HF* Wl, int kbase, int rA,int cA,int lane){
#pragma unroll
  for(int kk=0;kk<2;kk++){
    int cs=(kbase>>3)+kk*2;
    unsigned ah[4];
    ldsm4(ah,swp(A,rA,cs+cA));
    unsigned bh[NP][4], bl[NP][4];
#pragma unroll
    for(int np=0;np<NP;np++){ ldsm4b(bh[np],Wh,np,cs,lane); ldsm4b(bl[np],Wl,np,cs,lane); }
#pragma unroll
    for(int np=0;np<NP;np++){ mma(acc[2*np],ah,bh[np]); mma(acc[2*np+1],ah,bh[np]+2); }
#pragma unroll
    for(int np=0;np<NP;np++){ mma(acc[2*np],ah,bl[np]); mma(acc[2*np+1],ah,bl[np]+2); }
  }
}

// ---------------- prep (3 launches so k_persist is launch #4 = ncu slot) ----------------
__global__ void k_prepX(const float* __restrict__ x){
  size_t n=(size_t)T_*B_*IN0;
  for(size_t i=(size_t)blockIdx.x*blockDim.x+threadIdx.x;i<n;i+=(size_t)gridDim.x*blockDim.x)
    gX[i]=__float2half(x[i]);
}
__global__ void k_prepG(const float* __restrict__ Wih0,const float* __restrict__ Whh0,
                        const float* __restrict__ Wih1,const float* __restrict__ Whh1){
  const size_t n0=(size_t)NBLK*32*2560, n1=(size_t)NBLK*32*2048;
  for(size_t i=(size_t)blockIdx.x*blockDim.x+threadIdx.x;i<n0+n1;i+=(size_t)gridDim.x*blockDim.x){
    int layer = i>=n0;
    size_t ii = layer? i-n0 : i;
    const int KA1=layer?H_:IN0, KG=KA1+H_;
    const float* Wih=layer?Wih1:Wih0; const float* Whh=layer?Whh1:Whh0;
    HF* dh=layer?gG1h:gG0h; HF* dl=layer?gG1l:gG0l;
    int k=(int)(ii%KG); int q=(int)(ii/KG); int nr=q&31, blk=q>>5;
    int row=(nr>>3)*H_+blk*8+(nr&7);
    float v = (k<KA1)? Wih[(size_t)row*KA1+k] : Whh[(size_t)row*H_+(k-KA1)];
    splitw(v,&dh[ii],&dl[ii]);
  }
}
__global__ void k_prepS2(const float* __restrict__ W0,const float* __restrict__ W1){
  const int n=NBLK*8*1024;
  for(int i=blockIdx.x*blockDim.x+threadIdx.x;i<2*n;i+=gridDim.x*blockDim.x){
    int layer=i>=n, ii=layer?i-n:i;
    const float* W=layer?W1:W0;
    HF* dh=gSkh+(size_t)layer*n; HF* dl=gSkl+(size_t)layer*n;
    int k=ii&1023; int q=ii>>10; int nr=q&7, blk=q>>3;
    splitw(W[(size_t)k*H_+blk*8+nr],&dh[ii],&dl[ii]);
  }
}
__global__ void k_prepWo(const float* __restrict__ W){
  for(int i=blockIdx.x*blockDim.x+threadIdx.x;i<OUTD*H_;i+=gridDim.x*blockDim.x)
    splitw(W[i],&gWoh[i],&gWol[i]);
}

// ---------------- persistent recurrence (512 thr, 2m x 8kg, fp16 2-term) ----------------
// smem: sA 4 x 16384B @0 ; sW 4 x 16384B @65536 ; Cred 8 x 2560 f32 @131072 -> 212992
__global__ void __launch_bounds__(NTHR,1) k_persist(const int* __restrict__ mask,
    const float* __restrict__ h0, const float* __restrict__ c0,
    const float* __restrict__ bih0,const float* __restrict__ bhh0,const float* __restrict__ bh20,
    const float* __restrict__ bih1,const float* __restrict__ bhh1,const float* __restrict__ bh21)
{
  extern __shared__ __align__(1024) char smx[];
  HF* sA=(HF*)smx;
  HF* sW=(HF*)(smx+65536);
  float* Cred=(float*)(smx+131072);
  const int tid=threadIdx.x, lane=tid&31, w=tid>>5, blk=blockIdx.x;
  const int m=w&1, kg=w>>1;
  const int hsel=kg>>2, csl=(kg&3)*2;
  const int rA0=m*32+(lane&7)+((lane>>3)&1)*8, cA=(lane>>4)&1;
  const int nB=lane&7, cB=(lane>>3)&1;
  const int rr=lane>>2, cc=(lane&3)*2;

  // ---- precomputed ldsm addresses (byte-based, stage-invariant parts) ----
  auto offf=[](int r,int c)->unsigned{ return (unsigned)(r*128 + ((c^(r&7))<<4)); };
  const unsigned bAu=su32(sA), bWu=su32(sW);
  const unsigned uA0=bAu+hsel*8192+offf(rA0,csl+cA);
  const unsigned uA1=bAu+hsel*8192+offf(rA0+16,csl+cA);
  const int rB=((lane>>4)<<3)+(lane&7), cgB=csl+((lane>>3)&1);
  const unsigned uB0=bWu+hsel*8192+offf(rB,cgB);
  const unsigned uB1=bWu+hsel*8192+offf(rB+16,cgB);
  const unsigned uS =bWu+hsel*8192+offf(nB,csl+cB);

  // ---- precomputed staging constants ----
  const int ar=tid>>3;
  const unsigned dA_off=offf(ar,tid&7);
  const unsigned rIN0=(unsigned)ar*IN0, rHh=(unsigned)ar*H_;
  const unsigned cs8=(unsigned)(tid&7)*8;
  const int plane=tid>>8, wr=(tid&255)>>3;
  const unsigned dW_off=offf(wr,tid&7)+(unsigned)plane*4096u;
  const unsigned rS1024=(unsigned)wr*1024u;
  const bool wskip=(wr<8);

  // c-state in registers (tid <-> element bijection)
  float creg0, creg1;
  {
    int r=tid>>3, j=blk*8+(tid&7);
    creg0=c0[(size_t)r*H_+j];
    creg1=c0[(size_t)(B_+r)*H_+j];
#pragma unroll
    for(int L=0;L<2;L++){
      size_t b0=(size_t)L*SLAB+(size_t)r*H_+j;
      gH[b0]=__float2half(0.f);
      gH[b0+SLOT]=__float2half(h0[(size_t)(L*B_+r)*H_+j]);
    }
  }
  gridbar();

  for(int t=0;t<T_;t++){
#pragma unroll 1
    for(int L=0;L<2;L++){
      const int KG=L?2048:2560;
      const int NG2=KG>>7, NIT=NG2+8;
      const HF* Gh=(L?gG1h:gG0h)+(size_t)blk*32*KG;
      const HF* Gl=(L?gG1l:gG0l)+(size_t)blk*32*KG;
      const HF* Sh=gSkh+(size_t)L*NBLK*8*1024+(size_t)blk*8*1024;
      const HF* Sl=gSkl+(size_t)L*NBLK*8*1024+(size_t)blk*8*1024;
      const HF* skA=gH+(size_t)L*SLAB+(size_t)t*SLOT;
      const HF* WG=plane?Gl:Gh;
      const HF* WS=plane?Sl:Sh;
      const unsigned rWg=(unsigned)wr*(unsigned)KG;

      float accG[2][4][4], accS[2][4];
#pragma unroll
      for(int a=0;a<2;a++){
#pragma unroll
        for(int b=0;b<4;b++){accG[a][b][0]=0;accG[a][b][1]=0;accG[a][b][2]=0;accG[a][b][3]=0;}
        accS[a][0]=0;accS[a][1]=0;accS[a][2]=0;accS[a][3]=0;
      }

      auto do_stage=[&](int it){
        unsigned sb=(unsigned)(it&3)*16384u;
        const HF* paA; unsigned rAo;
        const HF* pw; unsigned rWo; bool wact;
        if(it<NG2){
          int k0=it*128;
          if(L==0){
            if(k0<IN0){paA=gX+(size_t)t*B_*IN0+k0; rAo=rIN0;}
            else {paA=gH+(size_t)(t+1)*SLOT+(k0-IN0); rAo=rHh;}
          }else{
            if(k0<H_){paA=gH+(size_t)(t+2)*SLOT+k0; rAo=rHh;}
            else {paA=gH+SLAB+(size_t)(t+1)*SLOT+(k0-H_); rAo=rHh;}
          }
          pw=WG+k0; rWo=rWg; wact=true;
        }else{
          int k0=(it-NG2)*128;
          paA=skA+k0; rAo=rHh;
          pw=WS+k0; rWo=rS1024; wact=wskip;
        }
        cp16u(bAu+sb+dA_off,      paA+rAo+cs8);
        cp16u(bAu+sb+8192u+dA_off,paA+rAo+64+cs8);
        if(wact){
          cp16u(bWu+sb+dW_off,      pw+rWo+cs8);
          cp16u(bWu+sb+8192u+dW_off,pw+rWo+64+cs8);
        }
        cpc();
      };

      do_stage(0); do_stage(1); do_stage(2);
#pragma unroll 1
      for(int it=0;it<NIT;it++){
        if(it+2<NIT) cpw<2>(); else if(it+1<NIT) cpw<1>(); else cpw<0>();
        __syncthreads();
        if(it+3<NIT) do_stage(it+3);
        unsigned sb=(unsigned)(it&3)*16384u;
        unsigned a0[4],a1[4];
        ldsm4u(a0,uA0+sb); ldsm4u(a1,uA1+sb);
        if(it<NG2){
          unsigned bh[4],bl[4];
          ldsm4u(bh,uB0+sb); ldsm4u(bl,uB0+sb+4096u);
          mma(accG[0][0],a0,bh);   mma(accG[0][1],a0,bh+2);
          mma(accG[1][0],a1,bh);   mma(accG[1][1],a1,bh+2);
          mma(accG[0][0],a0,bl);   mma(accG[0][1],a0,bl+2);
          mma(accG[1][0],a1,bl);   mma(accG[1][1],a1,bl+2);
          ldsm4u(bh,uB1+sb); ldsm4u(bl,uB1+sb+4096u);
          mma(accG[0][2],a0,bh);   mma(accG[0][3],a0,bh+2);
          mma(accG[1][2],a1,bh);   mma(accG[1][3],a1,bh+2);
          mma(accG[0][2],a0,bl);   mma(accG[0][3],a0,bl+2);
          mma(accG[1][2],a1,bl);   mma(accG[1][3],a1,bl+2);
        }else{
          unsigned h2[2],l2[2];
          ldsm2u(h2,uS+sb); ldsm2u(l2,uS+sb+4096u);
          mma(accS[0],a0,h2); mma(accS[1],a1,h2);
          mma(accS[0],a0,l2); mma(accS[1],a1,l2);
        }
      }
      __syncthreads();

      // every warp dumps its partials into its kg slab
      {
        float* Cs=Cred+kg*2560;
#pragma unroll
        for(int mi=0;mi<2;mi++){
          int rb=m*32+mi*16+rr;
#pragma unroll
          for(int nt=0;nt<4;nt++){
#pragma unroll
            for(int q=0;q<2;q++){
              Cs[(rb+q*8)*40+nt*8+cc]   =accG[mi][nt][q*2];
              Cs[(rb+q*8)*40+nt*8+cc+1] =accG[mi][nt][q*2+1];
            }
          }
#pragma unroll
          for(int q=0;q<2;q++){
            Cs[(rb+q*8)*40+32+cc]   =accS[mi][q*2];
            Cs[(rb+q*8)*40+32+cc+1] =accS[mi][q*2+1];
          }
        }
      }
      __syncthreads();

      // cooperative reduce + LSTM elementwise: 512 threads, 1 h-element each
      {
        const float* bi=L?bih1:bih0; const float* bh=L?bhh1:bhh0; const float* b2=L?bh21:bh20;
        int e=tid, r=e>>3, jl=e&7, j=blk*8+jl;
        float g0=0,g1=0,g2=0,g3=0,g4=0;
#pragma unroll
        for(int s=0;s<8;s++){
          const float* Cs=Cred+s*2560+r*40;
          g0+=Cs[jl]; g1+=Cs[8+jl]; g2+=Cs[16+jl]; g3+=Cs[24+jl]; g4+=Cs[32+jl];
        }
        float ig=g0+bi[j]     +bh[j];
        float fg=g1+bi[H_+j]  +bh[H_+j];
        float gg=g2+bi[2*H_+j]+bh[2*H_+j];
        float og=g3+bi[3*H_+j]+bh[3*H_+j];
        float sk=g4+b2[j];
        float cv=L?creg1:creg0;
        float cn=sigf(fg)*cv+sigf(ig)*tanhf(gg);
        float h1=sigf(og)*tanhf(cn);
        float h2=sigf(sk);
        int code=mask[(size_t)t*2*H_+(size_t)L*H_+j];
        float hn=(code!=1?h1:0.f)+(code!=0?h2:0.f);
        if(L) creg1=cn; else creg0=cn;
        gH[(size_t)L*SLAB+(size_t)(t+2)*SLOT+(size_t)r*H_+j]=__float2half(hn);
      }
      if(L==0) gridbar();   // single grid barrier per step
      else __syncthreads(); // protect Cred reuse into next step
    }
  }
}

// ---------------- output GEMM (fp16 2-term, unchanged) ----------------
__global__ void __launch_bounds__(256,1) k_out(const float* __restrict__ bo, float* __restrict__ out){
  extern __shared__ __align__(1024) char smx[];
  HF* sA=(HF*)smx;
  HF* sW=(HF*)(smx+32768);
  float* Cred=(float*)(smx+98304);
  const int tid=threadIdx.x, lane=tid&31, w=tid>>5;
  const int kg=w>>2, r0=(w&3)*16;
  const int rA=r0+(lane&7)+((lane>>3)&1)*8, cA=(lane>>4)&1;
  const int rr=r0+(lane>>2), cc=(lane&3)*2;
  const int kbase=kg*32;
  const int t=blockIdx.x, n0=blockIdx.y*64;
  const HF* Ah=gH+SLAB+(size_t)(t+2)*SLOT;
  const HF* Wh=gWoh+(size_t)n0*H_;
  const HF* Wl=gWol+(size_t)n0*H_;
  float acc[8][4];
#pragma unroll
  for(int i=0;i<8;i++){acc[i][0]=0;acc[i][1]=0;acc[i][2]=0;acc[i][3]=0;}
  auto do_stage=[&](int it){
    int st=it&3, k0=it*64;
    HF* dA=sA+st*4096; HF* dW=sW+st*8192;
    stA(dA,Ah+k0,H_,64,tid,256);
    stW(dW,dW+4096,Wh+k0,Wl+k0,H_,64,tid,256);
    cpc();
  };
  do_stage(0); do_stage(1); do_stage(2);
#pragma unroll 1
  for(int it=0;it<16;it++){
    int rem=15-it;
    if(rem>1) cpw<2>(); else if(rem==1) cpw<1>(); else cpw<0>();
    __syncthreads();
    int st=it&3;
    HF* bA=sA+st*4096; HF* bW=sW+st*8192;
    mm32i<4>(acc,bA,bW,bW+4096,kbase,rA,cA,lane);
    if(it+3<16) do_stage(it+3);
  }
  if(w>=4){
#pragma unroll
    for(int nt=0;nt<8;nt++)
#pragma unroll
      for(int q=0;q<2;q++)
#pragma unroll
        for(int p=0;p<2;p++)
          Cred[(rr+q*8)*64+nt*8+cc+p]=acc[nt][q*2+p];
  }
  __syncthreads();
  if(w<4){
#pragma unroll
    for(int nt=0;nt<8;nt++)
#pragma unroll
      for(int q=0;q<2;q++)
#pragma unroll
        for(int p=0;p<2;p++){
          int r=rr+q*8, col=n0+nt*8+cc+p;
          float v=acc[nt][q*2+p]+Cred[r*64+nt*8+cc+p]+bo[col];
          out[(size_t)t*B_*OUTD+(size_t)r*OUTD+col]=v;
        }
  }
}

extern "C" void kernel_launch(void* const* d_in, const int* in_sizes, int n_in,
                              void* d_out, int out_size) {
  const float* targets=(const float*)d_in[0];
  const float* h0  =(const float*)d_in[1];
  const float* c0  =(const float*)d_in[2];
  const int*   mask=(const int*)  d_in[3];
  const float* Wih0=(const float*)d_in[4];
  const float* Whh0=(const float*)d_in[5];
  const float* bih0=(const float*)d_in[6];
  const float* bhh0=(const float*)d_in[7];
  const float* Wih1=(const float*)d_in[8];
  const float* Whh1=(const float*)d_in[9];
  const float* bih1=(const float*)d_in[10];
  const float* bhh1=(const float*)d_in[11];
  const float* Wh20=(const float*)d_in[12];
  const float* bh20=(const float*)d_in[13];
  const float* Wh21=(const float*)d_in[14];
  const float* bh21=(const float*)d_in[15];
  const float* Wout=(const float*)d_in[16];
  const float* bout=(const float*)d_in[17];

  static int inited=0;
  if(!inited){
    cudaFuncSetAttribute(k_persist, cudaFuncAttributeMaxDynamicSharedMemorySize, 212992);
    cudaFuncSetAttribute(k_out,     cudaFuncAttributeMaxDynamicSharedMemorySize, 114688);
    inited=1;
  }
  // exactly 3 launches before k_persist -> k_persist occupies the ncu capture slot
  k_prepX<<<4096,256>>>(targets);
  k_prepG<<<4096,256>>>(Wih0,Whh0,Wih1,Whh1);
  k_prepS2<<<1024,256>>>(Wh20,Wh21);
  k_persist<<<NBLK,NTHR,212992>>>(mask,h0,c0,bih0,bhh0,bh20,bih1,bhh1,bh21);
  k_prepWo<<<512,256>>>(Wout);
  k_out<<<dim3(T_,8),256,114688>>>(bout,(float*)d_out);
}

// round 17
// speedup vs baseline: 3.1077x; 1.2001x over previous
#include <cuda_runtime.h>
#include <cuda_fp16.h>
#include <math.h>
#include <stdint.h>

typedef __half HF;
#define T_ 512
#define B_ 64
#define H_ 1024
#define IN0 1536
#define OUTD 512
#define SLOT (B_*H_)
#define SLAB ((size_t)514*SLOT)
#define NBLK 128
#define NTHR 512

__device__ __align__(16) HF gG0[(size_t)NBLK*32*2560];
__device__ __align__(16) HF gG1[(size_t)NBLK*32*2048];
__device__ __align__(16) HF gSk[(size_t)2*NBLK*8*1024];
__device__ __align__(16) HF gWo[OUTD*H_];
__device__ __align__(16) HF gX[(size_t)T_*B_*IN0];
__device__ __align__(16) HF gH[2*SLAB];

__device__ volatile unsigned gBarGen;
__device__ unsigned gBarCnt;

__device__ __forceinline__ float sigf(float x){ return 1.f/(1.f+expf(-x)); }
__device__ __forceinline__ unsigned su32(const void* p){ return (unsigned)__cvta_generic_to_shared(p); }
__device__ __forceinline__ void cp16(HF* d, const HF* s){
  asm volatile("cp.async.cg.shared.global [%0],[%1],16;"::"r"(su32(d)),"l"(s));
}
__device__ __forceinline__ void cp16u(unsigned d, const HF* s){
  asm volatile("cp.async.cg.shared.global [%0],[%1],16;"::"r"(d),"l"(s));
}
__device__ __forceinline__ void cpc(){ asm volatile("cp.async.commit_group;"); }
template<int N> __device__ __forceinline__ void cpw(){ asm volatile("cp.async.wait_group %0;"::"n"(N)); }

__device__ __forceinline__ void gridbar(){
  __syncthreads();
  if(threadIdx.x==0){
    unsigned old = gBarGen;
    __threadfence();
    unsigned prev = atomicAdd(&gBarCnt,1u);
    if(prev==NBLK-1u){ gBarCnt=0u; __threadfence(); gBarGen=old+1u; }
    else { while(gBarGen==old){} }
    __threadfence();
  }
  __syncthreads();
}

// tiles: rows x 64 fp16, 128B rows, 8-way 16B XOR swizzle
__device__ __forceinline__ const HF* swp(const HF* t_, int r, int cseg){
  return t_ + r*64 + ((cseg ^ (r&7))<<3);
}
__device__ __forceinline__ void stA(HF* d, const HF* p, int ld, int rows, int tid, int nthr){
  for(int u=tid; u<rows*8; u+=nthr){
    int r=u>>3, cs=u&7;
    cp16(d + r*64 + ((cs ^ (r&7))<<3), p + (size_t)r*ld + cs*8);
  }
}
__device__ __forceinline__ void ldsm4(unsigned a[4], const HF* p){
  asm volatile("ldmatrix.sync.aligned.m8n8.x4.shared.b16 {%0,%1,%2,%3},[%4];"
    :"=r"(a[0]),"=r"(a[1]),"=r"(a[2]),"=r"(a[3]):"r"(su32(p)));
}
__device__ __forceinline__ void ldsm4u(unsigned a[4], unsigned p){
  asm volatile("ldmatrix.sync.aligned.m8n8.x4.shared.b16 {%0,%1,%2,%3},[%4];"
    :"=r"(a[0]),"=r"(a[1]),"=r"(a[2]),"=r"(a[3]):"r"(p));
}
__device__ __forceinline__ void ldsm2u(unsigned b[2], unsigned p){
  asm volatile("ldmatrix.sync.aligned.m8n8.x2.shared.b16 {%0,%1},[%2];"
    :"=r"(b[0]),"=r"(b[1]):"r"(p));
}
__device__ __forceinline__ void mma(float c[4], const unsigned a[4], const unsigned b[2]){
  asm volatile("mma.sync.aligned.m16n8k16.row.col.f32.f16.f16.f32 "
    "{%0,%1,%2,%3},{%4,%5,%6,%7},{%8,%9},{%0,%1,%2,%3};"
    :"+f"(c[0]),"+f"(c[1]),"+f"(c[2]),"+f"(c[3])
    :"r"(a[0]),"r"(a[1]),"r"(a[2]),"r"(a[3]),"r"(b[0]),"r"(b[1]));
}
__device__ __forceinline__ void ldsm4b(unsigned b[4], const HF* t_, int np, int cs, int lane){
  int row  = np*16 + ((lane>>4)<<3) + (lane&7);
  int cseg = cs + ((lane>>3)&1);
  ldsm4(b, t_ + row*64 + ((cseg ^ (row&7))<<3));
}
// k_out helper: single-plane W
template<int NP>
__device__ __forceinline__ void mm32h(float (*acc)[4], const HF* A,
     const HF* W, int kbase, int rA,int cA,int lane){
#pragma unroll
  for(int kk=0;kk<2;kk++){
    int cs=(kbase>>3)+kk*2;
    unsigned ah[4];
    ldsm4(ah,swp(A,rA,cs+cA));
#pragma unroll
    for(int np=0;np<NP;np++){
      unsigned bh[4];
      ldsm4b(bh,W,np,cs,lane);
      mma(acc[2*np],ah,bh); mma(acc[2*np+1],ah,bh+2);
    }
  }
}

// ---------------- prep (3 launches so k_persist is launch #4 = ncu slot) ----------------
__global__ void k_prepX(const float* __restrict__ x){
  size_t n=(size_t)T_*B_*IN0;
  for(size_t i=(size_t)blockIdx.x*blockDim.x+threadIdx.x;i<n;i+=(size_t)gridDim.x*blockDim.x)
    gX[i]=__float2half(x[i]);
}
__global__ void k_prepG(const float* __restrict__ Wih0,const float* __restrict__ Whh0,
                        const float* __restrict__ Wih1,const float* __restrict__ Whh1){
  const size_t n0=(size_t)NBLK*32*2560, n1=(size_t)NBLK*32*2048;
  for(size_t i=(size_t)blockIdx.x*blockDim.x+threadIdx.x;i<n0+n1;i+=(size_t)gridDim.x*blockDim.x){
    int layer = i>=n0;
    size_t ii = layer? i-n0 : i;
    const int KA1=layer?H_:IN0, KG=KA1+H_;
    const float* Wih=layer?Wih1:Wih0; const float* Whh=layer?Whh1:Whh0;
    HF* dst=layer?gG1:gG0;
    int k=(int)(ii%KG); int q=(int)(ii/KG); int nr=q&31, blk=q>>5;
    int row=(nr>>3)*H_+blk*8+(nr&7);
    float v = (k<KA1)? Wih[(size_t)row*KA1+k] : Whh[(size_t)row*H_+(k-KA1)];
    dst[ii]=__float2half(v);
  }
}
__global__ void k_prepS2(const float* __restrict__ W0,const float* __restrict__ W1){
  const int n=NBLK*8*1024;
  for(int i=blockIdx.x*blockDim.x+threadIdx.x;i<2*n;i+=gridDim.x*blockDim.x){
    int layer=i>=n, ii=layer?i-n:i;
    const float* W=layer?W1:W0;
    HF* dst=gSk+(size_t)layer*n;
    int k=ii&1023; int q=ii>>10; int nr=q&7, blk=q>>3;
    dst[ii]=__float2half(W[(size_t)k*H_+blk*8+nr]);
  }
}
__global__ void k_prepWo(const float* __restrict__ W){
  for(int i=blockIdx.x*blockDim.x+threadIdx.x;i<OUTD*H_;i+=gridDim.x*blockDim.x)
    gWo[i]=__float2half(W[i]);
}

// ---------------- persistent recurrence (512 thr, 2m x 8kg, fp16 single-plane W) ----------------
// smem: sA 4 x 16384B @0 ; sW 4 x 8192B @65536 ; Cred 8 x 2560 f32 @98304 -> 180224
__global__ void __launch_bounds__(NTHR,1) k_persist(const int* __restrict__ mask,
    const float* __restrict__ h0, const float* __restrict__ c0,
    const float* __restrict__ bih0,const float* __restrict__ bhh0,const float* __restrict__ bh20,
    const float* __restrict__ bih1,const float* __restrict__ bhh1,const float* __restrict__ bh21)
{
  extern __shared__ __align__(1024) char smx[];
  HF* sA=(HF*)smx;
  HF* sW=(HF*)(smx+65536);
  float* Cred=(float*)(smx+98304);
  const int tid=threadIdx.x, lane=tid&31, w=tid>>5, blk=blockIdx.x;
  const int m=w&1, kg=w>>1;
  const int hsel=kg>>2, csl=(kg&3)*2;
  const int rA0=m*32+(lane&7)+((lane>>3)&1)*8, cA=(lane>>4)&1;
  const int nB=lane&7, cB=(lane>>3)&1;
  const int rr=lane>>2, cc=(lane&3)*2;

  // ---- precomputed ldsm addresses (byte offsets, stage-invariant) ----
  auto offf=[](int r,int c)->unsigned{ return (unsigned)(r*128 + ((c^(r&7))<<4)); };
  const unsigned bAu=su32(sA), bWu=su32(sW);
  const unsigned uA0=bAu+hsel*8192+offf(rA0,csl+cA);
  const unsigned uA1=bAu+hsel*8192+offf(rA0+16,csl+cA);
  const int rB=((lane>>4)<<3)+(lane&7), cgB=csl+((lane>>3)&1);
  const unsigned uB0=bWu+hsel*4096+offf(rB,cgB);
  const unsigned uB1=bWu+hsel*4096+offf(rB+16,cgB);
  const unsigned uS =bWu+hsel*4096+offf(nB,csl+cB);

  // ---- precomputed staging constants ----
  const int ar=tid>>3;
  const unsigned dA_off=offf(ar,tid&7);
  const unsigned rIN0=(unsigned)ar*IN0, rHh=(unsigned)ar*H_;
  const unsigned cs8=(unsigned)(tid&7)*8;
  const int whalf=tid>>8, wr=(tid&255)>>3;
  const unsigned dW_off=(unsigned)whalf*4096u+offf(wr,tid&7);
  const unsigned hw64=(unsigned)whalf*64u;
  const unsigned rS1024=(unsigned)wr*1024u;
  const bool wskip=((tid&255)<64);

  // c-state in registers (tid <-> element bijection)
  float creg0, creg1;
  {
    int r=tid>>3, j=blk*8+(tid&7);
    creg0=c0[(size_t)r*H_+j];
    creg1=c0[(size_t)(B_+r)*H_+j];
#pragma unroll
    for(int L=0;L<2;L++){
      size_t b0=(size_t)L*SLAB+(size_t)r*H_+j;
      gH[b0]=__float2half(0.f);
      gH[b0+SLOT]=__float2half(h0[(size_t)(L*B_+r)*H_+j]);
    }
  }
  gridbar();

  for(int t=0;t<T_;t++){
#pragma unroll 1
    for(int L=0;L<2;L++){
      const int KG=L?2048:2560;
      const int NG2=KG>>7, NIT=NG2+8;
      const HF* WG=(L?gG1:gG0)+(size_t)blk*32*KG;
      const HF* WS=gSk+(size_t)L*NBLK*8*1024+(size_t)blk*8*1024;
      const HF* skA=gH+(size_t)L*SLAB+(size_t)t*SLOT;
      const unsigned rWg=(unsigned)wr*(unsigned)KG;

      float accG[2][4][4], accS[2][4];
#pragma unroll
      for(int a=0;a<2;a++){
#pragma unroll
        for(int b=0;b<4;b++){accG[a][b][0]=0;accG[a][b][1]=0;accG[a][b][2]=0;accG[a][b][3]=0;}
        accS[a][0]=0;accS[a][1]=0;accS[a][2]=0;accS[a][3]=0;
      }

      auto do_stage=[&](int it){
        unsigned sbA=(unsigned)(it&3)*16384u, sbW=(unsigned)(it&3)*8192u;
        const HF* paA; unsigned rAo;
        const HF* pw; unsigned rWo; bool wact;
        if(it<NG2){
          int k0=it*128;
          if(L==0){
            if(k0<IN0){paA=gX+(size_t)t*B_*IN0+k0; rAo=rIN0;}
            else {paA=gH+(size_t)(t+1)*SLOT+(k0-IN0); rAo=rHh;}
          }else{
            if(k0<H_){paA=gH+(size_t)(t+2)*SLOT+k0; rAo=rHh;}
            else {paA=gH+SLAB+(size_t)(t+1)*SLOT+(k0-H_); rAo=rHh;}
          }
          pw=WG+k0; rWo=rWg; wact=true;
        }else{
          int k0=(it-NG2)*128;
          paA=skA+k0; rAo=rHh;
          pw=WS+k0; rWo=rS1024; wact=wskip;
        }
        cp16u(bAu+sbA+dA_off,      paA+rAo+cs8);
        cp16u(bAu+sbA+8192u+dA_off,paA+rAo+64+cs8);
        if(wact) cp16u(bWu+sbW+dW_off, pw+rWo+hw64+cs8);
        cpc();
      };

      do_stage(0); do_stage(1); do_stage(2);
#pragma unroll 1
      for(int it=0;it<NIT;it++){
        if(it+2<NIT) cpw<2>(); else if(it+1<NIT) cpw<1>(); else cpw<0>();
        __syncthreads();
        if(it+3<NIT) do_stage(it+3);
        unsigned sbA=(unsigned)(it&3)*16384u, sbW=(unsigned)(it&3)*8192u;
        unsigned a0[4],a1[4];
        ldsm4u(a0,uA0+sbA); ldsm4u(a1,uA1+sbA);
        if(it<NG2){
          unsigned b0[4],b1[4];
          ldsm4u(b0,uB0+sbW); ldsm4u(b1,uB1+sbW);
          mma(accG[0][0],a0,b0);   mma(accG[0][1],a0,b0+2);
          mma(accG[1][0],a1,b0);   mma(accG[1][1],a1,b0+2);
          mma(accG[0][2],a0,b1);   mma(accG[0][3],a0,b1+2);
          mma(accG[1][2],a1,b1);   mma(accG[1][3],a1,b1+2);
        }else{
          unsigned s2[2];
          ldsm2u(s2,uS+sbW);
          mma(accS[0],a0,s2); mma(accS[1],a1,s2);
        }
      }
      __syncthreads();

      // every warp dumps its partials into its kg slab
      {
        float* Cs=Cred+kg*2560;
#pragma unroll
        for(int mi=0;mi<2;mi++){
          int rb=m*32+mi*16+rr;
#pragma unroll
          for(int nt=0;nt<4;nt++){
#pragma unroll
            for(int q=0;q<2;q++){
              Cs[(rb+q*8)*40+nt*8+cc]   =accG[mi][nt][q*2];
              Cs[(rb+q*8)*40+nt*8+cc+1] =accG[mi][nt][q*2+1];
            }
          }
#pragma unroll
          for(int q=0;q<2;q++){
            Cs[(rb+q*8)*40+32+cc]   =accS[mi][q*2];
            Cs[(rb+q*8)*40+32+cc+1] =accS[mi][q*2+1];
          }
        }
      }
      __syncthreads();

      // cooperative reduce + LSTM elementwise: 512 threads, 1 h-element each
      {
        const float* bi=L?bih1:bih0; const float* bh=L?bhh1:bhh0; const float* b2=L?bh21:bh20;
        int e=tid, r=e>>3, jl=e&7, j=blk*8+jl;
        float g0=0,g1=0,g2=0,g3=0,g4=0;
#pragma unroll
        for(int s=0;s<8;s++){
          const float* Cs=Cred+s*2560+r*40;
          g0+=Cs[jl]; g1+=Cs[8+jl]; g2+=Cs[16+jl]; g3+=Cs[24+jl]; g4+=Cs[32+jl];
        }
        float ig=g0+bi[j]     +bh[j];
        float fg=g1+bi[H_+j]  +bh[H_+j];
        float gg=g2+bi[2*H_+j]+bh[2*H_+j];
        float og=g3+bi[3*H_+j]+bh[3*H_+j];
        float sk=g4+b2[j];
        float cv=L?creg1:creg0;
        float cn=sigf(fg)*cv+sigf(ig)*tanhf(gg);
        float h1=sigf(og)*tanhf(cn);
        float h2=sigf(sk);
        int code=mask[(size_t)t*2*H_+(size_t)L*H_+j];
        float hn=(code!=1?h1:0.f)+(code!=0?h2:0.f);
        if(L) creg1=cn; else creg0=cn;
        gH[(size_t)L*SLAB+(size_t)(t+2)*SLOT+(size_t)r*H_+j]=__float2half(hn);
      }
      if(L==0) gridbar();   // single grid barrier per step
      else __syncthreads(); // protect Cred reuse into next step
    }
  }
}

// ---------------- output GEMM (fp16 single-plane W) ----------------
// smem: sA 4 x 8192B @0 ; sW 4 x 8192B @32768 ; Cred 16KB @65536 -> 81920
__global__ void __launch_bounds__(256,1) k_out(const float* __restrict__ bo, float* __restrict__ out){
  extern __shared__ __align__(1024) char smx[];
  HF* sA=(HF*)smx;
  HF* sW=(HF*)(smx+32768);
  float* Cred=(float*)(smx+65536);
  const int tid=threadIdx.x, lane=tid&31, w=tid>>5;
  const int kg=w>>2, r0=(w&3)*16;
  const int rA=r0+(lane&7)+((lane>>3)&1)*8, cA=(lane>>4)&1;
  const int rr=r0+(lane>>2), cc=(lane&3)*2;
  const int kbase=kg*32;
  const int t=blockIdx.x, n0=blockIdx.y*64;
  const HF* Ah=gH+SLAB+(size_t)(t+2)*SLOT;
  const HF* Wh=gWo+(size_t)n0*H_;
  float acc[8][4];
#pragma unroll
  for(int i=0;i<8;i++){acc[i][0]=0;acc[i][1]=0;acc[i][2]=0;acc[i][3]=0;}
  auto do_stage=[&](int it){
    int st=it&3, k0=it*64;
    HF* dA=sA+st*4096; HF* dW=sW+st*4096;
    stA(dA,Ah+k0,H_,64,tid,256);
    stA(dW,Wh+k0,H_,64,tid,256);
    cpc();
  };
  do_stage(0); do_stage(1); do_stage(2);
#pragma unroll 1
  for(int it=0;it<16;it++){
    int rem=15-it;
    if(rem>1) cpw<2>(); else if(rem==1) cpw<1>(); else cpw<0>();
    __syncthreads();
    int st=it&3;
    HF* bA=sA+st*4096; HF* bW=sW+st*4096;
    mm32h<4>(acc,bA,bW,kbase,rA,cA,lane);
    if(it+3<16) do_stage(it+3);
  }
  if(w>=4){
#pragma unroll
    for(int nt=0;nt<8;nt++)
#pragma unroll
      for(int q=0;q<2;q++)
#pragma unroll
        for(int p=0;p<2;p++)
          Cred[(rr+q*8)*64+nt*8+cc+p]=acc[nt][q*2+p];
  }
  __syncthreads();
  if(w<4){
#pragma unroll
    for(int nt=0;nt<8;nt++)
#pragma unroll
      for(int q=0;q<2;q++)
#pragma unroll
        for(int p=0;p<2;p++){
          int r=rr+q*8, col=n0+nt*8+cc+p;
          float v=acc[nt][q*2+p]+Cred[r*64+nt*8+cc+p]+bo[col];
          out[(size_t)t*B_*OUTD+(size_t)r*OUTD+col]=v;
        }
  }
}

extern "C" void kernel_launch(void* const* d_in, const int* in_sizes, int n_in,
                              void* d_out, int out_size) {
  const float* targets=(const float*)d_in[0];
  const float* h0  =(const float*)d_in[1];
  const float* c0  =(const float*)d_in[2];
  const int*   mask=(const int*)  d_in[3];
  const float* Wih0=(const float*)d_in[4];
  const float* Whh0=(const float*)d_in[5];
  const float* bih0=(const float*)d_in[6];
  const float* bhh0=(const float*)d_in[7];
  const float* Wih1=(const float*)d_in[8];
  const float* Whh1=(const float*)d_in[9];
  const float* bih1=(const float*)d_in[10];
  const float* bhh1=(const float*)d_in[11];
  const float* Wh20=(const float*)d_in[12];
  const float* bh20=(const float*)d_in[13];
  const float* Wh21=(const float*)d_in[14];
  const float* bh21=(const float*)d_in[15];
  const float* Wout=(const float*)d_in[16];
  const float* bout=(const float*)d_in[17];

  static int inited=0;
  if(!inited){
    cudaFuncSetAttribute(k_persist, cudaFuncAttributeMaxDynamicSharedMemorySize, 180224);
    cudaFuncSetAttribute(k_out,     cudaFuncAttributeMaxDynamicSharedMemorySize, 81920);
    inited=1;
  }
  // exactly 3 launches before k_persist -> k_persist occupies the ncu capture slot
  k_prepX<<<4096,256>>>(targets);
  k_prepG<<<4096,256>>>(Wih0,Whh0,Wih1,Whh1);
  k_prepS2<<<1024,256>>>(Wh20,Wh21);
  k_persist<<<NBLK,NTHR,180224>>>(mask,h0,c0,bih0,bhh0,bh20,bih1,bhh1,bh21);
  k_prepWo<<<512,256>>>(Wout);
  k_out<<<dim3(T_,8),256,81920>>>(bout,(float*)d_out);
}